// round 1
// baseline (speedup 1.0000x reference)
#include <cuda_runtime.h>
#include <math.h>

#define SLEN 2048
#define DMODEL 2048
#define NH 16
#define NKV 4
#define HD 128

// scratch (allocation-free contract: __device__ globals)
__device__ __align__(16) float g_q[SLEN * DMODEL];       // [s][h][d]
__device__ __align__(16) float g_k[SLEN * NKV * HD];     // [s][kvh][d]
__device__ __align__(16) float g_v[SLEN * NKV * HD];
__device__ __align__(16) float g_att[SLEN * DMODEL];     // [s][h*128+d]

// ---------------------------------------------------------------------------
// C[M,N] = A[M,K] @ B[N,K]^T   (both row-major, K contiguous)
// 128x128 tile, BK=8, 256 threads, 8x8 per thread
// ---------------------------------------------------------------------------
__global__ __launch_bounds__(256) void gemm_nt(
    const float* __restrict__ A, const float* __restrict__ B,
    float* __restrict__ C, int M, int N, int K)
{
    __shared__ float As[8][128];
    __shared__ float Bs[8][128];
    int tid = threadIdx.x;
    int bm = blockIdx.y * 128;
    int bn = blockIdx.x * 128;
    int tr = tid >> 4, tc = tid & 15;
    int lr = tid >> 1;
    int lc = (tid & 1) * 4;

    float acc[8][8];
#pragma unroll
    for (int i = 0; i < 8; i++)
#pragma unroll
        for (int j = 0; j < 8; j++) acc[i][j] = 0.f;

    const float* Ap = A + (size_t)(bm + lr) * K + lc;
    const float* Bp = B + (size_t)(bn + lr) * K + lc;

    for (int k0 = 0; k0 < K; k0 += 8) {
        float4 a4 = *(const float4*)(Ap + k0);
        float4 b4 = *(const float4*)(Bp + k0);
        As[lc + 0][lr] = a4.x; As[lc + 1][lr] = a4.y;
        As[lc + 2][lr] = a4.z; As[lc + 3][lr] = a4.w;
        Bs[lc + 0][lr] = b4.x; Bs[lc + 1][lr] = b4.y;
        Bs[lc + 2][lr] = b4.z; Bs[lc + 3][lr] = b4.w;
        __syncthreads();
#pragma unroll
        for (int kk = 0; kk < 8; kk++) {
            float a[8], b[8];
            *(float4*)(a)     = *(const float4*)&As[kk][tr * 4];
            *(float4*)(a + 4) = *(const float4*)&As[kk][tr * 4 + 64];
            *(float4*)(b)     = *(const float4*)&Bs[kk][tc * 4];
            *(float4*)(b + 4) = *(const float4*)&Bs[kk][tc * 4 + 64];
#pragma unroll
            for (int i = 0; i < 8; i++)
#pragma unroll
                for (int j = 0; j < 8; j++)
                    acc[i][j] += a[i] * b[j];
        }
        __syncthreads();
    }

#pragma unroll
    for (int i = 0; i < 8; i++) {
        int row = bm + tr * 4 + (i < 4 ? i : 60 + i);
        float* Cp = C + (size_t)row * N + bn;
        *(float4*)(Cp + tc * 4)      = make_float4(acc[i][0], acc[i][1], acc[i][2], acc[i][3]);
        *(float4*)(Cp + tc * 4 + 64) = make_float4(acc[i][4], acc[i][5], acc[i][6], acc[i][7]);
    }
}

// ---------------------------------------------------------------------------
// RMSNorm (per head row of 128) + RoPE, in place, for q and k
// one warp per (s, head) row
// ---------------------------------------------------------------------------
__global__ __launch_bounds__(256) void norm_rope(
    float* __restrict__ q, float* __restrict__ k,
    const float* __restrict__ freqs)
{
    int gwarp = (blockIdx.x * blockDim.x + threadIdx.x) >> 5;
    int lane  = threadIdx.x & 31;
    const int total = SLEN * (NH + NKV);
    if (gwarp >= total) return;
    int s = gwarp / (NH + NKV);
    int h = gwarp % (NH + NKV);
    float* row = (h < NH) ? (q + ((size_t)s * NH + h) * HD)
                          : (k + ((size_t)s * NKV + (h - NH)) * HD);

    float4 x = *(float4*)&row[lane * 4];
    float ss = x.x * x.x + x.y * x.y + x.z * x.z + x.w * x.w;
#pragma unroll
    for (int off = 16; off; off >>= 1)
        ss += __shfl_xor_sync(0xffffffffu, ss, off);
    float r = rsqrtf(ss * (1.f / 128.f) + 1.1920929e-07f);

    // rope: lane handles pairs j=2*lane, 2*lane+1 (elements 4*lane..4*lane+3)
    float4 fc = *(const float4*)&freqs[(size_t)s * 128 + lane * 4];
    float x1 = x.x * r, x2 = x.y * r, x3 = x.z * r, x4 = x.w * r;
    float4 o;
    o.x = x1 * fc.x - x2 * fc.y;
    o.y = x1 * fc.y + x2 * fc.x;
    o.z = x3 * fc.z - x4 * fc.w;
    o.w = x3 * fc.w + x4 * fc.z;
    *(float4*)&row[lane * 4] = o;
}

// ---------------------------------------------------------------------------
// Flash attention, causal, with sink scaling. BQ=BK=64, D=128, 256 threads.
// smem: Qs[64][128] | KVs[64][128] (K then V reuse) | Ps[64][64]  = 80 KB
// thread (ty,tx): S frag rows ty*4..+3, cols tx*4..+3 ; O cols tx*4(+64)
// ---------------------------------------------------------------------------
__global__ __launch_bounds__(256) void attn_kernel(
    const float* __restrict__ q, const float* __restrict__ k,
    const float* __restrict__ v, const float* __restrict__ sinks,
    float* __restrict__ out)
{
    extern __shared__ float sm[];
    float* Qs  = sm;                // 64*128
    float* KVs = sm + 64 * 128;     // 64*128
    float* Ps  = sm + 2 * 64 * 128; // 64*64

    int tid = threadIdx.x;
    int h   = blockIdx.y;
    int kvh = h >> 2;                       // n_rep = 4
    int qt  = gridDim.x - 1 - blockIdx.x;   // heavy tiles scheduled first
    int ty = tid >> 4, tx = tid & 15;

    // load Q tile
    for (int idx = tid; idx < 64 * 32; idx += 256) {
        int row = idx >> 5, c4 = idx & 31;
        ((float4*)Qs)[idx] =
            *(const float4*)&q[(((size_t)(qt * 64 + row)) * NH + h) * HD + c4 * 4];
    }

    float oacc[4][8];
#pragma unroll
    for (int i = 0; i < 4; i++)
#pragma unroll
        for (int j = 0; j < 8; j++) oacc[i][j] = 0.f;
    float m_i[4], l_i[4];
#pragma unroll
    for (int i = 0; i < 4; i++) { m_i[i] = -1e30f; l_i[i] = 0.f; }

    const float scale = 0.08838834764831845f; // 1/sqrt(128)

    for (int kt = 0; kt <= qt; kt++) {
        __syncthreads();  // prev PV done reading KVs/Ps; Qs ready (1st iter)
        for (int idx = tid; idx < 64 * 32; idx += 256) {
            int row = idx >> 5, c4 = idx & 31;
            ((float4*)KVs)[idx] =
                *(const float4*)&k[(((size_t)(kt * 64 + row)) * NKV + kvh) * HD + c4 * 4];
        }
        __syncthreads();

        float sfrag[4][4];
#pragma unroll
        for (int i = 0; i < 4; i++)
#pragma unroll
            for (int j = 0; j < 4; j++) sfrag[i][j] = 0.f;

#pragma unroll 4
        for (int d4 = 0; d4 < 32; d4++) {
            float4 a[4], b[4];
#pragma unroll
            for (int i = 0; i < 4; i++)
                a[i] = ((const float4*)(Qs + (ty * 4 + i) * 128))[d4];
#pragma unroll
            for (int j = 0; j < 4; j++)
                b[j] = ((const float4*)(KVs + (tx * 4 + j) * 128))[d4];
#pragma unroll
            for (int i = 0; i < 4; i++)
#pragma unroll
                for (int j = 0; j < 4; j++)
                    sfrag[i][j] += a[i].x * b[j].x + a[i].y * b[j].y
                                 + a[i].z * b[j].z + a[i].w * b[j].w;
        }

        bool diag = (kt == qt);
#pragma unroll
        for (int i = 0; i < 4; i++) {
            int qr = qt * 64 + ty * 4 + i;
            float rmax = -1e30f;
#pragma unroll
            for (int j = 0; j < 4; j++) {
                int kc = kt * 64 + tx * 4 + j;
                float sv = (!diag || kc <= qr) ? sfrag[i][j] * scale : -1e30f;
                sfrag[i][j] = sv;
                rmax = fmaxf(rmax, sv);
            }
#pragma unroll
            for (int off = 8; off; off >>= 1)
                rmax = fmaxf(rmax, __shfl_xor_sync(0xffffffffu, rmax, off));
            float newm = fmaxf(m_i[i], rmax);
            float alpha = __expf(m_i[i] - newm);
            float rsum = 0.f;
#pragma unroll
            for (int j = 0; j < 4; j++) {
                float p = __expf(sfrag[i][j] - newm);
                Ps[(ty * 4 + i) * 64 + tx * 4 + j] = p;
                rsum += p;
            }
#pragma unroll
            for (int off = 8; off; off >>= 1)
                rsum += __shfl_xor_sync(0xffffffffu, rsum, off);
            l_i[i] = l_i[i] * alpha + rsum;
            m_i[i] = newm;
#pragma unroll
            for (int j = 0; j < 8; j++) oacc[i][j] *= alpha;
        }
        __syncthreads();  // Ps written; KVs S-reads done

        // load V into KVs
        for (int idx = tid; idx < 64 * 32; idx += 256) {
            int row = idx >> 5, c4 = idx & 31;
            ((float4*)KVs)[idx] =
                *(const float4*)&v[(((size_t)(kt * 64 + row)) * NKV + kvh) * HD + c4 * 4];
        }
        __syncthreads();

#pragma unroll 8
        for (int kk = 0; kk < 64; kk++) {
            float p[4];
#pragma unroll
            for (int i = 0; i < 4; i++) p[i] = Ps[(ty * 4 + i) * 64 + kk];
            float4 v0 = ((const float4*)(KVs + kk * 128))[tx];
            float4 v1 = ((const float4*)(KVs + kk * 128))[tx + 16];
#pragma unroll
            for (int i = 0; i < 4; i++) {
                oacc[i][0] += p[i] * v0.x; oacc[i][1] += p[i] * v0.y;
                oacc[i][2] += p[i] * v0.z; oacc[i][3] += p[i] * v0.w;
                oacc[i][4] += p[i] * v1.x; oacc[i][5] += p[i] * v1.y;
                oacc[i][6] += p[i] * v1.z; oacc[i][7] += p[i] * v1.w;
            }
        }
    }

    float sink = sinks[h];
#pragma unroll
    for (int i = 0; i < 4; i++) {
        int qr = qt * 64 + ty * 4 + i;
        float lse = m_i[i] + logf(l_i[i]);
        float sg = 1.f / (1.f + __expf(sink - lse));   // sigmoid(lse - sink)
        float sc = sg / l_i[i];
        float* op = out + (size_t)qr * DMODEL + h * HD;
        *(float4*)(op + tx * 4) = make_float4(
            oacc[i][0] * sc, oacc[i][1] * sc, oacc[i][2] * sc, oacc[i][3] * sc);
        *(float4*)(op + tx * 4 + 64) = make_float4(
            oacc[i][4] * sc, oacc[i][5] * sc, oacc[i][6] * sc, oacc[i][7] * sc);
    }
}

// ---------------------------------------------------------------------------
extern "C" void kernel_launch(void* const* d_in, const int* in_sizes, int n_in,
                              void* d_out, int out_size)
{
    const float* x     = (const float*)d_in[0];
    const float* freqs = (const float*)d_in[1];
    const float* wq    = (const float*)d_in[2];
    const float* wk    = (const float*)d_in[3];
    const float* wv    = (const float*)d_in[4];
    const float* wo    = (const float*)d_in[5];
    const float* sinks = (const float*)d_in[6];
    float* out = (float*)d_out;

    float *q, *k, *v, *att;
    cudaGetSymbolAddress((void**)&q,   g_q);
    cudaGetSymbolAddress((void**)&k,   g_k);
    cudaGetSymbolAddress((void**)&v,   g_v);
    cudaGetSymbolAddress((void**)&att, g_att);

    cudaFuncSetAttribute(attn_kernel,
                         cudaFuncAttributeMaxDynamicSharedMemorySize, 81920);

    // QKV projections
    gemm_nt<<<dim3(16, 16), 256>>>(x, wq, q, SLEN, DMODEL, DMODEL);
    gemm_nt<<<dim3(4, 16),  256>>>(x, wk, k, SLEN, NKV * HD, DMODEL);
    gemm_nt<<<dim3(4, 16),  256>>>(x, wv, v, SLEN, NKV * HD, DMODEL);

    // RMSNorm + RoPE on q, k (one warp per head-row)
    norm_rope<<<(SLEN * (NH + NKV) * 32) / 256, 256>>>(q, k, freqs);

    // causal flash attention with sink scaling
    attn_kernel<<<dim3(SLEN / 64, NH), 256, 81920>>>(q, k, v, sinks, att);

    // output projection
    gemm_nt<<<dim3(16, 16), 256>>>(att, wo, out, SLEN, DMODEL, DMODEL);
}

// round 3
// speedup vs baseline: 3.9401x; 3.9401x over previous
#include <cuda_runtime.h>
#include <cuda_bf16.h>
#include <math.h>

typedef unsigned int u32;

#define SLEN 2048
#define DMODEL 2048
#define NH 16
#define NKV 4
#define HD 128

// scratch (allocation-free contract: __device__ globals)
__device__ __align__(16) float g_q[SLEN * DMODEL];       // [s][h][d]
__device__ __align__(16) float g_k[SLEN * NKV * HD];     // [s][kvh][d]
__device__ __align__(16) float g_v[SLEN * NKV * HD];
__device__ __align__(16) float g_att[SLEN * DMODEL];     // [s][h*128+d]

// ---------------------------------------------------------------------------
// helpers
// ---------------------------------------------------------------------------
__device__ __forceinline__ u32 sptr(const void* p) {
    return (u32)__cvta_generic_to_shared(p);
}
__device__ __forceinline__ void ldm4(u32 a, u32& r0, u32& r1, u32& r2, u32& r3) {
    asm volatile("ldmatrix.sync.aligned.m8n8.x4.shared.b16 {%0,%1,%2,%3},[%4];"
                 : "=r"(r0), "=r"(r1), "=r"(r2), "=r"(r3) : "r"(a));
}
__device__ __forceinline__ void ldm4t(u32 a, u32& r0, u32& r1, u32& r2, u32& r3) {
    asm volatile("ldmatrix.sync.aligned.m8n8.x4.trans.shared.b16 {%0,%1,%2,%3},[%4];"
                 : "=r"(r0), "=r"(r1), "=r"(r2), "=r"(r3) : "r"(a));
}
__device__ __forceinline__ void mma16816(float* c, u32 a0, u32 a1, u32 a2, u32 a3,
                                         u32 b0, u32 b1) {
    asm volatile(
        "mma.sync.aligned.m16n8k16.row.col.f32.bf16.bf16.f32 "
        "{%0,%1,%2,%3},{%4,%5,%6,%7},{%8,%9},{%0,%1,%2,%3};"
        : "+f"(c[0]), "+f"(c[1]), "+f"(c[2]), "+f"(c[3])
        : "r"(a0), "r"(a1), "r"(a2), "r"(a3), "r"(b0), "r"(b1));
}
__device__ __forceinline__ u32 packbf(__nv_bfloat16 a, __nv_bfloat16 b) {
    __nv_bfloat162 t = __halves2bfloat162(a, b);
    return *reinterpret_cast<u32*>(&t);
}
// split (x,y) into bf16 hi pair + bf16 lo pair (Ootomo split)
__device__ __forceinline__ void split2(float x, float y, u32& h, u32& l) {
    __nv_bfloat16 hx = __float2bfloat16(x), hy = __float2bfloat16(y);
    __nv_bfloat16 lx = __float2bfloat16(x - __bfloat162float(hx));
    __nv_bfloat16 ly = __float2bfloat16(y - __bfloat162float(hy));
    h = packbf(hx, hy);
    l = packbf(lx, ly);
}
__device__ __forceinline__ float ex2(float x) {
    float y; asm("ex2.approx.f32 %0, %1;" : "=f"(y) : "f"(x)); return y;
}

// ---------------------------------------------------------------------------
// C[M,N] = A[M,K] @ B[N,K]^T, fp32 in/out, split-bf16 tensor-core compute.
// 128x128x32 tiles, 256 threads (8 warps: 4m x 2n), warp tile 32x64.
// smem rows padded: stride 40 bf16 (80 B) for conflict-light ldmatrix.
// ---------------------------------------------------------------------------
__global__ __launch_bounds__(256, 2) void gemm_nt(
    const float* __restrict__ A, const float* __restrict__ B,
    float* __restrict__ C, int M, int N, int K)
{
    __shared__ u32 As_h[128 * 20], As_l[128 * 20];
    __shared__ u32 Bs_h[128 * 20], Bs_l[128 * 20];

    const int tid = threadIdx.x, lane = tid & 31, w = tid >> 5;
    const int wm = w >> 1, wn = w & 1;
    const int bm = blockIdx.y * 128, bn = blockIdx.x * 128;

    float acc[2][8][4];
#pragma unroll
    for (int a = 0; a < 2; a++)
#pragma unroll
        for (int b = 0; b < 8; b++)
#pragma unroll
            for (int c = 0; c < 4; c++) acc[a][b][c] = 0.f;

    const int lr = tid >> 3, lc = tid & 7;
    const float* Ap = A + (size_t)(bm + lr) * K + lc * 4;
    const float* Bp = B + (size_t)(bn + lr) * K + lc * 4;

    const u32 a_h = sptr(As_h) + (wm * 32 + (lane & 15)) * 80 + (lane >> 4) * 16;
    const u32 a_l = sptr(As_l) + (wm * 32 + (lane & 15)) * 80 + (lane >> 4) * 16;
    const int brow = wn * 64 + (lane >> 4) * 8 + (lane & 7);
    const u32 b_h = sptr(Bs_h) + brow * 80 + ((lane >> 3) & 1) * 16;
    const u32 b_l = sptr(Bs_l) + brow * 80 + ((lane >> 3) & 1) * 16;

    for (int kc = 0; kc < K; kc += 32) {
#pragma unroll
        for (int p = 0; p < 4; p++) {
            float4 av = *(const float4*)(Ap + (size_t)(p * 32) * K + kc);
            float4 bv = *(const float4*)(Bp + (size_t)(p * 32) * K + kc);
            int idx = (lr + p * 32) * 20 + lc * 2;
            u32 h0, h1, l0, l1;
            split2(av.x, av.y, h0, l0); split2(av.z, av.w, h1, l1);
            As_h[idx] = h0; As_h[idx + 1] = h1;
            As_l[idx] = l0; As_l[idx + 1] = l1;
            split2(bv.x, bv.y, h0, l0); split2(bv.z, bv.w, h1, l1);
            Bs_h[idx] = h0; Bs_h[idx + 1] = h1;
            Bs_l[idx] = l0; Bs_l[idx + 1] = l1;
        }
        __syncthreads();
#pragma unroll
        for (int ks = 0; ks < 2; ks++) {
            u32 ah[2][4], al[2][4];
            ldm4(a_h + ks * 32,        ah[0][0], ah[0][1], ah[0][2], ah[0][3]);
            ldm4(a_h + ks * 32 + 1280, ah[1][0], ah[1][1], ah[1][2], ah[1][3]);
            ldm4(a_l + ks * 32,        al[0][0], al[0][1], al[0][2], al[0][3]);
            ldm4(a_l + ks * 32 + 1280, al[1][0], al[1][1], al[1][2], al[1][3]);
#pragma unroll
            for (int g = 0; g < 4; g++) {
                u32 bh[4], bl[4];
                ldm4(b_h + g * 1280 + ks * 32, bh[0], bh[1], bh[2], bh[3]);
                ldm4(b_l + g * 1280 + ks * 32, bl[0], bl[1], bl[2], bl[3]);
#pragma unroll
                for (int mt = 0; mt < 2; mt++)
#pragma unroll
                    for (int s = 0; s < 2; s++) {
                        float* c = acc[mt][g * 2 + s];
                        mma16816(c, ah[mt][0], ah[mt][1], ah[mt][2], ah[mt][3],
                                 bh[2 * s], bh[2 * s + 1]);
                        mma16816(c, ah[mt][0], ah[mt][1], ah[mt][2], ah[mt][3],
                                 bl[2 * s], bl[2 * s + 1]);
                        mma16816(c, al[mt][0], al[mt][1], al[mt][2], al[mt][3],
                                 bh[2 * s], bh[2 * s + 1]);
                    }
            }
        }
        __syncthreads();
    }

#pragma unroll
    for (int mt = 0; mt < 2; mt++)
#pragma unroll
        for (int nt = 0; nt < 8; nt++) {
            int row = bm + wm * 32 + mt * 16 + (lane >> 2);
            int col = bn + wn * 64 + nt * 8 + (lane & 3) * 2;
            *(float2*)&C[(size_t)row * N + col] =
                make_float2(acc[mt][nt][0], acc[mt][nt][1]);
            *(float2*)&C[(size_t)(row + 8) * N + col] =
                make_float2(acc[mt][nt][2], acc[mt][nt][3]);
        }
}

// ---------------------------------------------------------------------------
// RMSNorm + RoPE, fp32 in place
// ---------------------------------------------------------------------------
__global__ __launch_bounds__(256) void norm_rope(
    float* __restrict__ q, float* __restrict__ k,
    const float* __restrict__ freqs)
{
    int gwarp = (blockIdx.x * blockDim.x + threadIdx.x) >> 5;
    int lane  = threadIdx.x & 31;
    const int total = SLEN * (NH + NKV);
    if (gwarp >= total) return;
    int s = gwarp / (NH + NKV);
    int h = gwarp % (NH + NKV);
    float* row = (h < NH) ? (q + ((size_t)s * NH + h) * HD)
                          : (k + ((size_t)s * NKV + (h - NH)) * HD);

    float4 x = *(float4*)&row[lane * 4];
    float ss = x.x * x.x + x.y * x.y + x.z * x.z + x.w * x.w;
#pragma unroll
    for (int off = 16; off; off >>= 1)
        ss += __shfl_xor_sync(0xffffffffu, ss, off);
    float r = rsqrtf(ss * (1.f / 128.f) + 1.1920929e-07f);

    float4 fc = *(const float4*)&freqs[(size_t)s * 128 + lane * 4];
    float x1 = x.x * r, x2 = x.y * r, x3 = x.z * r, x4 = x.w * r;
    float4 o;
    o.x = x1 * fc.x - x2 * fc.y;
    o.y = x1 * fc.y + x2 * fc.x;
    o.z = x3 * fc.z - x4 * fc.w;
    o.w = x3 * fc.w + x4 * fc.z;
    *(float4*)&row[lane * 4] = o;
}

// ---------------------------------------------------------------------------
// Flash attention (causal, sink) with split-bf16 MMA.
// BQ=64, BKV=64, D=128, 256 threads (8 warps: 4m x 2n).
// Q pre-scaled by scale*log2e -> exp2-domain softmax.
// smem (bytes): Qh 0, Ql 17408, Kh 34816, Kl 52224, Ph 69632, Pl 78848,
//               rmax 88064 (2*64 f32), rsum 88576 -> total 89088
// Q/K/V row stride: 136 bf16 = 272 B.  P row stride: 72 bf16 = 144 B.
// Cross-warp (wn) softmax stats exchanged through rmax/rsum.
// ---------------------------------------------------------------------------
__global__ __launch_bounds__(256, 2) void attn_kernel(
    const float* __restrict__ q, const float* __restrict__ k,
    const float* __restrict__ v, const float* __restrict__ sinks,
    float* __restrict__ out)
{
    extern __shared__ char smr[];
    u32* Qh = (u32*)smr;
    u32* Ql = (u32*)(smr + 17408);
    u32* Kh = (u32*)(smr + 34816);
    u32* Kl = (u32*)(smr + 52224);
    float* rmax = (float*)(smr + 88064);   // [2][64]
    float* rsum = (float*)(smr + 88576);   // [2][64]

    const int tid = threadIdx.x, lane = tid & 31, w = tid >> 5;
    const int wm = w >> 1, wn = w & 1;
    const int h = blockIdx.y, kvh = h >> 2;
    const int qt = gridDim.x - 1 - blockIdx.x;   // heavy tiles first

    const float CS = 0.08838834764831845f * 1.4426950408889634f; // scale*log2e

    // load + prescale + split Q tile [64][128]
#pragma unroll
    for (int i = 0; i < 8; i++) {
        int idx = tid + i * 256;
        int r = idx >> 5, c4 = idx & 31;
        float4 xv = *(const float4*)&q[(((size_t)(qt * 64 + r)) * NH + h) * HD + c4 * 4];
        xv.x *= CS; xv.y *= CS; xv.z *= CS; xv.w *= CS;
        u32 h0, h1, l0, l1;
        split2(xv.x, xv.y, h0, l0); split2(xv.z, xv.w, h1, l1);
        int si = r * 68 + c4 * 2;
        Qh[si] = h0; Qh[si + 1] = h1; Ql[si] = l0; Ql[si + 1] = l1;
    }

    float oacc[8][4];
#pragma unroll
    for (int a = 0; a < 8; a++)
#pragma unroll
        for (int c = 0; c < 4; c++) oacc[a][c] = 0.f;
    float mrow[2] = {-1e30f, -1e30f}, lrow[2] = {0.f, 0.f};

    const u32 qa = sptr(Qh) + (wm * 16 + (lane & 15)) * 272 + (lane >> 4) * 16;
    const u32 kb = sptr(Kh) + (wn * 32 + (lane >> 4) * 8 + (lane & 7)) * 272
                   + ((lane >> 3) & 1) * 16;
    const u32 vb = sptr(Kh) + (((lane >> 3) & 1) * 8 + (lane & 7)) * 272
                   + (wn * 64 + (lane >> 4) * 8) * 2;
    const u32 pa = sptr(smr + 69632) + (wm * 16 + (lane & 15)) * 144
                   + (lane >> 4) * 16;
    const int rowl0 = wm * 16 + (lane >> 2);       // local q row, half i adds 8*i
    const int p_col = wn * 32 + (lane & 3) * 2;

    for (int kt = 0; kt <= qt; kt++) {
        __syncthreads();   // (A) prev PV done with V/P; red bufs free
        // load + split K tile
#pragma unroll
        for (int i = 0; i < 8; i++) {
            int idx = tid + i * 256;
            int r = idx >> 5, c4 = idx & 31;
            float4 xv = *(const float4*)&k[(((size_t)(kt * 64 + r)) * NKV + kvh) * HD + c4 * 4];
            u32 h0, h1, l0, l1;
            split2(xv.x, xv.y, h0, l0); split2(xv.z, xv.w, h1, l1);
            int si = r * 68 + c4 * 2;
            Kh[si] = h0; Kh[si + 1] = h1; Kl[si] = l0; Kl[si + 1] = l1;
        }
        __syncthreads();   // (B)

        // S = Q' K^T   (16x32 per warp)
        float sacc[4][4];
#pragma unroll
        for (int a = 0; a < 4; a++)
#pragma unroll
            for (int c = 0; c < 4; c++) sacc[a][c] = 0.f;

#pragma unroll
        for (int ks = 0; ks < 8; ks++) {
            u32 ah0, ah1, ah2, ah3, al0, al1, al2, al3;
            ldm4(qa + ks * 32,         ah0, ah1, ah2, ah3);
            ldm4(qa + 17408 + ks * 32, al0, al1, al2, al3);
#pragma unroll
            for (int g = 0; g < 2; g++) {
                u32 bh[4], bl[4];
                ldm4(kb + g * 4352 + ks * 32,         bh[0], bh[1], bh[2], bh[3]);
                ldm4(kb + 17408 + g * 4352 + ks * 32, bl[0], bl[1], bl[2], bl[3]);
#pragma unroll
                for (int s = 0; s < 2; s++) {
                    float* c = sacc[g * 2 + s];
                    mma16816(c, ah0, ah1, ah2, ah3, bh[2 * s], bh[2 * s + 1]);
                    mma16816(c, ah0, ah1, ah2, ah3, bl[2 * s], bl[2 * s + 1]);
                    mma16816(c, al0, al1, al2, al3, bh[2 * s], bh[2 * s + 1]);
                }
            }
        }

        // causal mask on diagonal tile only
        if (kt == qt) {
            int r0 = qt * 64 + wm * 16 + (lane >> 2);
#pragma unroll
            for (int nt = 0; nt < 4; nt++) {
                int col0 = kt * 64 + wn * 32 + nt * 8 + (lane & 3) * 2;
#pragma unroll
                for (int ci = 0; ci < 4; ci++) {
                    int row = r0 + ((ci >= 2) ? 8 : 0);
                    int col = col0 + (ci & 1);
                    if (col > row) sacc[nt][ci] = -1e30f;
                }
            }
        }

        // --- cross-warp row max ---
        float rmloc[2];
#pragma unroll
        for (int i = 0; i < 2; i++) {
            float rm = -1e30f;
#pragma unroll
            for (int nt = 0; nt < 4; nt++)
                rm = fmaxf(rm, fmaxf(sacc[nt][2 * i], sacc[nt][2 * i + 1]));
            rm = fmaxf(rm, __shfl_xor_sync(0xffffffffu, rm, 1));
            rm = fmaxf(rm, __shfl_xor_sync(0xffffffffu, rm, 2));
            rmloc[i] = rm;
            if ((lane & 3) == 0) rmax[wn * 64 + rowl0 + i * 8] = rm;
        }
        __syncthreads();   // (C) rmax visible

        float alpha[2];
#pragma unroll
        for (int i = 0; i < 2; i++) {
            float cand = fmaxf(rmax[rowl0 + i * 8], rmax[64 + rowl0 + i * 8]);
            float mn = fmaxf(mrow[i], cand);
            alpha[i] = ex2(mrow[i] - mn);
            mrow[i] = mn;
            float rs = 0.f;
            int off = (rowl0 + i * 8 - (lane >> 2)) * 144 + (lane >> 2) * 144 + p_col * 2;
#pragma unroll
            for (int nt = 0; nt < 4; nt++) {
                float p0 = ex2(sacc[nt][2 * i] - mn);
                float p1 = ex2(sacc[nt][2 * i + 1] - mn);
                rs += p0 + p1;
                u32 hh, ll;
                split2(p0, p1, hh, ll);
                *(u32*)(smr + 69632 + off + nt * 16) = hh;
                *(u32*)(smr + 78848 + off + nt * 16) = ll;
            }
            rs += __shfl_xor_sync(0xffffffffu, rs, 1);
            rs += __shfl_xor_sync(0xffffffffu, rs, 2);
            if ((lane & 3) == 0) rsum[wn * 64 + rowl0 + i * 8] = rs;
#pragma unroll
            for (int nt = 0; nt < 8; nt++) {
                oacc[nt][2 * i]     *= alpha[i];
                oacc[nt][2 * i + 1] *= alpha[i];
            }
        }
        __syncthreads();   // (D) rsum + P visible; K reads done

#pragma unroll
        for (int i = 0; i < 2; i++) {
            float rs = rsum[rowl0 + i * 8] + rsum[64 + rowl0 + i * 8];
            lrow[i] = lrow[i] * alpha[i] + rs;
        }

        // load + split V tile into K buffer ([kv][d], ldmatrix.trans later)
#pragma unroll
        for (int i = 0; i < 8; i++) {
            int idx = tid + i * 256;
            int r = idx >> 5, c4 = idx & 31;
            float4 xv = *(const float4*)&v[(((size_t)(kt * 64 + r)) * NKV + kvh) * HD + c4 * 4];
            u32 h0, h1, l0, l1;
            split2(xv.x, xv.y, h0, l0); split2(xv.z, xv.w, h1, l1);
            int si = r * 68 + c4 * 2;
            Kh[si] = h0; Kh[si + 1] = h1; Kl[si] = l0; Kl[si + 1] = l1;
        }
        __syncthreads();   // (E) V visible

        // O += P V   (16x64 per warp)
#pragma unroll
        for (int ks = 0; ks < 4; ks++) {
            u32 ph0, ph1, ph2, ph3, pl0, pl1, pl2, pl3;
            ldm4(pa + ks * 32,        ph0, ph1, ph2, ph3);
            ldm4(pa + 9216 + ks * 32, pl0, pl1, pl2, pl3);
#pragma unroll
            for (int g = 0; g < 4; g++) {
                u32 bh[4], bl[4];
                ldm4t(vb + ks * 4352 + g * 32,         bh[0], bh[1], bh[2], bh[3]);
                ldm4t(vb + 17408 + ks * 4352 + g * 32, bl[0], bl[1], bl[2], bl[3]);
#pragma unroll
                for (int s = 0; s < 2; s++) {
                    float* c = oacc[g * 2 + s];
                    mma16816(c, ph0, ph1, ph2, ph3, bh[2 * s], bh[2 * s + 1]);
                    mma16816(c, ph0, ph1, ph2, ph3, bl[2 * s], bl[2 * s + 1]);
                    mma16816(c, pl0, pl1, pl2, pl3, bh[2 * s], bh[2 * s + 1]);
                }
            }
        }
    }

    // epilogue: lse (from log2 domain), sink sigmoid, normalize
    float sk = sinks[h];
#pragma unroll
    for (int i = 0; i < 2; i++) {
        float lse = mrow[i] * 0.6931471805599453f + logf(lrow[i]);
        float sg = 1.f / (1.f + expf(sk - lse));
        float sc = sg / lrow[i];
        int row = qt * 64 + wm * 16 + (lane >> 2) + i * 8;
        float* op = out + (size_t)row * DMODEL + h * HD;
#pragma unroll
        for (int nt = 0; nt < 8; nt++) {
            int col = wn * 64 + nt * 8 + (lane & 3) * 2;
            *(float2*)&op[col] =
                make_float2(oacc[nt][2 * i] * sc, oacc[nt][2 * i + 1] * sc);
        }
    }
}

// ---------------------------------------------------------------------------
extern "C" void kernel_launch(void* const* d_in, const int* in_sizes, int n_in,
                              void* d_out, int out_size)
{
    const float* x     = (const float*)d_in[0];
    const float* freqs = (const float*)d_in[1];
    const float* wq    = (const float*)d_in[2];
    const float* wk    = (const float*)d_in[3];
    const float* wv    = (const float*)d_in[4];
    const float* wo    = (const float*)d_in[5];
    const float* sinks = (const float*)d_in[6];
    float* out = (float*)d_out;

    float *q, *k, *v, *att;
    cudaGetSymbolAddress((void**)&q,   g_q);
    cudaGetSymbolAddress((void**)&k,   g_k);
    cudaGetSymbolAddress((void**)&v,   g_v);
    cudaGetSymbolAddress((void**)&att, g_att);

    cudaFuncSetAttribute(attn_kernel,
                         cudaFuncAttributeMaxDynamicSharedMemorySize, 89088);

    // QKV projections (split-bf16 tensor cores)
    gemm_nt<<<dim3(16, 16), 256>>>(x, wq, q, SLEN, DMODEL, DMODEL);
    gemm_nt<<<dim3(4, 16),  256>>>(x, wk, k, SLEN, NKV * HD, DMODEL);
    gemm_nt<<<dim3(4, 16),  256>>>(x, wv, v, SLEN, NKV * HD, DMODEL);

    // RMSNorm + RoPE
    norm_rope<<<(SLEN * (NH + NKV) * 32) / 256, 256>>>(q, k, freqs);

    // causal flash attention with sink scaling
    attn_kernel<<<dim3(SLEN / 64, NH), 256, 89088>>>(q, k, v, sinks, att);

    // output projection
    gemm_nt<<<dim3(16, 16), 256>>>(att, wo, out, SLEN, DMODEL, DMODEL);
}

// round 4
// speedup vs baseline: 4.3025x; 1.0920x over previous
#include <cuda_runtime.h>
#include <cuda_bf16.h>
#include <math.h>

typedef unsigned int u32;

#define SLEN 2048
#define DMODEL 2048
#define NH 16
#define NKV 4
#define HD 128
#define MX (SLEN * DMODEL)          // 4194304
#define MKV (SLEN * NKV * HD)       // 1048576
#define WKV (NKV * HD * DMODEL)     // 1048576

// fp32 intermediates (pre-norm q, k)
__device__ __align__(16) float g_qf[MX];
__device__ __align__(16) float g_kf[MKV];

// pre-split bf16 hi/lo arrays
__device__ __align__(16) __nv_bfloat16 s_xh[MX],  s_xl[MX];
__device__ __align__(16) __nv_bfloat16 s_wqh[MX], s_wql[MX];
__device__ __align__(16) __nv_bfloat16 s_wkh[WKV], s_wkl[WKV];
__device__ __align__(16) __nv_bfloat16 s_wvh[WKV], s_wvl[WKV];
__device__ __align__(16) __nv_bfloat16 s_woh[MX], s_wol[MX];
__device__ __align__(16) __nv_bfloat16 s_qh[MX],  s_ql[MX];
__device__ __align__(16) __nv_bfloat16 s_kh[MKV], s_kl[MKV];
__device__ __align__(16) __nv_bfloat16 s_vh[MKV], s_vl[MKV];
__device__ __align__(16) __nv_bfloat16 s_ath[MX], s_atl[MX];

// ---------------------------------------------------------------------------
// helpers
// ---------------------------------------------------------------------------
__device__ __forceinline__ u32 sptr(const void* p) {
    return (u32)__cvta_generic_to_shared(p);
}
__device__ __forceinline__ void ldm4(u32 a, u32& r0, u32& r1, u32& r2, u32& r3) {
    asm volatile("ldmatrix.sync.aligned.m8n8.x4.shared.b16 {%0,%1,%2,%3},[%4];"
                 : "=r"(r0), "=r"(r1), "=r"(r2), "=r"(r3) : "r"(a));
}
__device__ __forceinline__ void ldm4t(u32 a, u32& r0, u32& r1, u32& r2, u32& r3) {
    asm volatile("ldmatrix.sync.aligned.m8n8.x4.trans.shared.b16 {%0,%1,%2,%3},[%4];"
                 : "=r"(r0), "=r"(r1), "=r"(r2), "=r"(r3) : "r"(a));
}
__device__ __forceinline__ void mma16816(float* c, u32 a0, u32 a1, u32 a2, u32 a3,
                                         u32 b0, u32 b1) {
    asm volatile(
        "mma.sync.aligned.m16n8k16.row.col.f32.bf16.bf16.f32 "
        "{%0,%1,%2,%3},{%4,%5,%6,%7},{%8,%9},{%0,%1,%2,%3};"
        : "+f"(c[0]), "+f"(c[1]), "+f"(c[2]), "+f"(c[3])
        : "r"(a0), "r"(a1), "r"(a2), "r"(a3), "r"(b0), "r"(b1));
}
__device__ __forceinline__ u32 packbf(__nv_bfloat16 a, __nv_bfloat16 b) {
    __nv_bfloat162 t = __halves2bfloat162(a, b);
    return *reinterpret_cast<u32*>(&t);
}
__device__ __forceinline__ void split2(float x, float y, u32& h, u32& l) {
    __nv_bfloat16 hx = __float2bfloat16(x), hy = __float2bfloat16(y);
    __nv_bfloat16 lx = __float2bfloat16(x - __bfloat162float(hx));
    __nv_bfloat16 ly = __float2bfloat16(y - __bfloat162float(hy));
    h = packbf(hx, hy);
    l = packbf(lx, ly);
}
__device__ __forceinline__ float ex2(float x) {
    float y; asm("ex2.approx.f32 %0, %1;" : "=f"(y) : "f"(x)); return y;
}
__device__ __forceinline__ void cpa16(u32 dst, const void* src) {
    asm volatile("cp.async.cg.shared.global [%0], [%1], 16;" :: "r"(dst), "l"(src));
}
__device__ __forceinline__ void cpcommit() {
    asm volatile("cp.async.commit_group;");
}
template <int N>
__device__ __forceinline__ void cpwait() {
    asm volatile("cp.async.wait_group %0;" :: "n"(N));
}

// ---------------------------------------------------------------------------
// split fp32 array -> bf16 hi/lo arrays (memory-bound, one pass)
// ---------------------------------------------------------------------------
__global__ __launch_bounds__(256) void split_arr(
    const float* __restrict__ in, __nv_bfloat16* __restrict__ h,
    __nv_bfloat16* __restrict__ l, int n4)
{
    int i = blockIdx.x * blockDim.x + threadIdx.x;
    if (i >= n4) return;
    float4 v = ((const float4*)in)[i];
    u32 h0, h1, l0, l1;
    split2(v.x, v.y, h0, l0); split2(v.z, v.w, h1, l1);
    ((u32*)h)[i * 2] = h0; ((u32*)h)[i * 2 + 1] = h1;
    ((u32*)l)[i * 2] = l0; ((u32*)l)[i * 2 + 1] = l1;
}

// ---------------------------------------------------------------------------
// C[M,N] = A[M,K] @ B[N,K]^T with pre-split bf16 operands, 3-term MMA.
// 128x128x32 tiles, 256 thr (8 warps: 4m x 2n), double-buffered cp.async.
// dyn smem per stage 40960 B: Ah@0 Al@10240 Bh@20480 Bl@30720; row stride 80 B.
// OUTMODE 0: fp32 C.   OUTMODE 1: split bf16 Ch/Cl.
// ---------------------------------------------------------------------------
template <int OUTMODE>
__global__ __launch_bounds__(256, 2) void gemm_bs(
    const __nv_bfloat16* __restrict__ Ah, const __nv_bfloat16* __restrict__ Al,
    const __nv_bfloat16* __restrict__ Bh, const __nv_bfloat16* __restrict__ Bl,
    float* __restrict__ C, __nv_bfloat16* __restrict__ Ch,
    __nv_bfloat16* __restrict__ Cl, int M, int N, int K)
{
    extern __shared__ char smd[];
    const int tid = threadIdx.x, lane = tid & 31, w = tid >> 5;
    const int wm = w >> 1, wn = w & 1;
    const int bm = blockIdx.y * 128, bn = blockIdx.x * 128;
    const u32 smb = sptr(smd);

    float acc[2][8][4];
#pragma unroll
    for (int a = 0; a < 2; a++)
#pragma unroll
        for (int b = 0; b < 8; b++)
#pragma unroll
            for (int c = 0; c < 4; c++) acc[a][b][c] = 0.f;

    const u32 aoff = (wm * 32 + (lane & 15)) * 80 + (lane >> 4) * 16;
    const u32 boff = 20480 + (wn * 64 + (lane >> 4) * 8 + (lane & 7)) * 80
                     + ((lane >> 3) & 1) * 16;

    auto load_stage = [&](int stg, int k0) {
        u32 sb = smb + stg * 40960;
#pragma unroll
        for (int p = 0; p < 2; p++) {
            int c = tid + p * 256;
            int row = c >> 2, kc = (c & 3) * 8;
            u32 d = sb + row * 80 + kc * 2;
            size_t ga = (size_t)(bm + row) * K + k0 + kc;
            size_t gb = (size_t)(bn + row) * K + k0 + kc;
            cpa16(d,         Ah + ga);
            cpa16(d + 10240, Al + ga);
            cpa16(d + 20480, Bh + gb);
            cpa16(d + 30720, Bl + gb);
        }
    };

    const int NCH = K >> 5;
    load_stage(0, 0);
    cpcommit();

    for (int ic = 0; ic < NCH; ic++) {
        if (ic + 1 < NCH) {
            load_stage((ic + 1) & 1, (ic + 1) * 32);
            cpcommit();
            cpwait<1>();
        } else {
            cpwait<0>();
        }
        __syncthreads();
        const u32 base = smb + (ic & 1) * 40960;
        const u32 a_h = base + aoff, a_l = a_h + 10240;
        const u32 b_h = base + boff, b_l = b_h + 10240;
#pragma unroll
        for (int ks = 0; ks < 2; ks++) {
            u32 ah[2][4], al[2][4];
            ldm4(a_h + ks * 32,        ah[0][0], ah[0][1], ah[0][2], ah[0][3]);
            ldm4(a_h + ks * 32 + 1280, ah[1][0], ah[1][1], ah[1][2], ah[1][3]);
            ldm4(a_l + ks * 32,        al[0][0], al[0][1], al[0][2], al[0][3]);
            ldm4(a_l + ks * 32 + 1280, al[1][0], al[1][1], al[1][2], al[1][3]);
#pragma unroll
            for (int g = 0; g < 4; g++) {
                u32 bh[4], bl[4];
                ldm4(b_h + g * 1280 + ks * 32, bh[0], bh[1], bh[2], bh[3]);
                ldm4(b_l + g * 1280 + ks * 32, bl[0], bl[1], bl[2], bl[3]);
#pragma unroll
                for (int mt = 0; mt < 2; mt++)
#pragma unroll
                    for (int s = 0; s < 2; s++) {
                        float* c = acc[mt][g * 2 + s];
                        mma16816(c, ah[mt][0], ah[mt][1], ah[mt][2], ah[mt][3],
                                 bh[2 * s], bh[2 * s + 1]);
                        mma16816(c, ah[mt][0], ah[mt][1], ah[mt][2], ah[mt][3],
                                 bl[2 * s], bl[2 * s + 1]);
                        mma16816(c, al[mt][0], al[mt][1], al[mt][2], al[mt][3],
                                 bh[2 * s], bh[2 * s + 1]);
                    }
            }
        }
        __syncthreads();
    }

#pragma unroll
    for (int mt = 0; mt < 2; mt++)
#pragma unroll
        for (int nt = 0; nt < 8; nt++) {
            int row = bm + wm * 32 + mt * 16 + (lane >> 2);
            int col = bn + wn * 64 + nt * 8 + (lane & 3) * 2;
            if (OUTMODE == 0) {
                *(float2*)&C[(size_t)row * N + col] =
                    make_float2(acc[mt][nt][0], acc[mt][nt][1]);
                *(float2*)&C[(size_t)(row + 8) * N + col] =
                    make_float2(acc[mt][nt][2], acc[mt][nt][3]);
            } else {
                u32 hh, ll;
                split2(acc[mt][nt][0], acc[mt][nt][1], hh, ll);
                ((u32*)Ch)[((size_t)row * N + col) >> 1] = hh;
                ((u32*)Cl)[((size_t)row * N + col) >> 1] = ll;
                split2(acc[mt][nt][2], acc[mt][nt][3], hh, ll);
                ((u32*)Ch)[((size_t)(row + 8) * N + col) >> 1] = hh;
                ((u32*)Cl)[((size_t)(row + 8) * N + col) >> 1] = ll;
            }
        }
}

// ---------------------------------------------------------------------------
// RMSNorm + RoPE on fp32 q/k, output pre-split bf16 (q pre-scaled by CS)
// ---------------------------------------------------------------------------
__global__ __launch_bounds__(256) void norm_rope_split(
    const float* __restrict__ qf, const float* __restrict__ kf,
    const float* __restrict__ freqs,
    __nv_bfloat16* __restrict__ qh, __nv_bfloat16* __restrict__ ql,
    __nv_bfloat16* __restrict__ kh, __nv_bfloat16* __restrict__ kl)
{
    const float CS = 0.08838834764831845f * 1.4426950408889634f; // scale*log2e
    int gwarp = (blockIdx.x * blockDim.x + threadIdx.x) >> 5;
    int lane  = threadIdx.x & 31;
    const int total = SLEN * (NH + NKV);
    if (gwarp >= total) return;
    int s = gwarp / (NH + NKV);
    int h = gwarp % (NH + NKV);
    bool isq = (h < NH);
    size_t base = isq ? ((size_t)s * NH + h) * HD
                      : ((size_t)s * NKV + (h - NH)) * HD;
    const float* row = (isq ? qf : kf) + base;

    float4 x = *(const float4*)&row[lane * 4];
    float ss = x.x * x.x + x.y * x.y + x.z * x.z + x.w * x.w;
#pragma unroll
    for (int off = 16; off; off >>= 1)
        ss += __shfl_xor_sync(0xffffffffu, ss, off);
    float r = rsqrtf(ss * (1.f / 128.f) + 1.1920929e-07f);
    if (isq) r *= CS;

    float4 fc = *(const float4*)&freqs[(size_t)s * 128 + lane * 4];
    float x1 = x.x * r, x2 = x.y * r, x3 = x.z * r, x4 = x.w * r;
    float o0 = x1 * fc.x - x2 * fc.y;
    float o1 = x1 * fc.y + x2 * fc.x;
    float o2 = x3 * fc.z - x4 * fc.w;
    float o3 = x3 * fc.w + x4 * fc.z;

    u32 h0, l0, h1, l1;
    split2(o0, o1, h0, l0); split2(o2, o3, h1, l1);
    u32* H = (u32*)(isq ? qh : kh);
    u32* L = (u32*)(isq ? ql : kl);
    size_t idx = (base >> 1) + lane * 2;
    H[idx] = h0; H[idx + 1] = h1;
    L[idx] = l0; L[idx + 1] = l1;
}

// ---------------------------------------------------------------------------
// Flash attention (causal, sink) with split-bf16 MMA; pre-split inputs,
// pre-split output. BQ=BKV=64, 256 thr (8 warps: 4m x 2n).
// smem: Qh 0, Ql 17408, Kh 34816, Kl 52224 (V reuses K), Ph 69632, Pl 78848,
//       rmax 88064, rsum 88576 -> 89088 total. Tile row stride 272 B.
// ---------------------------------------------------------------------------
__global__ __launch_bounds__(256, 2) void attn_kernel(
    const __nv_bfloat16* __restrict__ qh, const __nv_bfloat16* __restrict__ ql,
    const __nv_bfloat16* __restrict__ kh, const __nv_bfloat16* __restrict__ kl,
    const __nv_bfloat16* __restrict__ vh, const __nv_bfloat16* __restrict__ vl,
    const float* __restrict__ sinks,
    __nv_bfloat16* __restrict__ ath, __nv_bfloat16* __restrict__ atl)
{
    extern __shared__ char smr[];
    const u32 smb = sptr(smr);
    float* rmax = (float*)(smr + 88064);   // [2][64]
    float* rsum = (float*)(smr + 88576);   // [2][64]

    const int tid = threadIdx.x, lane = tid & 31, w = tid >> 5;
    const int wm = w >> 1, wn = w & 1;
    const int h = blockIdx.y, kvh = h >> 2;
    const int qt = gridDim.x - 1 - blockIdx.x;   // heavy tiles first

    // async-load Q tile (hi+lo)
#pragma unroll
    for (int i = 0; i < 4; i++) {
        int c = tid + i * 256;
        int r = c >> 4, ck = c & 15;
        u32 d = smb + r * 272 + ck * 16;
        size_t g = ((size_t)(qt * 64 + r) * NH + h) * HD + ck * 8;
        cpa16(d,         qh + g);
        cpa16(d + 17408, ql + g);
    }
    cpcommit();

    float oacc[8][4];
#pragma unroll
    for (int a = 0; a < 8; a++)
#pragma unroll
        for (int c = 0; c < 4; c++) oacc[a][c] = 0.f;
    float mrow[2] = {-1e30f, -1e30f}, lrow[2] = {0.f, 0.f};

    const u32 qa = smb + (wm * 16 + (lane & 15)) * 272 + (lane >> 4) * 16;
    const u32 kb = smb + 34816 + (wn * 32 + (lane >> 4) * 8 + (lane & 7)) * 272
                   + ((lane >> 3) & 1) * 16;
    const u32 vb = smb + 34816 + (((lane >> 3) & 1) * 8 + (lane & 7)) * 272
                   + (wn * 64 + (lane >> 4) * 8) * 2;
    const u32 pa = smb + 69632 + (wm * 16 + (lane & 15)) * 144 + (lane >> 4) * 16;
    const int rowl0 = wm * 16 + (lane >> 2);
    const int p_col = wn * 32 + (lane & 3) * 2;

    for (int kt = 0; kt <= qt; kt++) {
        __syncthreads();   // (A) prev PV done with V/P buffers
        // async-load K tile
#pragma unroll
        for (int i = 0; i < 4; i++) {
            int c = tid + i * 256;
            int r = c >> 4, ck = c & 15;
            u32 d = smb + 34816 + r * 272 + ck * 16;
            size_t g = ((size_t)(kt * 64 + r) * NKV + kvh) * HD + ck * 8;
            cpa16(d,         kh + g);
            cpa16(d + 17408, kl + g);
        }
        cpcommit();
        cpwait<0>();       // Q (first iter) + K complete
        __syncthreads();   // (B)

        // S = Q' K^T   (16x32 per warp)
        float sacc[4][4];
#pragma unroll
        for (int a = 0; a < 4; a++)
#pragma unroll
            for (int c = 0; c < 4; c++) sacc[a][c] = 0.f;

#pragma unroll
        for (int ks = 0; ks < 8; ks++) {
            u32 ah0, ah1, ah2, ah3, al0, al1, al2, al3;
            ldm4(qa + ks * 32,         ah0, ah1, ah2, ah3);
            ldm4(qa + 17408 + ks * 32, al0, al1, al2, al3);
#pragma unroll
            for (int g = 0; g < 2; g++) {
                u32 bh[4], bl[4];
                ldm4(kb + g * 4352 + ks * 32,         bh[0], bh[1], bh[2], bh[3]);
                ldm4(kb + 17408 + g * 4352 + ks * 32, bl[0], bl[1], bl[2], bl[3]);
#pragma unroll
                for (int s = 0; s < 2; s++) {
                    float* c = sacc[g * 2 + s];
                    mma16816(c, ah0, ah1, ah2, ah3, bh[2 * s], bh[2 * s + 1]);
                    mma16816(c, ah0, ah1, ah2, ah3, bl[2 * s], bl[2 * s + 1]);
                    mma16816(c, al0, al1, al2, al3, bh[2 * s], bh[2 * s + 1]);
                }
            }
        }

        // causal mask on diagonal tile
        if (kt == qt) {
            int r0 = qt * 64 + wm * 16 + (lane >> 2);
#pragma unroll
            for (int nt = 0; nt < 4; nt++) {
                int col0 = kt * 64 + wn * 32 + nt * 8 + (lane & 3) * 2;
#pragma unroll
                for (int ci = 0; ci < 4; ci++) {
                    int row = r0 + ((ci >= 2) ? 8 : 0);
                    int col = col0 + (ci & 1);
                    if (col > row) sacc[nt][ci] = -1e30f;
                }
            }
        }

        // cross-warp row max
#pragma unroll
        for (int i = 0; i < 2; i++) {
            float rm = -1e30f;
#pragma unroll
            for (int nt = 0; nt < 4; nt++)
                rm = fmaxf(rm, fmaxf(sacc[nt][2 * i], sacc[nt][2 * i + 1]));
            rm = fmaxf(rm, __shfl_xor_sync(0xffffffffu, rm, 1));
            rm = fmaxf(rm, __shfl_xor_sync(0xffffffffu, rm, 2));
            if ((lane & 3) == 0) rmax[wn * 64 + rowl0 + i * 8] = rm;
        }
        __syncthreads();   // (C)

        float alpha[2];
#pragma unroll
        for (int i = 0; i < 2; i++) {
            float cand = fmaxf(rmax[rowl0 + i * 8], rmax[64 + rowl0 + i * 8]);
            float mn = fmaxf(mrow[i], cand);
            alpha[i] = ex2(mrow[i] - mn);
            mrow[i] = mn;
            float rs = 0.f;
            int off = (rowl0 + i * 8) * 144 + p_col * 2;
#pragma unroll
            for (int nt = 0; nt < 4; nt++) {
                float p0 = ex2(sacc[nt][2 * i] - mn);
                float p1 = ex2(sacc[nt][2 * i + 1] - mn);
                rs += p0 + p1;
                u32 hh, ll;
                split2(p0, p1, hh, ll);
                *(u32*)(smr + 69632 + off + nt * 16) = hh;
                *(u32*)(smr + 78848 + off + nt * 16) = ll;
            }
            rs += __shfl_xor_sync(0xffffffffu, rs, 1);
            rs += __shfl_xor_sync(0xffffffffu, rs, 2);
            if ((lane & 3) == 0) rsum[wn * 64 + rowl0 + i * 8] = rs;
#pragma unroll
            for (int nt = 0; nt < 8; nt++) {
                oacc[nt][2 * i]     *= alpha[i];
                oacc[nt][2 * i + 1] *= alpha[i];
            }
        }
        __syncthreads();   // (D) rsum + P visible; K smem reads done

#pragma unroll
        for (int i = 0; i < 2; i++) {
            float rs = rsum[rowl0 + i * 8] + rsum[64 + rowl0 + i * 8];
            lrow[i] = lrow[i] * alpha[i] + rs;
        }

        // async-load V tile into K buffer
#pragma unroll
        for (int i = 0; i < 4; i++) {
            int c = tid + i * 256;
            int r = c >> 4, ck = c & 15;
            u32 d = smb + 34816 + r * 272 + ck * 16;
            size_t g = ((size_t)(kt * 64 + r) * NKV + kvh) * HD + ck * 8;
            cpa16(d,         vh + g);
            cpa16(d + 17408, vl + g);
        }
        cpcommit();
        cpwait<0>();
        __syncthreads();   // (E)

        // O += P V
#pragma unroll
        for (int ks = 0; ks < 4; ks++) {
            u32 ph0, ph1, ph2, ph3, pl0, pl1, pl2, pl3;
            ldm4(pa + ks * 32,        ph0, ph1, ph2, ph3);
            ldm4(pa + 9216 + ks * 32, pl0, pl1, pl2, pl3);
#pragma unroll
            for (int g = 0; g < 4; g++) {
                u32 bh[4], bl[4];
                ldm4t(vb + ks * 4352 + g * 32,         bh[0], bh[1], bh[2], bh[3]);
                ldm4t(vb + 17408 + ks * 4352 + g * 32, bl[0], bl[1], bl[2], bl[3]);
#pragma unroll
                for (int s = 0; s < 2; s++) {
                    float* c = oacc[g * 2 + s];
                    mma16816(c, ph0, ph1, ph2, ph3, bh[2 * s], bh[2 * s + 1]);
                    mma16816(c, ph0, ph1, ph2, ph3, bl[2 * s], bl[2 * s + 1]);
                    mma16816(c, pl0, pl1, pl2, pl3, bh[2 * s], bh[2 * s + 1]);
                }
            }
        }
    }

    // epilogue: lse, sink sigmoid, normalize, split-store
    float sk = sinks[h];
#pragma unroll
    for (int i = 0; i < 2; i++) {
        float lse = mrow[i] * 0.6931471805599453f + logf(lrow[i]);
        float sg = 1.f / (1.f + expf(sk - lse));
        float sc = sg / lrow[i];
        int row = qt * 64 + wm * 16 + (lane >> 2) + i * 8;
        size_t rb = (size_t)row * DMODEL + h * HD;
#pragma unroll
        for (int nt = 0; nt < 8; nt++) {
            int col = wn * 64 + nt * 8 + (lane & 3) * 2;
            u32 hh, ll;
            split2(oacc[nt][2 * i] * sc, oacc[nt][2 * i + 1] * sc, hh, ll);
            ((u32*)ath)[(rb + col) >> 1] = hh;
            ((u32*)atl)[(rb + col) >> 1] = ll;
        }
    }
}

// ---------------------------------------------------------------------------
extern "C" void kernel_launch(void* const* d_in, const int* in_sizes, int n_in,
                              void* d_out, int out_size)
{
    const float* x     = (const float*)d_in[0];
    const float* freqs = (const float*)d_in[1];
    const float* wq    = (const float*)d_in[2];
    const float* wk    = (const float*)d_in[3];
    const float* wv    = (const float*)d_in[4];
    const float* wo    = (const float*)d_in[5];
    const float* sinks = (const float*)d_in[6];
    float* out = (float*)d_out;

    float *qf, *kf;
    __nv_bfloat16 *xh, *xl, *wqh, *wql, *wkh, *wkl, *wvh, *wvl, *woh, *wol;
    __nv_bfloat16 *qh, *ql, *kh, *kl, *vh, *vl, *ath, *atl;
    cudaGetSymbolAddress((void**)&qf,  g_qf);
    cudaGetSymbolAddress((void**)&kf,  g_kf);
    cudaGetSymbolAddress((void**)&xh,  s_xh);  cudaGetSymbolAddress((void**)&xl,  s_xl);
    cudaGetSymbolAddress((void**)&wqh, s_wqh); cudaGetSymbolAddress((void**)&wql, s_wql);
    cudaGetSymbolAddress((void**)&wkh, s_wkh); cudaGetSymbolAddress((void**)&wkl, s_wkl);
    cudaGetSymbolAddress((void**)&wvh, s_wvh); cudaGetSymbolAddress((void**)&wvl, s_wvl);
    cudaGetSymbolAddress((void**)&woh, s_woh); cudaGetSymbolAddress((void**)&wol, s_wol);
    cudaGetSymbolAddress((void**)&qh,  s_qh);  cudaGetSymbolAddress((void**)&ql,  s_ql);
    cudaGetSymbolAddress((void**)&kh,  s_kh);  cudaGetSymbolAddress((void**)&kl,  s_kl);
    cudaGetSymbolAddress((void**)&vh,  s_vh);  cudaGetSymbolAddress((void**)&vl,  s_vl);
    cudaGetSymbolAddress((void**)&ath, s_ath); cudaGetSymbolAddress((void**)&atl, s_atl);

    cudaFuncSetAttribute(gemm_bs<0>, cudaFuncAttributeMaxDynamicSharedMemorySize, 81920);
    cudaFuncSetAttribute(gemm_bs<1>, cudaFuncAttributeMaxDynamicSharedMemorySize, 81920);
    cudaFuncSetAttribute(attn_kernel, cudaFuncAttributeMaxDynamicSharedMemorySize, 89088);

    // pre-split inputs
    split_arr<<<MX / 4 / 256, 256>>>(x,  xh,  xl,  MX / 4);
    split_arr<<<MX / 4 / 256, 256>>>(wq, wqh, wql, MX / 4);
    split_arr<<<WKV / 4 / 256, 256>>>(wk, wkh, wkl, WKV / 4);
    split_arr<<<WKV / 4 / 256, 256>>>(wv, wvh, wvl, WKV / 4);
    split_arr<<<MX / 4 / 256, 256>>>(wo, woh, wol, MX / 4);

    // QKV projections
    gemm_bs<0><<<dim3(16, 16), 256, 81920>>>(xh, xl, wqh, wql, qf, nullptr, nullptr,
                                             SLEN, DMODEL, DMODEL);
    gemm_bs<0><<<dim3(4, 16), 256, 81920>>>(xh, xl, wkh, wkl, kf, nullptr, nullptr,
                                            SLEN, NKV * HD, DMODEL);
    gemm_bs<1><<<dim3(4, 16), 256, 81920>>>(xh, xl, wvh, wvl, nullptr, vh, vl,
                                            SLEN, NKV * HD, DMODEL);

    // RMSNorm + RoPE -> pre-split q/k (q pre-scaled)
    norm_rope_split<<<(SLEN * (NH + NKV) * 32) / 256, 256>>>(qf, kf, freqs,
                                                             qh, ql, kh, kl);

    // causal flash attention with sink scaling -> pre-split att
    attn_kernel<<<dim3(SLEN / 64, NH), 256, 89088>>>(qh, ql, kh, kl, vh, vl,
                                                     sinks, ath, atl);

    // output projection
    gemm_bs<0><<<dim3(16, 16), 256, 81920>>>(ath, atl, woh, wol, out, nullptr, nullptr,
                                             SLEN, DMODEL, DMODEL);
}

// round 6
// speedup vs baseline: 7.2983x; 1.6963x over previous
#include <cuda_runtime.h>
#include <cuda_fp16.h>
#include <math.h>

typedef unsigned int u32;

#define SLEN 2048
#define DMODEL 2048
#define NH 16
#define NKV 4
#define HD 128
#define MX (SLEN * DMODEL)          // 4194304
#define MKV (SLEN * NKV * HD)       // 1048576
#define WKV (NKV * HD * DMODEL)     // 1048576

// fp32 packed QKV projection output: [s][3072] (q 0-2047, k 2048-2559, v 2560-3071)
__device__ __align__(16) float g_qkvf[SLEN * 3072];

// fp16 operands
__device__ __align__(16) __half s_xh[MX], s_xl[MX];          // x split
__device__ __align__(16) __half s_wqkvh[3072 * DMODEL];      // packed wq|wk|wv, single
__device__ __align__(16) __half s_woh[MX];                   // wo, single
__device__ __align__(16) __half s_qh[MX], s_ql[MX];          // q split (post norm+rope)
__device__ __align__(16) __half s_kh[MKV];                   // k single (post norm+rope)
__device__ __align__(16) __half s_vh[MKV];                   // v single
__device__ __align__(16) __half s_ath[MX], s_atl[MX];        // attention out split

// ---------------------------------------------------------------------------
// helpers
// ---------------------------------------------------------------------------
__device__ __forceinline__ u32 sptr(const void* p) {
    return (u32)__cvta_generic_to_shared(p);
}
__device__ __forceinline__ void ldm4(u32 a, u32& r0, u32& r1, u32& r2, u32& r3) {
    asm volatile("ldmatrix.sync.aligned.m8n8.x4.shared.b16 {%0,%1,%2,%3},[%4];"
                 : "=r"(r0), "=r"(r1), "=r"(r2), "=r"(r3) : "r"(a));
}
__device__ __forceinline__ void ldm4t(u32 a, u32& r0, u32& r1, u32& r2, u32& r3) {
    asm volatile("ldmatrix.sync.aligned.m8n8.x4.trans.shared.b16 {%0,%1,%2,%3},[%4];"
                 : "=r"(r0), "=r"(r1), "=r"(r2), "=r"(r3) : "r"(a));
}
__device__ __forceinline__ void mma_h(float* c, u32 a0, u32 a1, u32 a2, u32 a3,
                                      u32 b0, u32 b1) {
    asm volatile(
        "mma.sync.aligned.m16n8k16.row.col.f32.f16.f16.f32 "
        "{%0,%1,%2,%3},{%4,%5,%6,%7},{%8,%9},{%0,%1,%2,%3};"
        : "+f"(c[0]), "+f"(c[1]), "+f"(c[2]), "+f"(c[3])
        : "r"(a0), "r"(a1), "r"(a2), "r"(a3), "r"(b0), "r"(b1));
}
__device__ __forceinline__ u32 pack2h(__half a, __half b) {
    __half2 t = __halves2half2(a, b);
    return *reinterpret_cast<u32*>(&t);
}
__device__ __forceinline__ u32 cvt2h(float x, float y) {
    return pack2h(__float2half_rn(x), __float2half_rn(y));
}
__device__ __forceinline__ void split2h(float x, float y, u32& h, u32& l) {
    __half hx = __float2half_rn(x), hy = __float2half_rn(y);
    __half lx = __float2half_rn(x - __half2float(hx));
    __half ly = __float2half_rn(y - __half2float(hy));
    h = pack2h(hx, hy);
    l = pack2h(lx, ly);
}
__device__ __forceinline__ float ex2(float x) {
    float y; asm("ex2.approx.f32 %0, %1;" : "=f"(y) : "f"(x)); return y;
}
__device__ __forceinline__ void cpa16(u32 dst, const void* src) {
    asm volatile("cp.async.cg.shared.global [%0], [%1], 16;" :: "r"(dst), "l"(src));
}
__device__ __forceinline__ void cpcommit() {
    asm volatile("cp.async.commit_group;");
}
template <int N>
__device__ __forceinline__ void cpwait() {
    asm volatile("cp.async.wait_group %0;" :: "n"(N));
}

// ---------------------------------------------------------------------------
// fp32 -> fp16 split (hi/lo) and single convert, memory-bound passes
// ---------------------------------------------------------------------------
__global__ __launch_bounds__(256) void split_x(
    const float* __restrict__ in, __half* __restrict__ h,
    __half* __restrict__ l, int n4)
{
    int i = blockIdx.x * blockDim.x + threadIdx.x;
    if (i >= n4) return;
    float4 v = ((const float4*)in)[i];
    u32 h0, h1, l0, l1;
    split2h(v.x, v.y, h0, l0); split2h(v.z, v.w, h1, l1);
    ((u32*)h)[i * 2] = h0; ((u32*)h)[i * 2 + 1] = h1;
    ((u32*)l)[i * 2] = l0; ((u32*)l)[i * 2 + 1] = l1;
}
__global__ __launch_bounds__(256) void cvt_arr(
    const float* __restrict__ in, __half* __restrict__ out, int n4)
{
    int i = blockIdx.x * blockDim.x + threadIdx.x;
    if (i >= n4) return;
    float4 v = ((const float4*)in)[i];
    ((u32*)out)[i * 2]     = cvt2h(v.x, v.y);
    ((u32*)out)[i * 2 + 1] = cvt2h(v.z, v.w);
}

// ---------------------------------------------------------------------------
// C[M,N] = A[M,K] @ B[N,K]^T ; A split fp16 hi/lo (2-term), B single fp16.
// 128x128x32 tiles, 256 thr (8 warps: 4m x 2n), double-buffered cp.async.
// dyn smem per stage 30720 B: Ah@0 Al@10240 B@20480; row stride 80 B.
// ---------------------------------------------------------------------------
__global__ __launch_bounds__(256, 2) void gemm2(
    const __half* __restrict__ Ah, const __half* __restrict__ Al,
    const __half* __restrict__ Bh, float* __restrict__ C, int M, int N, int K)
{
    extern __shared__ char smd[];
    const u32 smb = sptr(smd);
    const int tid = threadIdx.x, lane = tid & 31, w = tid >> 5;
    const int wm = w >> 1, wn = w & 1;
    const int bm = blockIdx.y * 128, bn = blockIdx.x * 128;

    float acc[2][8][4];
#pragma unroll
    for (int a = 0; a < 2; a++)
#pragma unroll
        for (int b = 0; b < 8; b++)
#pragma unroll
            for (int c = 0; c < 4; c++) acc[a][b][c] = 0.f;

    const u32 aoff = (wm * 32 + (lane & 15)) * 80 + (lane >> 4) * 16;
    const u32 boff = 20480 + (wn * 64 + (lane >> 4) * 8 + (lane & 7)) * 80
                     + ((lane >> 3) & 1) * 16;

    auto load_stage = [&](int stg, int k0) {
        u32 sb = smb + stg * 30720;
#pragma unroll
        for (int p = 0; p < 2; p++) {
            int c = tid + p * 256;
            int row = c >> 2, kc = (c & 3) * 8;
            u32 d = sb + row * 80 + kc * 2;
            size_t ga = (size_t)(bm + row) * K + k0 + kc;
            size_t gb = (size_t)(bn + row) * K + k0 + kc;
            cpa16(d,         Ah + ga);
            cpa16(d + 10240, Al + ga);
            cpa16(d + 20480, Bh + gb);
        }
        cpcommit();
    };

    const int NCH = K >> 5;
    load_stage(0, 0);

    for (int ic = 0; ic < NCH; ic++) {
        if (ic + 1 < NCH) {
            load_stage((ic + 1) & 1, (ic + 1) * 32);
            cpwait<1>();
        } else {
            cpwait<0>();
        }
        __syncthreads();
        const u32 base = smb + (ic & 1) * 30720;
        const u32 a_h = base + aoff, a_l = a_h + 10240;
        const u32 b_ = base + boff;
#pragma unroll
        for (int ks = 0; ks < 2; ks++) {
            u32 ah[2][4], al[2][4];
            ldm4(a_h + ks * 32,        ah[0][0], ah[0][1], ah[0][2], ah[0][3]);
            ldm4(a_h + ks * 32 + 1280, ah[1][0], ah[1][1], ah[1][2], ah[1][3]);
            ldm4(a_l + ks * 32,        al[0][0], al[0][1], al[0][2], al[0][3]);
            ldm4(a_l + ks * 32 + 1280, al[1][0], al[1][1], al[1][2], al[1][3]);
#pragma unroll
            for (int g = 0; g < 4; g++) {
                u32 bh[4];
                ldm4(b_ + g * 1280 + ks * 32, bh[0], bh[1], bh[2], bh[3]);
#pragma unroll
                for (int mt = 0; mt < 2; mt++)
#pragma unroll
                    for (int s = 0; s < 2; s++) {
                        float* c = acc[mt][g * 2 + s];
                        mma_h(c, ah[mt][0], ah[mt][1], ah[mt][2], ah[mt][3],
                              bh[2 * s], bh[2 * s + 1]);
                        mma_h(c, al[mt][0], al[mt][1], al[mt][2], al[mt][3],
                              bh[2 * s], bh[2 * s + 1]);
                    }
            }
        }
        __syncthreads();
    }

#pragma unroll
    for (int mt = 0; mt < 2; mt++)
#pragma unroll
        for (int nt = 0; nt < 8; nt++) {
            int row = bm + wm * 32 + mt * 16 + (lane >> 2);
            int col = bn + wn * 64 + nt * 8 + (lane & 3) * 2;
            *(float2*)&C[(size_t)row * N + col] =
                make_float2(acc[mt][nt][0], acc[mt][nt][1]);
            *(float2*)&C[(size_t)(row + 8) * N + col] =
                make_float2(acc[mt][nt][2], acc[mt][nt][3]);
        }
}

// ---------------------------------------------------------------------------
// RMSNorm + RoPE + convert from packed qkv fp32.
// 24 warps per seq pos: h<16 q (split fp16), 16-19 k (single), 20-23 v (single).
// ---------------------------------------------------------------------------
__global__ __launch_bounds__(256) void norm_rope_cvt(
    const float* __restrict__ qkvf, const float* __restrict__ freqs,
    __half* __restrict__ qh, __half* __restrict__ ql,
    __half* __restrict__ kh, __half* __restrict__ vh)
{
    int gwarp = (blockIdx.x * blockDim.x + threadIdx.x) >> 5;
    int lane  = threadIdx.x & 31;
    const int total = SLEN * 24;
    if (gwarp >= total) return;
    int s = gwarp / 24;
    int h = gwarp % 24;

    if (h >= 20) {   // v: plain convert
        const float* row = qkvf + (size_t)s * 3072 + 2560 + (h - 20) * 128;
        float4 x = *(const float4*)&row[lane * 4];
        size_t idx = ((((size_t)s * NKV + (h - 20)) * HD) >> 1) + lane * 2;
        ((u32*)vh)[idx]     = cvt2h(x.x, x.y);
        ((u32*)vh)[idx + 1] = cvt2h(x.z, x.w);
        return;
    }

    bool isq = (h < 16);
    const float* row = qkvf + (size_t)s * 3072 + (isq ? h * 128 : 2048 + (h - 16) * 128);
    float4 x = *(const float4*)&row[lane * 4];
    float ss = x.x * x.x + x.y * x.y + x.z * x.z + x.w * x.w;
#pragma unroll
    for (int off = 16; off; off >>= 1)
        ss += __shfl_xor_sync(0xffffffffu, ss, off);
    float r = rsqrtf(ss * (1.f / 128.f) + 1.1920929e-07f);

    float4 fc = *(const float4*)&freqs[(size_t)s * 128 + lane * 4];
    float x1 = x.x * r, x2 = x.y * r, x3 = x.z * r, x4 = x.w * r;
    float o0 = x1 * fc.x - x2 * fc.y;
    float o1 = x1 * fc.y + x2 * fc.x;
    float o2 = x3 * fc.z - x4 * fc.w;
    float o3 = x3 * fc.w + x4 * fc.z;

    if (isq) {
        size_t idx = ((((size_t)s * NH + h) * HD) >> 1) + lane * 2;
        u32 h0, l0, h1, l1;
        split2h(o0, o1, h0, l0); split2h(o2, o3, h1, l1);
        ((u32*)qh)[idx] = h0; ((u32*)qh)[idx + 1] = h1;
        ((u32*)ql)[idx] = l0; ((u32*)ql)[idx + 1] = l1;
    } else {
        size_t idx = ((((size_t)s * NKV + (h - 16)) * HD) >> 1) + lane * 2;
        ((u32*)kh)[idx]     = cvt2h(o0, o1);
        ((u32*)kh)[idx + 1] = cvt2h(o2, o3);
    }
}

// ---------------------------------------------------------------------------
// Flash attention (causal, sink), 2-term fp16 MMA.
// BQ=BKV=64, 256 thr (8 warps: 4m x 2n). q split, k/v single, P split.
// smem: Qh 0 (17408), Ql 17408, KV 34816 (17408), Ph 52224 (9216), Pl 61440,
//       rmax 70656, rsum 71168 -> total 71680. Tile row stride 272 B.
// ---------------------------------------------------------------------------
__global__ __launch_bounds__(256, 2) void attn_kernel(
    const __half* __restrict__ qh, const __half* __restrict__ ql,
    const __half* __restrict__ kh, const __half* __restrict__ vh,
    const float* __restrict__ sinks,
    __half* __restrict__ ath, __half* __restrict__ atl)
{
    extern __shared__ char smr[];
    const u32 smb = sptr(smr);
    float* rmax = (float*)(smr + 70656);   // [2][64]
    float* rsum = (float*)(smr + 71168);   // [2][64]

    const int tid = threadIdx.x, lane = tid & 31, w = tid >> 5;
    const int wm = w >> 1, wn = w & 1;
    const int h = blockIdx.y, kvh = h >> 2;
    const int qt = gridDim.x - 1 - blockIdx.x;   // heavy tiles first

    const float CS = 0.08838834764831845f * 1.4426950408889634f; // scale*log2e

    // async-load Q tile (hi+lo)
#pragma unroll
    for (int i = 0; i < 4; i++) {
        int c = tid + i * 256;
        int r = c >> 4, ck = c & 15;
        u32 d = smb + r * 272 + ck * 16;
        size_t g = ((size_t)(qt * 64 + r) * NH + h) * HD + ck * 8;
        cpa16(d,         qh + g);
        cpa16(d + 17408, ql + g);
    }
    cpcommit();

    float oacc[8][4];
#pragma unroll
    for (int a = 0; a < 8; a++)
#pragma unroll
        for (int c = 0; c < 4; c++) oacc[a][c] = 0.f;
    float mrow[2] = {-1e30f, -1e30f}, lrow[2] = {0.f, 0.f};

    const u32 qa = smb + (wm * 16 + (lane & 15)) * 272 + (lane >> 4) * 16;
    const u32 kb = smb + 34816 + (wn * 32 + (lane >> 4) * 8 + (lane & 7)) * 272
                   + ((lane >> 3) & 1) * 16;
    const u32 vb = smb + 34816 + (((lane >> 3) & 1) * 8 + (lane & 7)) * 272
                   + (wn * 64 + (lane >> 4) * 8) * 2;
    const u32 pa = smb + 52224 + (wm * 16 + (lane & 15)) * 144 + (lane >> 4) * 16;
    const int rowl0 = wm * 16 + (lane >> 2);
    const int p_col = wn * 32 + (lane & 3) * 2;

    for (int kt = 0; kt <= qt; kt++) {
        __syncthreads();   // (A) prev PV done with KV/P buffers
        // async-load K tile (single)
#pragma unroll
        for (int i = 0; i < 4; i++) {
            int c = tid + i * 256;
            int r = c >> 4, ck = c & 15;
            u32 d = smb + 34816 + r * 272 + ck * 16;
            size_t g = ((size_t)(kt * 64 + r) * NKV + kvh) * HD + ck * 8;
            cpa16(d, kh + g);
        }
        cpcommit();
        cpwait<0>();
        __syncthreads();   // (B)

        // S = q K^T (16x32 per warp), 2-term
        float sacc[4][4];
#pragma unroll
        for (int a = 0; a < 4; a++)
#pragma unroll
            for (int c = 0; c < 4; c++) sacc[a][c] = 0.f;

#pragma unroll
        for (int ks = 0; ks < 8; ks++) {
            u32 ah0, ah1, ah2, ah3, al0, al1, al2, al3;
            ldm4(qa + ks * 32,         ah0, ah1, ah2, ah3);
            ldm4(qa + 17408 + ks * 32, al0, al1, al2, al3);
#pragma unroll
            for (int g = 0; g < 2; g++) {
                u32 bh[4];
                ldm4(kb + g * 4352 + ks * 32, bh[0], bh[1], bh[2], bh[3]);
#pragma unroll
                for (int s = 0; s < 2; s++) {
                    float* c = sacc[g * 2 + s];
                    mma_h(c, ah0, ah1, ah2, ah3, bh[2 * s], bh[2 * s + 1]);
                    mma_h(c, al0, al1, al2, al3, bh[2 * s], bh[2 * s + 1]);
                }
            }
        }

        // scale to log2 domain
#pragma unroll
        for (int a = 0; a < 4; a++)
#pragma unroll
            for (int c = 0; c < 4; c++) sacc[a][c] *= CS;

        // causal mask on diagonal tile
        if (kt == qt) {
            int r0 = qt * 64 + wm * 16 + (lane >> 2);
#pragma unroll
            for (int nt = 0; nt < 4; nt++) {
                int col0 = kt * 64 + wn * 32 + nt * 8 + (lane & 3) * 2;
#pragma unroll
                for (int ci = 0; ci < 4; ci++) {
                    int row = r0 + ((ci >= 2) ? 8 : 0);
                    int col = col0 + (ci & 1);
                    if (col > row) sacc[nt][ci] = -1e30f;
                }
            }
        }

        // cross-warp row max
#pragma unroll
        for (int i = 0; i < 2; i++) {
            float rm = -1e30f;
#pragma unroll
            for (int nt = 0; nt < 4; nt++)
                rm = fmaxf(rm, fmaxf(sacc[nt][2 * i], sacc[nt][2 * i + 1]));
            rm = fmaxf(rm, __shfl_xor_sync(0xffffffffu, rm, 1));
            rm = fmaxf(rm, __shfl_xor_sync(0xffffffffu, rm, 2));
            if ((lane & 3) == 0) rmax[wn * 64 + rowl0 + i * 8] = rm;
        }
        __syncthreads();   // (C)

        float alpha[2];
#pragma unroll
        for (int i = 0; i < 2; i++) {
            float cand = fmaxf(rmax[rowl0 + i * 8], rmax[64 + rowl0 + i * 8]);
            float mn = fmaxf(mrow[i], cand);
            alpha[i] = ex2(mrow[i] - mn);
            mrow[i] = mn;
            float rs = 0.f;
            int off = (rowl0 + i * 8) * 144 + p_col * 2;
#pragma unroll
            for (int nt = 0; nt < 4; nt++) {
                float p0 = ex2(sacc[nt][2 * i] - mn);
                float p1 = ex2(sacc[nt][2 * i + 1] - mn);
                rs += p0 + p1;
                u32 hh, ll;
                split2h(p0, p1, hh, ll);
                *(u32*)(smr + 52224 + off + nt * 16) = hh;
                *(u32*)(smr + 61440 + off + nt * 16) = ll;
            }
            rs += __shfl_xor_sync(0xffffffffu, rs, 1);
            rs += __shfl_xor_sync(0xffffffffu, rs, 2);
            if ((lane & 3) == 0) rsum[wn * 64 + rowl0 + i * 8] = rs;
#pragma unroll
            for (int nt = 0; nt < 8; nt++) {
                oacc[nt][2 * i]     *= alpha[i];
                oacc[nt][2 * i + 1] *= alpha[i];
            }
        }
        __syncthreads();   // (D) rsum + P visible; K smem reads done

#pragma unroll
        for (int i = 0; i < 2; i++) {
            float rs = rsum[rowl0 + i * 8] + rsum[64 + rowl0 + i * 8];
            lrow[i] = lrow[i] * alpha[i] + rs;
        }

        // async-load V tile (single) into KV buffer
#pragma unroll
        for (int i = 0; i < 4; i++) {
            int c = tid + i * 256;
            int r = c >> 4, ck = c & 15;
            u32 d = smb + 34816 + r * 272 + ck * 16;
            size_t g = ((size_t)(kt * 64 + r) * NKV + kvh) * HD + ck * 8;
            cpa16(d, vh + g);
        }
        cpcommit();
        cpwait<0>();
        __syncthreads();   // (E)

        // O += P V, 2-term (P split, V single)
#pragma unroll
        for (int ks = 0; ks < 4; ks++) {
            u32 ph0, ph1, ph2, ph3, pl0, pl1, pl2, pl3;
            ldm4(pa + ks * 32,        ph0, ph1, ph2, ph3);
            ldm4(pa + 9216 + ks * 32, pl0, pl1, pl2, pl3);
#pragma unroll
            for (int g = 0; g < 4; g++) {
                u32 bh[4];
                ldm4t(vb + ks * 4352 + g * 32, bh[0], bh[1], bh[2], bh[3]);
#pragma unroll
                for (int s = 0; s < 2; s++) {
                    float* c = oacc[g * 2 + s];
                    mma_h(c, ph0, ph1, ph2, ph3, bh[2 * s], bh[2 * s + 1]);
                    mma_h(c, pl0, pl1, pl2, pl3, bh[2 * s], bh[2 * s + 1]);
                }
            }
        }
    }

    // epilogue: lse, sink sigmoid, normalize, split-store
    float sk = sinks[h];
#pragma unroll
    for (int i = 0; i < 2; i++) {
        float lse = mrow[i] * 0.6931471805599453f + logf(lrow[i]);
        float sg = 1.f / (1.f + expf(sk - lse));
        float sc = sg / lrow[i];
        int row = qt * 64 + wm * 16 + (lane >> 2) + i * 8;
        size_t rb = (size_t)row * DMODEL + h * HD;
#pragma unroll
        for (int nt = 0; nt < 8; nt++) {
            int col = wn * 64 + nt * 8 + (lane & 3) * 2;
            u32 hh, ll;
            split2h(oacc[nt][2 * i] * sc, oacc[nt][2 * i + 1] * sc, hh, ll);
            ((u32*)ath)[(rb + col) >> 1] = hh;
            ((u32*)atl)[(rb + col) >> 1] = ll;
        }
    }
}

// ---------------------------------------------------------------------------
extern "C" void kernel_launch(void* const* d_in, const int* in_sizes, int n_in,
                              void* d_out, int out_size)
{
    const float* x     = (const float*)d_in[0];
    const float* freqs = (const float*)d_in[1];
    const float* wq    = (const float*)d_in[2];
    const float* wk    = (const float*)d_in[3];
    const float* wv    = (const float*)d_in[4];
    const float* wo    = (const float*)d_in[5];
    const float* sinks = (const float*)d_in[6];
    float* out = (float*)d_out;

    float* qkvf;
    __half *xh, *xl, *wqkvh, *woh, *qh, *ql, *kh, *vh, *ath, *atl;
    cudaGetSymbolAddress((void**)&qkvf,  g_qkvf);
    cudaGetSymbolAddress((void**)&xh,    s_xh);
    cudaGetSymbolAddress((void**)&xl,    s_xl);
    cudaGetSymbolAddress((void**)&wqkvh, s_wqkvh);
    cudaGetSymbolAddress((void**)&woh,   s_woh);
    cudaGetSymbolAddress((void**)&qh,    s_qh);
    cudaGetSymbolAddress((void**)&ql,    s_ql);
    cudaGetSymbolAddress((void**)&kh,    s_kh);
    cudaGetSymbolAddress((void**)&vh,    s_vh);
    cudaGetSymbolAddress((void**)&ath,   s_ath);
    cudaGetSymbolAddress((void**)&atl,   s_atl);

    cudaFuncSetAttribute(gemm2, cudaFuncAttributeMaxDynamicSharedMemorySize, 61440);
    cudaFuncSetAttribute(attn_kernel, cudaFuncAttributeMaxDynamicSharedMemorySize, 71680);

    // prepare fp16 operands
    split_x<<<MX / 4 / 256, 256>>>(x, xh, xl, MX / 4);
    cvt_arr<<<MX / 4 / 256, 256>>>(wq, wqkvh, MX / 4);
    cvt_arr<<<WKV / 4 / 256, 256>>>(wk, wqkvh + 2048 * DMODEL, WKV / 4);
    cvt_arr<<<WKV / 4 / 256, 256>>>(wv, wqkvh + 2560 * DMODEL, WKV / 4);
    cvt_arr<<<MX / 4 / 256, 256>>>(wo, woh, MX / 4);

    // fused QKV projection: [2048, 3072] = x @ [wq|wk|wv]^T
    gemm2<<<dim3(24, 16), 256, 61440>>>(xh, xl, wqkvh, qkvf, SLEN, 3072, DMODEL);

    // RMSNorm + RoPE + convert (q split, k/v single)
    norm_rope_cvt<<<(SLEN * 24 * 32) / 256, 256>>>(qkvf, freqs, qh, ql, kh, vh);

    // causal flash attention with sink scaling
    attn_kernel<<<dim3(SLEN / 64, NH), 256, 71680>>>(qh, ql, kh, vh, sinks, ath, atl);

    // output projection
    gemm2<<<dim3(16, 16), 256, 61440>>>(ath, atl, woh, out, SLEN, DMODEL, DMODEL);
}

// round 8
// speedup vs baseline: 7.3604x; 1.0085x over previous
#include <cuda_runtime.h>
#include <cuda_fp16.h>
#include <math.h>

typedef unsigned int u32;

#define SLEN 2048
#define DMODEL 2048
#define NH 16
#define NKV 4
#define HD 128
#define MX (SLEN * DMODEL)          // 4194304
#define MKV (SLEN * NKV * HD)       // 1048576
#define WKV (NKV * HD * DMODEL)     // 1048576
#define N4X (MX / 4)                // 1048576 float4 items
#define N4KV (WKV / 4)              // 262144

// fp32 packed QKV projection output: [s][3072] (q 0-2047, k 2048-2559, v 2560-3071)
__device__ __align__(16) float g_qkvf[SLEN * 3072];

// fp16 operands
__device__ __align__(16) __half s_xh[MX], s_xl[MX];          // x split
__device__ __align__(16) __half s_wqkvh[3072 * DMODEL];      // packed wq|wk|wv, single
__device__ __align__(16) __half s_woh[MX];                   // wo, single
__device__ __align__(16) __half s_qh[MX], s_ql[MX];          // q split (post norm+rope)
__device__ __align__(16) __half s_kh[MKV];                   // k single (post norm+rope)
__device__ __align__(16) __half s_vh[MKV];                   // v single
__device__ __align__(16) __half s_ath[MX], s_atl[MX];        // attention out split

// ---------------------------------------------------------------------------
// helpers
// ---------------------------------------------------------------------------
__device__ __forceinline__ u32 sptr(const void* p) {
    return (u32)__cvta_generic_to_shared(p);
}
__device__ __forceinline__ void ldm4(u32 a, u32& r0, u32& r1, u32& r2, u32& r3) {
    asm volatile("ldmatrix.sync.aligned.m8n8.x4.shared.b16 {%0,%1,%2,%3},[%4];"
                 : "=r"(r0), "=r"(r1), "=r"(r2), "=r"(r3) : "r"(a));
}
__device__ __forceinline__ void ldm4t(u32 a, u32& r0, u32& r1, u32& r2, u32& r3) {
    asm volatile("ldmatrix.sync.aligned.m8n8.x4.trans.shared.b16 {%0,%1,%2,%3},[%4];"
                 : "=r"(r0), "=r"(r1), "=r"(r2), "=r"(r3) : "r"(a));
}
__device__ __forceinline__ void mma_h(float* c, u32 a0, u32 a1, u32 a2, u32 a3,
                                      u32 b0, u32 b1) {
    asm volatile(
        "mma.sync.aligned.m16n8k16.row.col.f32.f16.f16.f32 "
        "{%0,%1,%2,%3},{%4,%5,%6,%7},{%8,%9},{%0,%1,%2,%3};"
        : "+f"(c[0]), "+f"(c[1]), "+f"(c[2]), "+f"(c[3])
        : "r"(a0), "r"(a1), "r"(a2), "r"(a3), "r"(b0), "r"(b1));
}
__device__ __forceinline__ u32 pack2h(__half a, __half b) {
    __half2 t = __halves2half2(a, b);
    return *reinterpret_cast<u32*>(&t);
}
__device__ __forceinline__ u32 cvt2h(float x, float y) {
    return pack2h(__float2half_rn(x), __float2half_rn(y));
}
__device__ __forceinline__ void split2h(float x, float y, u32& h, u32& l) {
    __half hx = __float2half_rn(x), hy = __float2half_rn(y);
    __half lx = __float2half_rn(x - __half2float(hx));
    __half ly = __float2half_rn(y - __half2float(hy));
    h = pack2h(hx, hy);
    l = pack2h(lx, ly);
}
__device__ __forceinline__ float ex2(float x) {
    float y; asm("ex2.approx.f32 %0, %1;" : "=f"(y) : "f"(x)); return y;
}
__device__ __forceinline__ void cpa16(u32 dst, const void* src) {
    asm volatile("cp.async.cg.shared.global [%0], [%1], 16;" :: "r"(dst), "l"(src));
}
__device__ __forceinline__ void cpcommit() {
    asm volatile("cp.async.commit_group;");
}
template <int N>
__device__ __forceinline__ void cpwait() {
    asm volatile("cp.async.wait_group %0;" :: "n"(N));
}

// ---------------------------------------------------------------------------
// merged prep: split x -> xh/xl ; convert wq|wk|wv -> wqkvh ; wo -> woh
// item space: [0,N4X) x | [N4X,2N4X) wq | +N4KV wk | +N4KV wv | +N4X wo
// ---------------------------------------------------------------------------
__global__ __launch_bounds__(256) void prep_all(
    const float* __restrict__ x, const float* __restrict__ wq,
    const float* __restrict__ wk, const float* __restrict__ wv,
    const float* __restrict__ wo,
    __half* __restrict__ xh, __half* __restrict__ xl,
    __half* __restrict__ wqkvh, __half* __restrict__ woh)
{
    int i = blockIdx.x * blockDim.x + threadIdx.x;
    if (i < N4X) {
        float4 v = ((const float4*)x)[i];
        u32 h0, h1, l0, l1;
        split2h(v.x, v.y, h0, l0); split2h(v.z, v.w, h1, l1);
        ((u32*)xh)[i * 2] = h0; ((u32*)xh)[i * 2 + 1] = h1;
        ((u32*)xl)[i * 2] = l0; ((u32*)xl)[i * 2 + 1] = l1;
        return;
    }
    i -= N4X;
    if (i < N4X) {   // wq -> wqkvh[0..MX)
        float4 v = ((const float4*)wq)[i];
        ((u32*)wqkvh)[i * 2]     = cvt2h(v.x, v.y);
        ((u32*)wqkvh)[i * 2 + 1] = cvt2h(v.z, v.w);
        return;
    }
    i -= N4X;
    if (i < N4KV) {  // wk -> wqkvh[MX..MX+WKV)
        float4 v = ((const float4*)wk)[i];
        u32* dst = (u32*)(wqkvh + MX);
        dst[i * 2]     = cvt2h(v.x, v.y);
        dst[i * 2 + 1] = cvt2h(v.z, v.w);
        return;
    }
    i -= N4KV;
    if (i < N4KV) {  // wv -> wqkvh[MX+WKV..MX+2*WKV)
        float4 v = ((const float4*)wv)[i];
        u32* dst = (u32*)(wqkvh + MX + WKV);
        dst[i * 2]     = cvt2h(v.x, v.y);
        dst[i * 2 + 1] = cvt2h(v.z, v.w);
        return;
    }
    i -= N4KV;
    {                // wo -> woh
        float4 v = ((const float4*)wo)[i];
        ((u32*)woh)[i * 2]     = cvt2h(v.x, v.y);
        ((u32*)woh)[i * 2 + 1] = cvt2h(v.z, v.w);
    }
}

// ---------------------------------------------------------------------------
// C[M,N] = A[M,K] @ B[N,K]^T ; A split fp16 hi/lo (2-term), B single fp16.
// 128x128x32 tiles, 256 thr (8 warps: 4m x 2n), 3-stage cp.async ring.
// dyn smem per stage 30720 B: Ah@0 Al@10240 B@20480; row stride 80 B. x3 = 92160.
// ---------------------------------------------------------------------------
__global__ __launch_bounds__(256, 2) void gemm2(
    const __half* __restrict__ Ah, const __half* __restrict__ Al,
    const __half* __restrict__ Bh, float* __restrict__ C, int M, int N, int K)
{
    extern __shared__ char smd[];
    const u32 smb = sptr(smd);
    const int tid = threadIdx.x, lane = tid & 31, w = tid >> 5;
    const int wm = w >> 1, wn = w & 1;
    const int bm = blockIdx.y * 128, bn = blockIdx.x * 128;

    float acc[2][8][4];
#pragma unroll
    for (int a = 0; a < 2; a++)
#pragma unroll
        for (int b = 0; b < 8; b++)
#pragma unroll
            for (int c = 0; c < 4; c++) acc[a][b][c] = 0.f;

    const u32 aoff = (wm * 32 + (lane & 15)) * 80 + (lane >> 4) * 16;
    const u32 boff = 20480 + (wn * 64 + (lane >> 4) * 8 + (lane & 7)) * 80
                     + ((lane >> 3) & 1) * 16;

    auto load_stage = [&](int stg, int k0) {
        u32 sb = smb + stg * 30720;
#pragma unroll
        for (int p = 0; p < 2; p++) {
            int c = tid + p * 256;
            int row = c >> 2, kc = (c & 3) * 8;
            u32 d = sb + row * 80 + kc * 2;
            size_t ga = (size_t)(bm + row) * K + k0 + kc;
            size_t gb = (size_t)(bn + row) * K + k0 + kc;
            cpa16(d,         Ah + ga);
            cpa16(d + 10240, Al + ga);
            cpa16(d + 20480, Bh + gb);
        }
        cpcommit();
    };

    const int NCH = K >> 5;
    load_stage(0, 0);
    load_stage(1, 32);

    int stg = 0;
    for (int ic = 0; ic < NCH; ic++) {
        if (ic + 2 < NCH) {
            int nxt = stg + 2; if (nxt >= 3) nxt -= 3;   // FIXED ring index
            load_stage(nxt, (ic + 2) * 32);
            cpwait<2>();
        } else if (ic + 1 < NCH) {
            cpwait<1>();
        } else {
            cpwait<0>();
        }
        __syncthreads();
        const u32 base = smb + stg * 30720;
        const u32 a_h = base + aoff, a_l = a_h + 10240;
        const u32 b_ = base + boff;
#pragma unroll
        for (int ks = 0; ks < 2; ks++) {
            u32 ah[2][4], al[2][4];
            ldm4(a_h + ks * 32,        ah[0][0], ah[0][1], ah[0][2], ah[0][3]);
            ldm4(a_h + ks * 32 + 1280, ah[1][0], ah[1][1], ah[1][2], ah[1][3]);
            ldm4(a_l + ks * 32,        al[0][0], al[0][1], al[0][2], al[0][3]);
            ldm4(a_l + ks * 32 + 1280, al[1][0], al[1][1], al[1][2], al[1][3]);
#pragma unroll
            for (int g = 0; g < 4; g++) {
                u32 bh[4];
                ldm4(b_ + g * 1280 + ks * 32, bh[0], bh[1], bh[2], bh[3]);
#pragma unroll
                for (int mt = 0; mt < 2; mt++)
#pragma unroll
                    for (int s = 0; s < 2; s++) {
                        float* c = acc[mt][g * 2 + s];
                        mma_h(c, ah[mt][0], ah[mt][1], ah[mt][2], ah[mt][3],
                              bh[2 * s], bh[2 * s + 1]);
                        mma_h(c, al[mt][0], al[mt][1], al[mt][2], al[mt][3],
                              bh[2 * s], bh[2 * s + 1]);
                    }
            }
        }
        __syncthreads();
        stg = (stg + 1 == 3) ? 0 : stg + 1;
    }

#pragma unroll
    for (int mt = 0; mt < 2; mt++)
#pragma unroll
        for (int nt = 0; nt < 8; nt++) {
            int row = bm + wm * 32 + mt * 16 + (lane >> 2);
            int col = bn + wn * 64 + nt * 8 + (lane & 3) * 2;
            *(float2*)&C[(size_t)row * N + col] =
                make_float2(acc[mt][nt][0], acc[mt][nt][1]);
            *(float2*)&C[(size_t)(row + 8) * N + col] =
                make_float2(acc[mt][nt][2], acc[mt][nt][3]);
        }
}

// ---------------------------------------------------------------------------
// RMSNorm + RoPE + convert from packed qkv fp32.
// 24 warps per seq pos: h<16 q (split fp16), 16-19 k (single), 20-23 v (single).
// ---------------------------------------------------------------------------
__global__ __launch_bounds__(256) void norm_rope_cvt(
    const float* __restrict__ qkvf, const float* __restrict__ freqs,
    __half* __restrict__ qh, __half* __restrict__ ql,
    __half* __restrict__ kh, __half* __restrict__ vh)
{
    int gwarp = (blockIdx.x * blockDim.x + threadIdx.x) >> 5;
    int lane  = threadIdx.x & 31;
    const int total = SLEN * 24;
    if (gwarp >= total) return;
    int s = gwarp / 24;
    int h = gwarp % 24;

    if (h >= 20) {   // v: plain convert
        const float* row = qkvf + (size_t)s * 3072 + 2560 + (h - 20) * 128;
        float4 x = *(const float4*)&row[lane * 4];
        size_t idx = ((((size_t)s * NKV + (h - 20)) * HD) >> 1) + lane * 2;
        ((u32*)vh)[idx]     = cvt2h(x.x, x.y);
        ((u32*)vh)[idx + 1] = cvt2h(x.z, x.w);
        return;
    }

    bool isq = (h < 16);
    const float* row = qkvf + (size_t)s * 3072 + (isq ? h * 128 : 2048 + (h - 16) * 128);
    float4 x = *(const float4*)&row[lane * 4];
    float ss = x.x * x.x + x.y * x.y + x.z * x.z + x.w * x.w;
#pragma unroll
    for (int off = 16; off; off >>= 1)
        ss += __shfl_xor_sync(0xffffffffu, ss, off);
    float r = rsqrtf(ss * (1.f / 128.f) + 1.1920929e-07f);

    float4 fc = *(const float4*)&freqs[(size_t)s * 128 + lane * 4];
    float x1 = x.x * r, x2 = x.y * r, x3 = x.z * r, x4 = x.w * r;
    float o0 = x1 * fc.x - x2 * fc.y;
    float o1 = x1 * fc.y + x2 * fc.x;
    float o2 = x3 * fc.z - x4 * fc.w;
    float o3 = x3 * fc.w + x4 * fc.z;

    if (isq) {
        size_t idx = ((((size_t)s * NH + h) * HD) >> 1) + lane * 2;
        u32 h0, l0, h1, l1;
        split2h(o0, o1, h0, l0); split2h(o2, o3, h1, l1);
        ((u32*)qh)[idx] = h0; ((u32*)qh)[idx + 1] = h1;
        ((u32*)ql)[idx] = l0; ((u32*)ql)[idx + 1] = l1;
    } else {
        size_t idx = ((((size_t)s * NKV + (h - 16)) * HD) >> 1) + lane * 2;
        ((u32*)kh)[idx]     = cvt2h(o0, o1);
        ((u32*)kh)[idx + 1] = cvt2h(o2, o3);
    }
}

// ---------------------------------------------------------------------------
// Flash attention (causal, sink), 2-term fp16 MMA, fully hidden K/V loads.
// BQ=BKV=64, 256 thr (8 warps: 4m x 2n). q split, k/v single, P split.
// smem: Qh 0, Ql 17408, K 34816, V 52224, Ph 69632, Pl 78848,
//       rmax 88064, rsum 88576 -> 89088 total. Tile row stride 272 B.
// Schedule: wait K(kt) -> QK -> sync -> issue V(kt)+K(kt+1) -> softmax
//           -> wait V -> PV.  Loads overlap softmax.
// ---------------------------------------------------------------------------
__global__ __launch_bounds__(256, 2) void attn_kernel(
    const __half* __restrict__ qh, const __half* __restrict__ ql,
    const __half* __restrict__ kh, const __half* __restrict__ vh,
    const float* __restrict__ sinks,
    __half* __restrict__ ath, __half* __restrict__ atl)
{
    extern __shared__ char smr[];
    const u32 smb = sptr(smr);
    float* rmax = (float*)(smr + 88064);   // [2][64]
    float* rsum = (float*)(smr + 88576);   // [2][64]

    const int tid = threadIdx.x, lane = tid & 31, w = tid >> 5;
    const int wm = w >> 1, wn = w & 1;
    const int h = blockIdx.y, kvh = h >> 2;
    const int qt = gridDim.x - 1 - blockIdx.x;   // heavy tiles first

    const float CS = 0.08838834764831845f * 1.4426950408889634f; // scale*log2e

    // async-load Q tile (hi+lo)  [group]
#pragma unroll
    for (int i = 0; i < 4; i++) {
        int c = tid + i * 256;
        int r = c >> 4, ck = c & 15;
        u32 d = smb + r * 272 + ck * 16;
        size_t g = ((size_t)(qt * 64 + r) * NH + h) * HD + ck * 8;
        cpa16(d,         qh + g);
        cpa16(d + 17408, ql + g);
    }
    cpcommit();

    auto load_k = [&](int kt) {
#pragma unroll
        for (int i = 0; i < 2; i++) {
            int c = tid + i * 256;
            int r = c >> 3, ck = c & 7;
            u32 d = smb + 34816 + r * 272 + ck * 32;
            size_t g = ((size_t)(kt * 64 + r) * NKV + kvh) * HD + ck * 16;
            cpa16(d,      kh + g);
            cpa16(d + 16, kh + g + 8);
        }
        cpcommit();
    };
    auto load_v = [&](int kt) {
#pragma unroll
        for (int i = 0; i < 2; i++) {
            int c = tid + i * 256;
            int r = c >> 3, ck = c & 7;
            u32 d = smb + 52224 + r * 272 + ck * 32;
            size_t g = ((size_t)(kt * 64 + r) * NKV + kvh) * HD + ck * 16;
            cpa16(d,      vh + g);
            cpa16(d + 16, vh + g + 8);
        }
        cpcommit();
    };

    load_k(0);   // [group]

    float oacc[8][4];
#pragma unroll
    for (int a = 0; a < 8; a++)
#pragma unroll
        for (int c = 0; c < 4; c++) oacc[a][c] = 0.f;
    float mrow[2] = {-1e30f, -1e30f}, lrow[2] = {0.f, 0.f};

    const u32 qa = smb + (wm * 16 + (lane & 15)) * 272 + (lane >> 4) * 16;
    const u32 kb = smb + 34816 + (wn * 32 + (lane >> 4) * 8 + (lane & 7)) * 272
                   + ((lane >> 3) & 1) * 16;
    const u32 vb = smb + 52224 + (((lane >> 3) & 1) * 8 + (lane & 7)) * 272
                   + (wn * 64 + (lane >> 4) * 8) * 2;
    const u32 pa = smb + 69632 + (wm * 16 + (lane & 15)) * 144 + (lane >> 4) * 16;
    const int rowl0 = wm * 16 + (lane >> 2);
    const int p_col = wn * 32 + (lane & 3) * 2;

    for (int kt = 0; kt <= qt; kt++) {
        cpwait<0>();       // K(kt) (+Q on first iter) arrived
        __syncthreads();   // (B) visible to all; prev PV done with V/P

        // S = q K^T (16x32 per warp), 2-term
        float sacc[4][4];
#pragma unroll
        for (int a = 0; a < 4; a++)
#pragma unroll
            for (int c = 0; c < 4; c++) sacc[a][c] = 0.f;

#pragma unroll
        for (int ks = 0; ks < 8; ks++) {
            u32 ah0, ah1, ah2, ah3, al0, al1, al2, al3;
            ldm4(qa + ks * 32,         ah0, ah1, ah2, ah3);
            ldm4(qa + 17408 + ks * 32, al0, al1, al2, al3);
#pragma unroll
            for (int g = 0; g < 2; g++) {
                u32 bh[4];
                ldm4(kb + g * 4352 + ks * 32, bh[0], bh[1], bh[2], bh[3]);
#pragma unroll
                for (int s = 0; s < 2; s++) {
                    float* c = sacc[g * 2 + s];
                    mma_h(c, ah0, ah1, ah2, ah3, bh[2 * s], bh[2 * s + 1]);
                    mma_h(c, al0, al1, al2, al3, bh[2 * s], bh[2 * s + 1]);
                }
            }
        }
        __syncthreads();   // (B2) all warps done reading K buffer

        // prefetch V(kt) and K(kt+1); they fly during softmax
        load_v(kt);
        if (kt < qt) load_k(kt + 1);

        // scale to log2 domain
#pragma unroll
        for (int a = 0; a < 4; a++)
#pragma unroll
            for (int c = 0; c < 4; c++) sacc[a][c] *= CS;

        // causal mask on diagonal tile
        if (kt == qt) {
            int r0 = qt * 64 + wm * 16 + (lane >> 2);
#pragma unroll
            for (int nt = 0; nt < 4; nt++) {
                int col0 = kt * 64 + wn * 32 + nt * 8 + (lane & 3) * 2;
#pragma unroll
                for (int ci = 0; ci < 4; ci++) {
                    int row = r0 + ((ci >= 2) ? 8 : 0);
                    int col = col0 + (ci & 1);
                    if (col > row) sacc[nt][ci] = -1e30f;
                }
            }
        }

        // cross-warp row max
#pragma unroll
        for (int i = 0; i < 2; i++) {
            float rm = -1e30f;
#pragma unroll
            for (int nt = 0; nt < 4; nt++)
                rm = fmaxf(rm, fmaxf(sacc[nt][2 * i], sacc[nt][2 * i + 1]));
            rm = fmaxf(rm, __shfl_xor_sync(0xffffffffu, rm, 1));
            rm = fmaxf(rm, __shfl_xor_sync(0xffffffffu, rm, 2));
            if ((lane & 3) == 0) rmax[wn * 64 + rowl0 + i * 8] = rm;
        }
        __syncthreads();   // (C)

        float alpha[2];
#pragma unroll
        for (int i = 0; i < 2; i++) {
            float cand = fmaxf(rmax[rowl0 + i * 8], rmax[64 + rowl0 + i * 8]);
            float mn = fmaxf(mrow[i], cand);
            alpha[i] = ex2(mrow[i] - mn);
            mrow[i] = mn;
            float rs = 0.f;
            int off = (rowl0 + i * 8) * 144 + p_col * 2;
#pragma unroll
            for (int nt = 0; nt < 4; nt++) {
                float p0 = ex2(sacc[nt][2 * i] - mn);
                float p1 = ex2(sacc[nt][2 * i + 1] - mn);
                rs += p0 + p1;
                u32 hh, ll;
                split2h(p0, p1, hh, ll);
                *(u32*)(smr + 69632 + off + nt * 16) = hh;
                *(u32*)(smr + 78848 + off + nt * 16) = ll;
            }
            rs += __shfl_xor_sync(0xffffffffu, rs, 1);
            rs += __shfl_xor_sync(0xffffffffu, rs, 2);
            if ((lane & 3) == 0) rsum[wn * 64 + rowl0 + i * 8] = rs;
#pragma unroll
            for (int nt = 0; nt < 8; nt++) {
                oacc[nt][2 * i]     *= alpha[i];
                oacc[nt][2 * i + 1] *= alpha[i];
            }
        }

        // V must be in; K(kt+1) may still be in flight
        if (kt < qt) cpwait<1>(); else cpwait<0>();
        __syncthreads();   // (D) P + rsum + V visible

#pragma unroll
        for (int i = 0; i < 2; i++) {
            float rs = rsum[rowl0 + i * 8] + rsum[64 + rowl0 + i * 8];
            lrow[i] = lrow[i] * alpha[i] + rs;
        }

        // O += P V, 2-term (P split, V single)
#pragma unroll
        for (int ks = 0; ks < 4; ks++) {
            u32 ph0, ph1, ph2, ph3, pl0, pl1, pl2, pl3;
            ldm4(pa + ks * 32,        ph0, ph1, ph2, ph3);
            ldm4(pa + 9216 + ks * 32, pl0, pl1, pl2, pl3);
#pragma unroll
            for (int g = 0; g < 4; g++) {
                u32 bh[4];
                ldm4t(vb + ks * 4352 + g * 32, bh[0], bh[1], bh[2], bh[3]);
#pragma unroll
                for (int s = 0; s < 2; s++) {
                    float* c = oacc[g * 2 + s];
                    mma_h(c, ph0, ph1, ph2, ph3, bh[2 * s], bh[2 * s + 1]);
                    mma_h(c, pl0, pl1, pl2, pl3, bh[2 * s], bh[2 * s + 1]);
                }
            }
        }
    }

    // epilogue: lse, sink sigmoid, normalize, split-store
    float sk = sinks[h];
#pragma unroll
    for (int i = 0; i < 2; i++) {
        float lse = mrow[i] * 0.6931471805599453f + logf(lrow[i]);
        float sg = 1.f / (1.f + expf(sk - lse));
        float sc = sg / lrow[i];
        int row = qt * 64 + wm * 16 + (lane >> 2) + i * 8;
        size_t rb = (size_t)row * DMODEL + h * HD;
#pragma unroll
        for (int nt = 0; nt < 8; nt++) {
            int col = wn * 64 + nt * 8 + (lane & 3) * 2;
            u32 hh, ll;
            split2h(oacc[nt][2 * i] * sc, oacc[nt][2 * i + 1] * sc, hh, ll);
            ((u32*)ath)[(rb + col) >> 1] = hh;
            ((u32*)atl)[(rb + col) >> 1] = ll;
        }
    }
}

// ---------------------------------------------------------------------------
extern "C" void kernel_launch(void* const* d_in, const int* in_sizes, int n_in,
                              void* d_out, int out_size)
{
    const float* x     = (const float*)d_in[0];
    const float* freqs = (const float*)d_in[1];
    const float* wq    = (const float*)d_in[2];
    const float* wk    = (const float*)d_in[3];
    const float* wv    = (const float*)d_in[4];
    const float* wo    = (const float*)d_in[5];
    const float* sinks = (const float*)d_in[6];
    float* out = (float*)d_out;

    float* qkvf;
    __half *xh, *xl, *wqkvh, *woh, *qh, *ql, *kh, *vh, *ath, *atl;
    cudaGetSymbolAddress((void**)&qkvf,  g_qkvf);
    cudaGetSymbolAddress((void**)&xh,    s_xh);
    cudaGetSymbolAddress((void**)&xl,    s_xl);
    cudaGetSymbolAddress((void**)&wqkvh, s_wqkvh);
    cudaGetSymbolAddress((void**)&woh,   s_woh);
    cudaGetSymbolAddress((void**)&qh,    s_qh);
    cudaGetSymbolAddress((void**)&ql,    s_ql);
    cudaGetSymbolAddress((void**)&kh,    s_kh);
    cudaGetSymbolAddress((void**)&vh,    s_vh);
    cudaGetSymbolAddress((void**)&ath,   s_ath);
    cudaGetSymbolAddress((void**)&atl,   s_atl);

    cudaFuncSetAttribute(gemm2, cudaFuncAttributeMaxDynamicSharedMemorySize, 92160);
    cudaFuncSetAttribute(attn_kernel, cudaFuncAttributeMaxDynamicSharedMemorySize, 89088);

    // merged operand prep (split x, convert weights)
    const int PREP_ITEMS = N4X * 3 + N4KV * 2;
    prep_all<<<PREP_ITEMS / 256, 256>>>(x, wq, wk, wv, wo, xh, xl, wqkvh, woh);

    // fused QKV projection: [2048, 3072] = x @ [wq|wk|wv]^T
    gemm2<<<dim3(24, 16), 256, 92160>>>(xh, xl, wqkvh, qkvf, SLEN, 3072, DMODEL);

    // RMSNorm + RoPE + convert (q split, k/v single)
    norm_rope_cvt<<<(SLEN * 24 * 32) / 256, 256>>>(qkvf, freqs, qh, ql, kh, vh);

    // causal flash attention with sink scaling
    attn_kernel<<<dim3(SLEN / 64, NH), 256, 89088>>>(qh, ql, kh, vh, sinks, ath, atl);

    // output projection
    gemm2<<<dim3(16, 16), 256, 92160>>>(ath, atl, woh, out, SLEN, DMODEL, DMODEL);
}

// round 9
// speedup vs baseline: 7.7570x; 1.0539x over previous
#include <cuda_runtime.h>
#include <cuda_fp16.h>
#include <math.h>

typedef unsigned int u32;

#define SLEN 2048
#define DMODEL 2048
#define NH 16
#define NKV 4
#define HD 128
#define MX (SLEN * DMODEL)          // 4194304
#define MKV (SLEN * NKV * HD)       // 1048576
#define WKV (NKV * HD * DMODEL)     // 1048576
#define N4X (MX / 4)                // 1048576 float4 items
#define N4KV (WKV / 4)              // 262144

// fp32 packed QKV projection output: [s][3072] (q 0-2047, k 2048-2559, v 2560-3071)
__device__ __align__(16) float g_qkvf[SLEN * 3072];

// fp16 operands
__device__ __align__(16) __half s_xh[MX], s_xl[MX];          // x split
__device__ __align__(16) __half s_wqkvh[3072 * DMODEL];      // packed wq|wk|wv, single
__device__ __align__(16) __half s_woh[MX];                   // wo, single
__device__ __align__(16) __half s_qh[MX], s_ql[MX];          // q split (post norm+rope)
__device__ __align__(16) __half s_kh[MKV];                   // k single (post norm+rope)
__device__ __align__(16) __half s_vh[MKV];                   // v single
__device__ __align__(16) __half s_ath[MX], s_atl[MX];        // attention out split

// ---------------------------------------------------------------------------
// helpers
// ---------------------------------------------------------------------------
__device__ __forceinline__ u32 sptr(const void* p) {
    return (u32)__cvta_generic_to_shared(p);
}
__device__ __forceinline__ void ldm4(u32 a, u32& r0, u32& r1, u32& r2, u32& r3) {
    asm volatile("ldmatrix.sync.aligned.m8n8.x4.shared.b16 {%0,%1,%2,%3},[%4];"
                 : "=r"(r0), "=r"(r1), "=r"(r2), "=r"(r3) : "r"(a));
}
__device__ __forceinline__ void ldm4t(u32 a, u32& r0, u32& r1, u32& r2, u32& r3) {
    asm volatile("ldmatrix.sync.aligned.m8n8.x4.trans.shared.b16 {%0,%1,%2,%3},[%4];"
                 : "=r"(r0), "=r"(r1), "=r"(r2), "=r"(r3) : "r"(a));
}
__device__ __forceinline__ void mma_h(float* c, u32 a0, u32 a1, u32 a2, u32 a3,
                                      u32 b0, u32 b1) {
    asm volatile(
        "mma.sync.aligned.m16n8k16.row.col.f32.f16.f16.f32 "
        "{%0,%1,%2,%3},{%4,%5,%6,%7},{%8,%9},{%0,%1,%2,%3};"
        : "+f"(c[0]), "+f"(c[1]), "+f"(c[2]), "+f"(c[3])
        : "r"(a0), "r"(a1), "r"(a2), "r"(a3), "r"(b0), "r"(b1));
}
__device__ __forceinline__ u32 pack2h(__half a, __half b) {
    __half2 t = __halves2half2(a, b);
    return *reinterpret_cast<u32*>(&t);
}
__device__ __forceinline__ u32 cvt2h(float x, float y) {
    return pack2h(__float2half_rn(x), __float2half_rn(y));
}
__device__ __forceinline__ void split2h(float x, float y, u32& h, u32& l) {
    __half hx = __float2half_rn(x), hy = __float2half_rn(y);
    __half lx = __float2half_rn(x - __half2float(hx));
    __half ly = __float2half_rn(y - __half2float(hy));
    h = pack2h(hx, hy);
    l = pack2h(lx, ly);
}
__device__ __forceinline__ float ex2(float x) {
    float y; asm("ex2.approx.f32 %0, %1;" : "=f"(y) : "f"(x)); return y;
}
__device__ __forceinline__ void cpa16(u32 dst, const void* src) {
    asm volatile("cp.async.cg.shared.global [%0], [%1], 16;" :: "r"(dst), "l"(src));
}
__device__ __forceinline__ void cpcommit() {
    asm volatile("cp.async.commit_group;");
}
template <int N>
__device__ __forceinline__ void cpwait() {
    asm volatile("cp.async.wait_group %0;" :: "n"(N));
}

// ---------------------------------------------------------------------------
// merged prep: split x -> xh/xl ; convert wq|wk|wv -> wqkvh ; wo -> woh
// ---------------------------------------------------------------------------
__global__ __launch_bounds__(256) void prep_all(
    const float* __restrict__ x, const float* __restrict__ wq,
    const float* __restrict__ wk, const float* __restrict__ wv,
    const float* __restrict__ wo,
    __half* __restrict__ xh, __half* __restrict__ xl,
    __half* __restrict__ wqkvh, __half* __restrict__ woh)
{
    int i = blockIdx.x * blockDim.x + threadIdx.x;
    if (i < N4X) {
        float4 v = ((const float4*)x)[i];
        u32 h0, h1, l0, l1;
        split2h(v.x, v.y, h0, l0); split2h(v.z, v.w, h1, l1);
        ((u32*)xh)[i * 2] = h0; ((u32*)xh)[i * 2 + 1] = h1;
        ((u32*)xl)[i * 2] = l0; ((u32*)xl)[i * 2 + 1] = l1;
        return;
    }
    i -= N4X;
    if (i < N4X) {
        float4 v = ((const float4*)wq)[i];
        ((u32*)wqkvh)[i * 2]     = cvt2h(v.x, v.y);
        ((u32*)wqkvh)[i * 2 + 1] = cvt2h(v.z, v.w);
        return;
    }
    i -= N4X;
    if (i < N4KV) {
        float4 v = ((const float4*)wk)[i];
        u32* dst = (u32*)(wqkvh + MX);
        dst[i * 2]     = cvt2h(v.x, v.y);
        dst[i * 2 + 1] = cvt2h(v.z, v.w);
        return;
    }
    i -= N4KV;
    if (i < N4KV) {
        float4 v = ((const float4*)wv)[i];
        u32* dst = (u32*)(wqkvh + MX + WKV);
        dst[i * 2]     = cvt2h(v.x, v.y);
        dst[i * 2 + 1] = cvt2h(v.z, v.w);
        return;
    }
    i -= N4KV;
    {
        float4 v = ((const float4*)wo)[i];
        ((u32*)woh)[i * 2]     = cvt2h(v.x, v.y);
        ((u32*)woh)[i * 2 + 1] = cvt2h(v.z, v.w);
    }
}

// ---------------------------------------------------------------------------
// C[M,N] = A[M,K] @ B[N,K]^T ; A split fp16 hi/lo (2-term), B single fp16.
// 128x128x32 tiles, 256 thr (8 warps: 4m x 2n), 3-stage cp.async ring.
// ---------------------------------------------------------------------------
__global__ __launch_bounds__(256, 2) void gemm2(
    const __half* __restrict__ Ah, const __half* __restrict__ Al,
    const __half* __restrict__ Bh, float* __restrict__ C, int M, int N, int K)
{
    extern __shared__ char smd[];
    const u32 smb = sptr(smd);
    const int tid = threadIdx.x, lane = tid & 31, w = tid >> 5;
    const int wm = w >> 1, wn = w & 1;
    const int bm = blockIdx.y * 128, bn = blockIdx.x * 128;

    float acc[2][8][4];
#pragma unroll
    for (int a = 0; a < 2; a++)
#pragma unroll
        for (int b = 0; b < 8; b++)
#pragma unroll
            for (int c = 0; c < 4; c++) acc[a][b][c] = 0.f;

    const u32 aoff = (wm * 32 + (lane & 15)) * 80 + (lane >> 4) * 16;
    const u32 boff = 20480 + (wn * 64 + (lane >> 4) * 8 + (lane & 7)) * 80
                     + ((lane >> 3) & 1) * 16;

    auto load_stage = [&](int stg, int k0) {
        u32 sb = smb + stg * 30720;
#pragma unroll
        for (int p = 0; p < 2; p++) {
            int c = tid + p * 256;
            int row = c >> 2, kc = (c & 3) * 8;
            u32 d = sb + row * 80 + kc * 2;
            size_t ga = (size_t)(bm + row) * K + k0 + kc;
            size_t gb = (size_t)(bn + row) * K + k0 + kc;
            cpa16(d,         Ah + ga);
            cpa16(d + 10240, Al + ga);
            cpa16(d + 20480, Bh + gb);
        }
        cpcommit();
    };

    const int NCH = K >> 5;
    load_stage(0, 0);
    load_stage(1, 32);

    int stg = 0;
    for (int ic = 0; ic < NCH; ic++) {
        if (ic + 2 < NCH) {
            int nxt = stg + 2; if (nxt >= 3) nxt -= 3;
            load_stage(nxt, (ic + 2) * 32);
            cpwait<2>();
        } else if (ic + 1 < NCH) {
            cpwait<1>();
        } else {
            cpwait<0>();
        }
        __syncthreads();
        const u32 base = smb + stg * 30720;
        const u32 a_h = base + aoff, a_l = a_h + 10240;
        const u32 b_ = base + boff;
#pragma unroll
        for (int ks = 0; ks < 2; ks++) {
            u32 ah[2][4], al[2][4];
            ldm4(a_h + ks * 32,        ah[0][0], ah[0][1], ah[0][2], ah[0][3]);
            ldm4(a_h + ks * 32 + 1280, ah[1][0], ah[1][1], ah[1][2], ah[1][3]);
            ldm4(a_l + ks * 32,        al[0][0], al[0][1], al[0][2], al[0][3]);
            ldm4(a_l + ks * 32 + 1280, al[1][0], al[1][1], al[1][2], al[1][3]);
#pragma unroll
            for (int g = 0; g < 4; g++) {
                u32 bh[4];
                ldm4(b_ + g * 1280 + ks * 32, bh[0], bh[1], bh[2], bh[3]);
#pragma unroll
                for (int mt = 0; mt < 2; mt++)
#pragma unroll
                    for (int s = 0; s < 2; s++) {
                        float* c = acc[mt][g * 2 + s];
                        mma_h(c, ah[mt][0], ah[mt][1], ah[mt][2], ah[mt][3],
                              bh[2 * s], bh[2 * s + 1]);
                        mma_h(c, al[mt][0], al[mt][1], al[mt][2], al[mt][3],
                              bh[2 * s], bh[2 * s + 1]);
                    }
            }
        }
        __syncthreads();
        stg = (stg + 1 == 3) ? 0 : stg + 1;
    }

#pragma unroll
    for (int mt = 0; mt < 2; mt++)
#pragma unroll
        for (int nt = 0; nt < 8; nt++) {
            int row = bm + wm * 32 + mt * 16 + (lane >> 2);
            int col = bn + wn * 64 + nt * 8 + (lane & 3) * 2;
            *(float2*)&C[(size_t)row * N + col] =
                make_float2(acc[mt][nt][0], acc[mt][nt][1]);
            *(float2*)&C[(size_t)(row + 8) * N + col] =
                make_float2(acc[mt][nt][2], acc[mt][nt][3]);
        }
}

// ---------------------------------------------------------------------------
// RMSNorm + RoPE + convert from packed qkv fp32.
// ---------------------------------------------------------------------------
__global__ __launch_bounds__(256) void norm_rope_cvt(
    const float* __restrict__ qkvf, const float* __restrict__ freqs,
    __half* __restrict__ qh, __half* __restrict__ ql,
    __half* __restrict__ kh, __half* __restrict__ vh)
{
    int gwarp = (blockIdx.x * blockDim.x + threadIdx.x) >> 5;
    int lane  = threadIdx.x & 31;
    const int total = SLEN * 24;
    if (gwarp >= total) return;
    int s = gwarp / 24;
    int h = gwarp % 24;

    if (h >= 20) {
        const float* row = qkvf + (size_t)s * 3072 + 2560 + (h - 20) * 128;
        float4 x = *(const float4*)&row[lane * 4];
        size_t idx = ((((size_t)s * NKV + (h - 20)) * HD) >> 1) + lane * 2;
        ((u32*)vh)[idx]     = cvt2h(x.x, x.y);
        ((u32*)vh)[idx + 1] = cvt2h(x.z, x.w);
        return;
    }

    bool isq = (h < 16);
    const float* row = qkvf + (size_t)s * 3072 + (isq ? h * 128 : 2048 + (h - 16) * 128);
    float4 x = *(const float4*)&row[lane * 4];
    float ss = x.x * x.x + x.y * x.y + x.z * x.z + x.w * x.w;
#pragma unroll
    for (int off = 16; off; off >>= 1)
        ss += __shfl_xor_sync(0xffffffffu, ss, off);
    float r = rsqrtf(ss * (1.f / 128.f) + 1.1920929e-07f);

    float4 fc = *(const float4*)&freqs[(size_t)s * 128 + lane * 4];
    float x1 = x.x * r, x2 = x.y * r, x3 = x.z * r, x4 = x.w * r;
    float o0 = x1 * fc.x - x2 * fc.y;
    float o1 = x1 * fc.y + x2 * fc.x;
    float o2 = x3 * fc.z - x4 * fc.w;
    float o3 = x3 * fc.w + x4 * fc.z;

    if (isq) {
        size_t idx = ((((size_t)s * NH + h) * HD) >> 1) + lane * 2;
        u32 h0, l0, h1, l1;
        split2h(o0, o1, h0, l0); split2h(o2, o3, h1, l1);
        ((u32*)qh)[idx] = h0; ((u32*)qh)[idx + 1] = h1;
        ((u32*)ql)[idx] = l0; ((u32*)ql)[idx + 1] = l1;
    } else {
        size_t idx = ((((size_t)s * NKV + (h - 16)) * HD) >> 1) + lane * 2;
        ((u32*)kh)[idx]     = cvt2h(o0, o1);
        ((u32*)kh)[idx + 1] = cvt2h(o2, o3);
    }
}

// ---------------------------------------------------------------------------
// Flash attention (causal, sink), FA2 warp layout: 4 warps (128 thr), each
// warp owns 16 q-rows x FULL 64-wide KV tile. P stays in registers (split
// fp16 hi/lo from the QK accumulator fragment). No cross-warp softmax, no
// P smem. q split, k/v single fp16.
// smem: Qh 0, Ql 17408, K 34816, V 52224 -> 69632 B (3 CTA/SM).
// Schedule: wait K(kt) -> sync -> issue V(kt) -> QK -> sync -> issue K(kt+1)
//           -> softmax (loads fly) -> wait V -> sync -> PV.
// ---------------------------------------------------------------------------
__global__ __launch_bounds__(128, 3) void attn_kernel(
    const __half* __restrict__ qh, const __half* __restrict__ ql,
    const __half* __restrict__ kh, const __half* __restrict__ vh,
    const float* __restrict__ sinks,
    __half* __restrict__ ath, __half* __restrict__ atl)
{
    extern __shared__ char smr[];
    const u32 smb = sptr(smr);

    const int tid = threadIdx.x, lane = tid & 31, w = tid >> 5;
    const int h = blockIdx.y, kvh = h >> 2;
    const int qt = gridDim.x - 1 - blockIdx.x;   // heavy tiles first

    const float CS = 0.08838834764831845f * 1.4426950408889634f; // scale*log2e

    // async-load Q tile (hi+lo): 64 rows x 256B x2
#pragma unroll
    for (int i = 0; i < 8; i++) {
        int c = tid + i * 128;
        int r = c >> 4, ck = c & 15;
        u32 d = smb + r * 272 + ck * 16;
        size_t g = ((size_t)(qt * 64 + r) * NH + h) * HD + ck * 8;
        cpa16(d,         qh + g);
        cpa16(d + 17408, ql + g);
    }
    auto load_k = [&](int kt) {
#pragma unroll
        for (int i = 0; i < 4; i++) {
            int c = tid + i * 128;
            int r = c >> 3, ck = c & 7;
            u32 d = smb + 34816 + r * 272 + ck * 32;
            size_t g = ((size_t)(kt * 64 + r) * NKV + kvh) * HD + ck * 16;
            cpa16(d,      kh + g);
            cpa16(d + 16, kh + g + 8);
        }
        cpcommit();
    };
    auto load_v = [&](int kt) {
#pragma unroll
        for (int i = 0; i < 4; i++) {
            int c = tid + i * 128;
            int r = c >> 3, ck = c & 7;
            u32 d = smb + 52224 + r * 272 + ck * 32;
            size_t g = ((size_t)(kt * 64 + r) * NKV + kvh) * HD + ck * 16;
            cpa16(d,      vh + g);
            cpa16(d + 16, vh + g + 8);
        }
        cpcommit();
    };
    load_k(0);   // Q + K(0) in one group

    float oacc[16][4];
#pragma unroll
    for (int a = 0; a < 16; a++)
#pragma unroll
        for (int c = 0; c < 4; c++) oacc[a][c] = 0.f;
    float mrow[2] = {-1e30f, -1e30f}, lrow[2] = {0.f, 0.f};

    // ldmatrix bases: warp owns q-rows w*16..w*16+15
    const u32 qa = smb + (w * 16 + (lane & 15)) * 272 + (lane >> 4) * 16;
    const u32 kb = smb + 34816 + ((lane >> 4) * 8 + (lane & 7)) * 272
                   + ((lane >> 3) & 1) * 16;
    const u32 vb = smb + 52224 + (((lane >> 3) & 1) * 8 + (lane & 7)) * 272
                   + ((lane >> 4) * 8) * 2;

    for (int kt = 0; kt <= qt; kt++) {
        cpwait<0>();       // K(kt) (+Q first iter) arrived
        __syncthreads();   // (B) K visible; prev PV done with V buffer
        load_v(kt);        // V(kt) flies during QK

        // S = q K^T : m16 n64 k128 per warp, 2-term
        float sacc[8][4];
#pragma unroll
        for (int a = 0; a < 8; a++)
#pragma unroll
            for (int c = 0; c < 4; c++) sacc[a][c] = 0.f;

#pragma unroll
        for (int ks = 0; ks < 8; ks++) {
            u32 ah0, ah1, ah2, ah3, al0, al1, al2, al3;
            ldm4(qa + ks * 32,         ah0, ah1, ah2, ah3);
            ldm4(qa + 17408 + ks * 32, al0, al1, al2, al3);
#pragma unroll
            for (int g = 0; g < 4; g++) {
                u32 bh[4];
                ldm4(kb + g * 4352 + ks * 32, bh[0], bh[1], bh[2], bh[3]);
#pragma unroll
                for (int s = 0; s < 2; s++) {
                    float* c = sacc[g * 2 + s];
                    mma_h(c, ah0, ah1, ah2, ah3, bh[2 * s], bh[2 * s + 1]);
                    mma_h(c, al0, al1, al2, al3, bh[2 * s], bh[2 * s + 1]);
                }
            }
        }
        __syncthreads();   // (B2) all warps done reading K buffer
        if (kt < qt) load_k(kt + 1);   // K(kt+1) flies during softmax

        // scale to log2 domain
#pragma unroll
        for (int a = 0; a < 8; a++)
#pragma unroll
            for (int c = 0; c < 4; c++) sacc[a][c] *= CS;

        // causal mask on diagonal tile
        if (kt == qt) {
            int r0 = qt * 64 + w * 16 + (lane >> 2);
#pragma unroll
            for (int nt = 0; nt < 8; nt++) {
                int col0 = kt * 64 + nt * 8 + (lane & 3) * 2;
#pragma unroll
                for (int ci = 0; ci < 4; ci++) {
                    int row = r0 + ((ci >= 2) ? 8 : 0);
                    int col = col0 + (ci & 1);
                    if (col > row) sacc[nt][ci] = -1e30f;
                }
            }
        }

        // softmax: rows fully quad-local, exp in place into sacc
        float alpha[2];
#pragma unroll
        for (int i = 0; i < 2; i++) {
            float rm = -1e30f;
#pragma unroll
            for (int nt = 0; nt < 8; nt++)
                rm = fmaxf(rm, fmaxf(sacc[nt][2 * i], sacc[nt][2 * i + 1]));
            rm = fmaxf(rm, __shfl_xor_sync(0xffffffffu, rm, 1));
            rm = fmaxf(rm, __shfl_xor_sync(0xffffffffu, rm, 2));
            float mn = fmaxf(mrow[i], rm);
            alpha[i] = ex2(mrow[i] - mn);
            mrow[i] = mn;
            float rs = 0.f;
#pragma unroll
            for (int nt = 0; nt < 8; nt++) {
                float p0 = ex2(sacc[nt][2 * i] - mn);
                float p1 = ex2(sacc[nt][2 * i + 1] - mn);
                sacc[nt][2 * i] = p0; sacc[nt][2 * i + 1] = p1;
                rs += p0 + p1;
            }
            rs += __shfl_xor_sync(0xffffffffu, rs, 1);
            rs += __shfl_xor_sync(0xffffffffu, rs, 2);
            lrow[i] = lrow[i] * alpha[i] + rs;
#pragma unroll
            for (int nt = 0; nt < 16; nt++) {
                oacc[nt][2 * i]     *= alpha[i];
                oacc[nt][2 * i + 1] *= alpha[i];
            }
        }

        cpwait<(1)>();     // V(kt) in (K(kt+1) may still fly); last iter: K group absent
        if (kt == qt) cpwait<0>();
        __syncthreads();   // (D) V visible to all warps

        // O += P V : m16 n128 k64, P from registers (split hi/lo)
#pragma unroll
        for (int j = 0; j < 4; j++) {
            u32 ph0, ph1, ph2, ph3, pl0, pl1, pl2, pl3;
            split2h(sacc[2 * j][0],     sacc[2 * j][1],     ph0, pl0);
            split2h(sacc[2 * j][2],     sacc[2 * j][3],     ph1, pl1);
            split2h(sacc[2 * j + 1][0], sacc[2 * j + 1][1], ph2, pl2);
            split2h(sacc[2 * j + 1][2], sacc[2 * j + 1][3], ph3, pl3);
#pragma unroll
            for (int g = 0; g < 8; g++) {
                u32 bh[4];
                ldm4t(vb + j * 4352 + g * 32, bh[0], bh[1], bh[2], bh[3]);
#pragma unroll
                for (int s = 0; s < 2; s++) {
                    float* c = oacc[g * 2 + s];
                    mma_h(c, ph0, ph1, ph2, ph3, bh[2 * s], bh[2 * s + 1]);
                    mma_h(c, pl0, pl1, pl2, pl3, bh[2 * s], bh[2 * s + 1]);
                }
            }
        }
    }

    // epilogue: lse, sink sigmoid, normalize, split-store
    float sk = sinks[h];
#pragma unroll
    for (int i = 0; i < 2; i++) {
        float lse = mrow[i] * 0.6931471805599453f + logf(lrow[i]);
        float sg = 1.f / (1.f + expf(sk - lse));
        float sc = sg / lrow[i];
        int row = qt * 64 + w * 16 + (lane >> 2) + i * 8;
        size_t rb = (size_t)row * DMODEL + h * HD;
#pragma unroll
        for (int nt = 0; nt < 16; nt++) {
            int col = nt * 8 + (lane & 3) * 2;
            u32 hh, ll;
            split2h(oacc[nt][2 * i] * sc, oacc[nt][2 * i + 1] * sc, hh, ll);
            ((u32*)ath)[(rb + col) >> 1] = hh;
            ((u32*)atl)[(rb + col) >> 1] = ll;
        }
    }
}

// ---------------------------------------------------------------------------
extern "C" void kernel_launch(void* const* d_in, const int* in_sizes, int n_in,
                              void* d_out, int out_size)
{
    const float* x     = (const float*)d_in[0];
    const float* freqs = (const float*)d_in[1];
    const float* wq    = (const float*)d_in[2];
    const float* wk    = (const float*)d_in[3];
    const float* wv    = (const float*)d_in[4];
    const float* wo    = (const float*)d_in[5];
    const float* sinks = (const float*)d_in[6];
    float* out = (float*)d_out;

    float* qkvf;
    __half *xh, *xl, *wqkvh, *woh, *qh, *ql, *kh, *vh, *ath, *atl;
    cudaGetSymbolAddress((void**)&qkvf,  g_qkvf);
    cudaGetSymbolAddress((void**)&xh,    s_xh);
    cudaGetSymbolAddress((void**)&xl,    s_xl);
    cudaGetSymbolAddress((void**)&wqkvh, s_wqkvh);
    cudaGetSymbolAddress((void**)&woh,   s_woh);
    cudaGetSymbolAddress((void**)&qh,    s_qh);
    cudaGetSymbolAddress((void**)&ql,    s_ql);
    cudaGetSymbolAddress((void**)&kh,    s_kh);
    cudaGetSymbolAddress((void**)&vh,    s_vh);
    cudaGetSymbolAddress((void**)&ath,   s_ath);
    cudaGetSymbolAddress((void**)&atl,   s_atl);

    cudaFuncSetAttribute(gemm2, cudaFuncAttributeMaxDynamicSharedMemorySize, 92160);
    cudaFuncSetAttribute(attn_kernel, cudaFuncAttributeMaxDynamicSharedMemorySize, 69632);

    // merged operand prep
    const int PREP_ITEMS = N4X * 3 + N4KV * 2;
    prep_all<<<PREP_ITEMS / 256, 256>>>(x, wq, wk, wv, wo, xh, xl, wqkvh, woh);

    // fused QKV projection: [2048, 3072] = x @ [wq|wk|wv]^T
    gemm2<<<dim3(24, 16), 256, 92160>>>(xh, xl, wqkvh, qkvf, SLEN, 3072, DMODEL);

    // RMSNorm + RoPE + convert (q split, k/v single)
    norm_rope_cvt<<<(SLEN * 24 * 32) / 256, 256>>>(qkvf, freqs, qh, ql, kh, vh);

    // causal flash attention with sink scaling (FA2 layout)
    attn_kernel<<<dim3(SLEN / 64, NH), 128, 69632>>>(qh, ql, kh, vh, sinks, ath, atl);

    // output projection
    gemm2<<<dim3(16, 16), 256, 92160>>>(ath, atl, woh, out, SLEN, DMODEL, DMODEL);
}

// round 10
// speedup vs baseline: 8.0827x; 1.0420x over previous
#include <cuda_runtime.h>
#include <cuda_fp16.h>
#include <math.h>

typedef unsigned int u32;

#define SLEN 2048
#define DMODEL 2048
#define NH 16
#define NKV 4
#define HD 128
#define MX (SLEN * DMODEL)          // 4194304
#define MKV (SLEN * NKV * HD)       // 1048576
#define WKV (NKV * HD * DMODEL)     // 1048576
#define N4X (MX / 4)                // 1048576 float4 items
#define N4KV (WKV / 4)              // 262144

// fp32 packed QKV projection output: [s][3072] (q 0-2047, k 2048-2559, v 2560-3071)
__device__ __align__(16) float g_qkvf[SLEN * 3072];

// fp16 operands
__device__ __align__(16) __half s_xh[MX], s_xl[MX];          // x split
__device__ __align__(16) __half s_wqkvh[3072 * DMODEL];      // packed wq|wk|wv, single
__device__ __align__(16) __half s_woh[MX];                   // wo, single
__device__ __align__(16) __half s_qh[MX], s_ql[MX];          // q split (post norm+rope, pre-scaled)
__device__ __align__(16) __half s_kh[MKV];                   // k single (post norm+rope)
__device__ __align__(16) __half s_vh[MKV];                   // v single
__device__ __align__(16) __half s_ath[MX], s_atl[MX];        // attention out split

// ---------------------------------------------------------------------------
// helpers
// ---------------------------------------------------------------------------
__device__ __forceinline__ u32 sptr(const void* p) {
    return (u32)__cvta_generic_to_shared(p);
}
__device__ __forceinline__ void ldm4(u32 a, u32& r0, u32& r1, u32& r2, u32& r3) {
    asm volatile("ldmatrix.sync.aligned.m8n8.x4.shared.b16 {%0,%1,%2,%3},[%4];"
                 : "=r"(r0), "=r"(r1), "=r"(r2), "=r"(r3) : "r"(a));
}
__device__ __forceinline__ void ldm4t(u32 a, u32& r0, u32& r1, u32& r2, u32& r3) {
    asm volatile("ldmatrix.sync.aligned.m8n8.x4.trans.shared.b16 {%0,%1,%2,%3},[%4];"
                 : "=r"(r0), "=r"(r1), "=r"(r2), "=r"(r3) : "r"(a));
}
__device__ __forceinline__ void mma_h(float* c, u32 a0, u32 a1, u32 a2, u32 a3,
                                      u32 b0, u32 b1) {
    asm volatile(
        "mma.sync.aligned.m16n8k16.row.col.f32.f16.f16.f32 "
        "{%0,%1,%2,%3},{%4,%5,%6,%7},{%8,%9},{%0,%1,%2,%3};"
        : "+f"(c[0]), "+f"(c[1]), "+f"(c[2]), "+f"(c[3])
        : "r"(a0), "r"(a1), "r"(a2), "r"(a3), "r"(b0), "r"(b1));
}
__device__ __forceinline__ u32 pack2h(__half a, __half b) {
    __half2 t = __halves2half2(a, b);
    return *reinterpret_cast<u32*>(&t);
}
__device__ __forceinline__ u32 cvt2h(float x, float y) {
    return pack2h(__float2half_rn(x), __float2half_rn(y));
}
__device__ __forceinline__ void split2h(float x, float y, u32& h, u32& l) {
    __half hx = __float2half_rn(x), hy = __float2half_rn(y);
    __half lx = __float2half_rn(x - __half2float(hx));
    __half ly = __float2half_rn(y - __half2float(hy));
    h = pack2h(hx, hy);
    l = pack2h(lx, ly);
}
__device__ __forceinline__ float ex2(float x) {
    float y; asm("ex2.approx.f32 %0, %1;" : "=f"(y) : "f"(x)); return y;
}
__device__ __forceinline__ void cpa16(u32 dst, const void* src) {
    asm volatile("cp.async.cg.shared.global [%0], [%1], 16;" :: "r"(dst), "l"(src));
}
__device__ __forceinline__ void cpcommit() {
    asm volatile("cp.async.commit_group;");
}
template <int N>
__device__ __forceinline__ void cpwait() {
    asm volatile("cp.async.wait_group %0;" :: "n"(N));
}

// ---------------------------------------------------------------------------
// merged prep: split x -> xh/xl ; convert wq|wk|wv -> wqkvh ; wo -> woh
// ---------------------------------------------------------------------------
__global__ __launch_bounds__(256) void prep_all(
    const float* __restrict__ x, const float* __restrict__ wq,
    const float* __restrict__ wk, const float* __restrict__ wv,
    const float* __restrict__ wo,
    __half* __restrict__ xh, __half* __restrict__ xl,
    __half* __restrict__ wqkvh, __half* __restrict__ woh)
{
    int i = blockIdx.x * blockDim.x + threadIdx.x;
    if (i < N4X) {
        float4 v = ((const float4*)x)[i];
        u32 h0, h1, l0, l1;
        split2h(v.x, v.y, h0, l0); split2h(v.z, v.w, h1, l1);
        ((u32*)xh)[i * 2] = h0; ((u32*)xh)[i * 2 + 1] = h1;
        ((u32*)xl)[i * 2] = l0; ((u32*)xl)[i * 2 + 1] = l1;
        return;
    }
    i -= N4X;
    if (i < N4X) {
        float4 v = ((const float4*)wq)[i];
        ((u32*)wqkvh)[i * 2]     = cvt2h(v.x, v.y);
        ((u32*)wqkvh)[i * 2 + 1] = cvt2h(v.z, v.w);
        return;
    }
    i -= N4X;
    if (i < N4KV) {
        float4 v = ((const float4*)wk)[i];
        u32* dst = (u32*)(wqkvh + MX);
        dst[i * 2]     = cvt2h(v.x, v.y);
        dst[i * 2 + 1] = cvt2h(v.z, v.w);
        return;
    }
    i -= N4KV;
    if (i < N4KV) {
        float4 v = ((const float4*)wv)[i];
        u32* dst = (u32*)(wqkvh + MX + WKV);
        dst[i * 2]     = cvt2h(v.x, v.y);
        dst[i * 2 + 1] = cvt2h(v.z, v.w);
        return;
    }
    i -= N4KV;
    {
        float4 v = ((const float4*)wo)[i];
        ((u32*)woh)[i * 2]     = cvt2h(v.x, v.y);
        ((u32*)woh)[i * 2 + 1] = cvt2h(v.z, v.w);
    }
}

// ---------------------------------------------------------------------------
// C[M,N] = A[M,K] @ B[N,K]^T ; A split fp16 hi/lo (2-term), B single fp16.
// 128x128x32 tiles, 256 thr (8 warps: 4m x 2n), 3-stage cp.async ring.
// ---------------------------------------------------------------------------
__global__ __launch_bounds__(256, 2) void gemm2(
    const __half* __restrict__ Ah, const __half* __restrict__ Al,
    const __half* __restrict__ Bh, float* __restrict__ C, int M, int N, int K)
{
    extern __shared__ char smd[];
    const u32 smb = sptr(smd);
    const int tid = threadIdx.x, lane = tid & 31, w = tid >> 5;
    const int wm = w >> 1, wn = w & 1;
    const int bm = blockIdx.y * 128, bn = blockIdx.x * 128;

    float acc[2][8][4];
#pragma unroll
    for (int a = 0; a < 2; a++)
#pragma unroll
        for (int b = 0; b < 8; b++)
#pragma unroll
            for (int c = 0; c < 4; c++) acc[a][b][c] = 0.f;

    const u32 aoff = (wm * 32 + (lane & 15)) * 80 + (lane >> 4) * 16;
    const u32 boff = 20480 + (wn * 64 + (lane >> 4) * 8 + (lane & 7)) * 80
                     + ((lane >> 3) & 1) * 16;

    auto load_stage = [&](int stg, int k0) {
        u32 sb = smb + stg * 30720;
#pragma unroll
        for (int p = 0; p < 2; p++) {
            int c = tid + p * 256;
            int row = c >> 2, kc = (c & 3) * 8;
            u32 d = sb + row * 80 + kc * 2;
            size_t ga = (size_t)(bm + row) * K + k0 + kc;
            size_t gb = (size_t)(bn + row) * K + k0 + kc;
            cpa16(d,         Ah + ga);
            cpa16(d + 10240, Al + ga);
            cpa16(d + 20480, Bh + gb);
        }
        cpcommit();
    };

    const int NCH = K >> 5;
    load_stage(0, 0);
    load_stage(1, 32);

    int stg = 0;
    for (int ic = 0; ic < NCH; ic++) {
        if (ic + 2 < NCH) {
            int nxt = stg + 2; if (nxt >= 3) nxt -= 3;
            load_stage(nxt, (ic + 2) * 32);
            cpwait<2>();
        } else if (ic + 1 < NCH) {
            cpwait<1>();
        } else {
            cpwait<0>();
        }
        __syncthreads();
        const u32 base = smb + stg * 30720;
        const u32 a_h = base + aoff, a_l = a_h + 10240;
        const u32 b_ = base + boff;
#pragma unroll
        for (int ks = 0; ks < 2; ks++) {
            u32 ah[2][4], al[2][4];
            ldm4(a_h + ks * 32,        ah[0][0], ah[0][1], ah[0][2], ah[0][3]);
            ldm4(a_h + ks * 32 + 1280, ah[1][0], ah[1][1], ah[1][2], ah[1][3]);
            ldm4(a_l + ks * 32,        al[0][0], al[0][1], al[0][2], al[0][3]);
            ldm4(a_l + ks * 32 + 1280, al[1][0], al[1][1], al[1][2], al[1][3]);
#pragma unroll
            for (int g = 0; g < 4; g++) {
                u32 bh[4];
                ldm4(b_ + g * 1280 + ks * 32, bh[0], bh[1], bh[2], bh[3]);
#pragma unroll
                for (int mt = 0; mt < 2; mt++)
#pragma unroll
                    for (int s = 0; s < 2; s++) {
                        float* c = acc[mt][g * 2 + s];
                        mma_h(c, ah[mt][0], ah[mt][1], ah[mt][2], ah[mt][3],
                              bh[2 * s], bh[2 * s + 1]);
                        mma_h(c, al[mt][0], al[mt][1], al[mt][2], al[mt][3],
                              bh[2 * s], bh[2 * s + 1]);
                    }
            }
        }
        __syncthreads();
        stg = (stg + 1 == 3) ? 0 : stg + 1;
    }

#pragma unroll
    for (int mt = 0; mt < 2; mt++)
#pragma unroll
        for (int nt = 0; nt < 8; nt++) {
            int row = bm + wm * 32 + mt * 16 + (lane >> 2);
            int col = bn + wn * 64 + nt * 8 + (lane & 3) * 2;
            *(float2*)&C[(size_t)row * N + col] =
                make_float2(acc[mt][nt][0], acc[mt][nt][1]);
            *(float2*)&C[(size_t)(row + 8) * N + col] =
                make_float2(acc[mt][nt][2], acc[mt][nt][3]);
        }
}

// ---------------------------------------------------------------------------
// RMSNorm + RoPE + convert from packed qkv fp32.
// q is PRE-SCALED by scale*log2e before splitting (moves the logit scale
// out of the attention inner loop).
// ---------------------------------------------------------------------------
__global__ __launch_bounds__(256) void norm_rope_cvt(
    const float* __restrict__ qkvf, const float* __restrict__ freqs,
    __half* __restrict__ qh, __half* __restrict__ ql,
    __half* __restrict__ kh, __half* __restrict__ vh)
{
    const float CS = 0.08838834764831845f * 1.4426950408889634f; // scale*log2e
    int gwarp = (blockIdx.x * blockDim.x + threadIdx.x) >> 5;
    int lane  = threadIdx.x & 31;
    const int total = SLEN * 24;
    if (gwarp >= total) return;
    int s = gwarp / 24;
    int h = gwarp % 24;

    if (h >= 20) {
        const float* row = qkvf + (size_t)s * 3072 + 2560 + (h - 20) * 128;
        float4 x = *(const float4*)&row[lane * 4];
        size_t idx = ((((size_t)s * NKV + (h - 20)) * HD) >> 1) + lane * 2;
        ((u32*)vh)[idx]     = cvt2h(x.x, x.y);
        ((u32*)vh)[idx + 1] = cvt2h(x.z, x.w);
        return;
    }

    bool isq = (h < 16);
    const float* row = qkvf + (size_t)s * 3072 + (isq ? h * 128 : 2048 + (h - 16) * 128);
    float4 x = *(const float4*)&row[lane * 4];
    float ss = x.x * x.x + x.y * x.y + x.z * x.z + x.w * x.w;
#pragma unroll
    for (int off = 16; off; off >>= 1)
        ss += __shfl_xor_sync(0xffffffffu, ss, off);
    float r = rsqrtf(ss * (1.f / 128.f) + 1.1920929e-07f);
    if (isq) r *= CS;      // fold logit scale into q

    float4 fc = *(const float4*)&freqs[(size_t)s * 128 + lane * 4];
    float x1 = x.x * r, x2 = x.y * r, x3 = x.z * r, x4 = x.w * r;
    float o0 = x1 * fc.x - x2 * fc.y;
    float o1 = x1 * fc.y + x2 * fc.x;
    float o2 = x3 * fc.z - x4 * fc.w;
    float o3 = x3 * fc.w + x4 * fc.z;

    if (isq) {
        size_t idx = ((((size_t)s * NH + h) * HD) >> 1) + lane * 2;
        u32 h0, l0, h1, l1;
        split2h(o0, o1, h0, l0); split2h(o2, o3, h1, l1);
        ((u32*)qh)[idx] = h0; ((u32*)qh)[idx + 1] = h1;
        ((u32*)ql)[idx] = l0; ((u32*)ql)[idx + 1] = l1;
    } else {
        size_t idx = ((((size_t)s * NKV + (h - 16)) * HD) >> 1) + lane * 2;
        ((u32*)kh)[idx]     = cvt2h(o0, o1);
        ((u32*)kh)[idx + 1] = cvt2h(o2, o3);
    }
}

// ---------------------------------------------------------------------------
// Flash attention (causal, sink), FA2 warp layout: 4 warps (128 thr), each
// warp owns 16 q-rows x FULL 64-wide KV tile. P stays in registers.
// Grid is (NH, NQT) so launch order is head-fastest: every head's HEAVY
// tiles fill wave 1, light tiles trail -> near-zero scheduling tail, and
// the 4 q-heads per KV head run the same qt concurrently (L2 reuse).
// q pre-scaled by scale*log2e (no logit scaling in the loop).
// smem: Qh 0, Ql 17408, K 34816, V 52224 -> 69632 B (3 CTA/SM).
// ---------------------------------------------------------------------------
__global__ __launch_bounds__(128, 3) void attn_kernel(
    const __half* __restrict__ qh, const __half* __restrict__ ql,
    const __half* __restrict__ kh, const __half* __restrict__ vh,
    const float* __restrict__ sinks,
    __half* __restrict__ ath, __half* __restrict__ atl)
{
    extern __shared__ char smr[];
    const u32 smb = sptr(smr);

    const int tid = threadIdx.x, lane = tid & 31, w = tid >> 5;
    const int h = blockIdx.x, kvh = h >> 2;
    const int qt = gridDim.y - 1 - blockIdx.y;   // heavy tiles launch first

    // async-load Q tile (hi+lo): 64 rows x 256B x2
#pragma unroll
    for (int i = 0; i < 8; i++) {
        int c = tid + i * 128;
        int r = c >> 4, ck = c & 15;
        u32 d = smb + r * 272 + ck * 16;
        size_t g = ((size_t)(qt * 64 + r) * NH + h) * HD + ck * 8;
        cpa16(d,         qh + g);
        cpa16(d + 17408, ql + g);
    }
    auto load_k = [&](int kt) {
#pragma unroll
        for (int i = 0; i < 4; i++) {
            int c = tid + i * 128;
            int r = c >> 3, ck = c & 7;
            u32 d = smb + 34816 + r * 272 + ck * 32;
            size_t g = ((size_t)(kt * 64 + r) * NKV + kvh) * HD + ck * 16;
            cpa16(d,      kh + g);
            cpa16(d + 16, kh + g + 8);
        }
        cpcommit();
    };
    auto load_v = [&](int kt) {
#pragma unroll
        for (int i = 0; i < 4; i++) {
            int c = tid + i * 128;
            int r = c >> 3, ck = c & 7;
            u32 d = smb + 52224 + r * 272 + ck * 32;
            size_t g = ((size_t)(kt * 64 + r) * NKV + kvh) * HD + ck * 16;
            cpa16(d,      vh + g);
            cpa16(d + 16, vh + g + 8);
        }
        cpcommit();
    };
    load_k(0);   // Q + K(0) in one group

    float oacc[16][4];
#pragma unroll
    for (int a = 0; a < 16; a++)
#pragma unroll
        for (int c = 0; c < 4; c++) oacc[a][c] = 0.f;
    float mrow[2] = {-1e30f, -1e30f}, lrow[2] = {0.f, 0.f};

    const u32 qa = smb + (w * 16 + (lane & 15)) * 272 + (lane >> 4) * 16;
    const u32 kb = smb + 34816 + ((lane >> 4) * 8 + (lane & 7)) * 272
                   + ((lane >> 3) & 1) * 16;
    const u32 vb = smb + 52224 + (((lane >> 3) & 1) * 8 + (lane & 7)) * 272
                   + ((lane >> 4) * 8) * 2;

    for (int kt = 0; kt <= qt; kt++) {
        cpwait<0>();       // K(kt) (+Q first iter) arrived
        __syncthreads();   // (B) K visible; prev PV done with V buffer
        load_v(kt);        // V(kt) flies during QK

        // S = q K^T : m16 n64 k128 per warp, 2-term (already log2-scaled)
        float sacc[8][4];
#pragma unroll
        for (int a = 0; a < 8; a++)
#pragma unroll
            for (int c = 0; c < 4; c++) sacc[a][c] = 0.f;

#pragma unroll
        for (int ks = 0; ks < 8; ks++) {
            u32 ah0, ah1, ah2, ah3, al0, al1, al2, al3;
            ldm4(qa + ks * 32,         ah0, ah1, ah2, ah3);
            ldm4(qa + 17408 + ks * 32, al0, al1, al2, al3);
#pragma unroll
            for (int g = 0; g < 4; g++) {
                u32 bh[4];
                ldm4(kb + g * 4352 + ks * 32, bh[0], bh[1], bh[2], bh[3]);
#pragma unroll
                for (int s = 0; s < 2; s++) {
                    float* c = sacc[g * 2 + s];
                    mma_h(c, ah0, ah1, ah2, ah3, bh[2 * s], bh[2 * s + 1]);
                    mma_h(c, al0, al1, al2, al3, bh[2 * s], bh[2 * s + 1]);
                }
            }
        }
        __syncthreads();   // (B2) all warps done reading K buffer
        if (kt < qt) load_k(kt + 1);   // K(kt+1) flies during softmax

        // causal mask on diagonal tile
        if (kt == qt) {
            int r0 = qt * 64 + w * 16 + (lane >> 2);
#pragma unroll
            for (int nt = 0; nt < 8; nt++) {
                int col0 = kt * 64 + nt * 8 + (lane & 3) * 2;
#pragma unroll
                for (int ci = 0; ci < 4; ci++) {
                    int row = r0 + ((ci >= 2) ? 8 : 0);
                    int col = col0 + (ci & 1);
                    if (col > row) sacc[nt][ci] = -1e30f;
                }
            }
        }

        // softmax: rows fully quad-local, exp in place into sacc
        float alpha[2];
#pragma unroll
        for (int i = 0; i < 2; i++) {
            float rm = -1e30f;
#pragma unroll
            for (int nt = 0; nt < 8; nt++)
                rm = fmaxf(rm, fmaxf(sacc[nt][2 * i], sacc[nt][2 * i + 1]));
            rm = fmaxf(rm, __shfl_xor_sync(0xffffffffu, rm, 1));
            rm = fmaxf(rm, __shfl_xor_sync(0xffffffffu, rm, 2));
            float mn = fmaxf(mrow[i], rm);
            alpha[i] = ex2(mrow[i] - mn);
            mrow[i] = mn;
            float rs = 0.f;
#pragma unroll
            for (int nt = 0; nt < 8; nt++) {
                float p0 = ex2(sacc[nt][2 * i] - mn);
                float p1 = ex2(sacc[nt][2 * i + 1] - mn);
                sacc[nt][2 * i] = p0; sacc[nt][2 * i + 1] = p1;
                rs += p0 + p1;
            }
            rs += __shfl_xor_sync(0xffffffffu, rs, 1);
            rs += __shfl_xor_sync(0xffffffffu, rs, 2);
            lrow[i] = lrow[i] * alpha[i] + rs;
#pragma unroll
            for (int nt = 0; nt < 16; nt++) {
                oacc[nt][2 * i]     *= alpha[i];
                oacc[nt][2 * i + 1] *= alpha[i];
            }
        }

        cpwait<(1)>();     // V(kt) in (K(kt+1) may still fly)
        if (kt == qt) cpwait<0>();
        __syncthreads();   // (D) V visible to all warps

        // O += P V : m16 n128 k64, P from registers (split hi/lo)
#pragma unroll
        for (int j = 0; j < 4; j++) {
            u32 ph0, ph1, ph2, ph3, pl0, pl1, pl2, pl3;
            split2h(sacc[2 * j][0],     sacc[2 * j][1],     ph0, pl0);
            split2h(sacc[2 * j][2],     sacc[2 * j][3],     ph1, pl1);
            split2h(sacc[2 * j + 1][0], sacc[2 * j + 1][1], ph2, pl2);
            split2h(sacc[2 * j + 1][2], sacc[2 * j + 1][3], ph3, pl3);
#pragma unroll
            for (int g = 0; g < 8; g++) {
                u32 bh[4];
                ldm4t(vb + j * 4352 + g * 32, bh[0], bh[1], bh[2], bh[3]);
#pragma unroll
                for (int s = 0; s < 2; s++) {
                    float* c = oacc[g * 2 + s];
                    mma_h(c, ph0, ph1, ph2, ph3, bh[2 * s], bh[2 * s + 1]);
                    mma_h(c, pl0, pl1, pl2, pl3, bh[2 * s], bh[2 * s + 1]);
                }
            }
        }
    }

    // epilogue: lse, sink sigmoid, normalize, split-store
    float sk = sinks[h];
#pragma unroll
    for (int i = 0; i < 2; i++) {
        float lse = mrow[i] * 0.6931471805599453f + logf(lrow[i]);
        float sg = 1.f / (1.f + expf(sk - lse));
        float sc = sg / lrow[i];
        int row = qt * 64 + w * 16 + (lane >> 2) + i * 8;
        size_t rb = (size_t)row * DMODEL + h * HD;
#pragma unroll
        for (int nt = 0; nt < 16; nt++) {
            int col = nt * 8 + (lane & 3) * 2;
            u32 hh, ll;
            split2h(oacc[nt][2 * i] * sc, oacc[nt][2 * i + 1] * sc, hh, ll);
            ((u32*)ath)[(rb + col) >> 1] = hh;
            ((u32*)atl)[(rb + col) >> 1] = ll;
        }
    }
}

// ---------------------------------------------------------------------------
extern "C" void kernel_launch(void* const* d_in, const int* in_sizes, int n_in,
                              void* d_out, int out_size)
{
    const float* x     = (const float*)d_in[0];
    const float* freqs = (const float*)d_in[1];
    const float* wq    = (const float*)d_in[2];
    const float* wk    = (const float*)d_in[3];
    const float* wv    = (const float*)d_in[4];
    const float* wo    = (const float*)d_in[5];
    const float* sinks = (const float*)d_in[6];
    float* out = (float*)d_out;

    float* qkvf;
    __half *xh, *xl, *wqkvh, *woh, *qh, *ql, *kh, *vh, *ath, *atl;
    cudaGetSymbolAddress((void**)&qkvf,  g_qkvf);
    cudaGetSymbolAddress((void**)&xh,    s_xh);
    cudaGetSymbolAddress((void**)&xl,    s_xl);
    cudaGetSymbolAddress((void**)&wqkvh, s_wqkvh);
    cudaGetSymbolAddress((void**)&woh,   s_woh);
    cudaGetSymbolAddress((void**)&qh,    s_qh);
    cudaGetSymbolAddress((void**)&ql,    s_ql);
    cudaGetSymbolAddress((void**)&kh,    s_kh);
    cudaGetSymbolAddress((void**)&vh,    s_vh);
    cudaGetSymbolAddress((void**)&ath,   s_ath);
    cudaGetSymbolAddress((void**)&atl,   s_atl);

    cudaFuncSetAttribute(gemm2, cudaFuncAttributeMaxDynamicSharedMemorySize, 92160);
    cudaFuncSetAttribute(attn_kernel, cudaFuncAttributeMaxDynamicSharedMemorySize, 69632);

    // merged operand prep
    const int PREP_ITEMS = N4X * 3 + N4KV * 2;
    prep_all<<<PREP_ITEMS / 256, 256>>>(x, wq, wk, wv, wo, xh, xl, wqkvh, woh);

    // fused QKV projection: [2048, 3072] = x @ [wq|wk|wv]^T
    gemm2<<<dim3(24, 16), 256, 92160>>>(xh, xl, wqkvh, qkvf, SLEN, 3072, DMODEL);

    // RMSNorm + RoPE + convert (q split + pre-scaled, k/v single)
    norm_rope_cvt<<<(SLEN * 24 * 32) / 256, 256>>>(qkvf, freqs, qh, ql, kh, vh);

    // causal flash attention with sink scaling (heavy-first grid order)
    attn_kernel<<<dim3(NH, SLEN / 64), 128, 69632>>>(qh, ql, kh, vh, sinks, ath, atl);

    // output projection
    gemm2<<<dim3(16, 16), 256, 92160>>>(ath, atl, woh, out, SLEN, DMODEL, DMODEL);
}

// round 11
// speedup vs baseline: 10.7413x; 1.3289x over previous
#include <cuda_runtime.h>
#include <cuda_fp16.h>
#include <math.h>

typedef unsigned int u32;

#define SLEN 2048
#define DMODEL 2048
#define NH 16
#define NKV 4
#define HD 128
#define MX (SLEN * DMODEL)          // 4194304
#define MKV (SLEN * NKV * HD)       // 1048576
#define WKV (NKV * HD * DMODEL)     // 1048576
#define N4X (MX / 4)                // 1048576 float4 items
#define N4KV (WKV / 4)              // 262144

// fp32 packed QKV projection output: [s][3072] (q 0-2047, k 2048-2559, v 2560-3071)
__device__ __align__(16) float g_qkvf[SLEN * 3072];

// fp16 operands
__device__ __align__(16) __half s_xh[MX];                    // x single
__device__ __align__(16) __half s_wqkvh[3072 * DMODEL];      // packed wq|wk|wv, single
__device__ __align__(16) __half s_woh[MX];                   // wo, single
__device__ __align__(16) __half s_qh[MX], s_ql[MX];          // q split (post norm+rope, pre-scaled)
__device__ __align__(16) __half s_kh[MKV];                   // k single (post norm+rope)
__device__ __align__(16) __half s_vh[MKV];                   // v single
__device__ __align__(16) __half s_ath[MX];                   // attention out single

// ---------------------------------------------------------------------------
// helpers
// ---------------------------------------------------------------------------
__device__ __forceinline__ u32 sptr(const void* p) {
    return (u32)__cvta_generic_to_shared(p);
}
__device__ __forceinline__ void ldm4(u32 a, u32& r0, u32& r1, u32& r2, u32& r3) {
    asm volatile("ldmatrix.sync.aligned.m8n8.x4.shared.b16 {%0,%1,%2,%3},[%4];"
                 : "=r"(r0), "=r"(r1), "=r"(r2), "=r"(r3) : "r"(a));
}
__device__ __forceinline__ void ldm4t(u32 a, u32& r0, u32& r1, u32& r2, u32& r3) {
    asm volatile("ldmatrix.sync.aligned.m8n8.x4.trans.shared.b16 {%0,%1,%2,%3},[%4];"
                 : "=r"(r0), "=r"(r1), "=r"(r2), "=r"(r3) : "r"(a));
}
__device__ __forceinline__ void mma_h(float* c, u32 a0, u32 a1, u32 a2, u32 a3,
                                      u32 b0, u32 b1) {
    asm volatile(
        "mma.sync.aligned.m16n8k16.row.col.f32.f16.f16.f32 "
        "{%0,%1,%2,%3},{%4,%5,%6,%7},{%8,%9},{%0,%1,%2,%3};"
        : "+f"(c[0]), "+f"(c[1]), "+f"(c[2]), "+f"(c[3])
        : "r"(a0), "r"(a1), "r"(a2), "r"(a3), "r"(b0), "r"(b1));
}
__device__ __forceinline__ u32 pack2h(__half a, __half b) {
    __half2 t = __halves2half2(a, b);
    return *reinterpret_cast<u32*>(&t);
}
__device__ __forceinline__ u32 cvt2h(float x, float y) {
    return pack2h(__float2half_rn(x), __float2half_rn(y));
}
__device__ __forceinline__ void split2h(float x, float y, u32& h, u32& l) {
    __half hx = __float2half_rn(x), hy = __float2half_rn(y);
    __half lx = __float2half_rn(x - __half2float(hx));
    __half ly = __float2half_rn(y - __half2float(hy));
    h = pack2h(hx, hy);
    l = pack2h(lx, ly);
}
__device__ __forceinline__ float ex2(float x) {
    float y; asm("ex2.approx.f32 %0, %1;" : "=f"(y) : "f"(x)); return y;
}
__device__ __forceinline__ void cpa16(u32 dst, const void* src) {
    asm volatile("cp.async.cg.shared.global [%0], [%1], 16;" :: "r"(dst), "l"(src));
}
__device__ __forceinline__ void cpcommit() {
    asm volatile("cp.async.commit_group;");
}
template <int N>
__device__ __forceinline__ void cpwait() {
    asm volatile("cp.async.wait_group %0;" :: "n"(N));
}

// ---------------------------------------------------------------------------
// merged prep: convert x -> xh ; wq|wk|wv -> wqkvh ; wo -> woh (all single)
// ---------------------------------------------------------------------------
__global__ __launch_bounds__(256) void prep_all(
    const float* __restrict__ x, const float* __restrict__ wq,
    const float* __restrict__ wk, const float* __restrict__ wv,
    const float* __restrict__ wo,
    __half* __restrict__ xh, __half* __restrict__ wqkvh, __half* __restrict__ woh)
{
    int i = blockIdx.x * blockDim.x + threadIdx.x;
    if (i < N4X) {
        float4 v = ((const float4*)x)[i];
        ((u32*)xh)[i * 2]     = cvt2h(v.x, v.y);
        ((u32*)xh)[i * 2 + 1] = cvt2h(v.z, v.w);
        return;
    }
    i -= N4X;
    if (i < N4X) {
        float4 v = ((const float4*)wq)[i];
        ((u32*)wqkvh)[i * 2]     = cvt2h(v.x, v.y);
        ((u32*)wqkvh)[i * 2 + 1] = cvt2h(v.z, v.w);
        return;
    }
    i -= N4X;
    if (i < N4KV) {
        float4 v = ((const float4*)wk)[i];
        u32* dst = (u32*)(wqkvh + MX);
        dst[i * 2]     = cvt2h(v.x, v.y);
        dst[i * 2 + 1] = cvt2h(v.z, v.w);
        return;
    }
    i -= N4KV;
    if (i < N4KV) {
        float4 v = ((const float4*)wv)[i];
        u32* dst = (u32*)(wqkvh + MX + WKV);
        dst[i * 2]     = cvt2h(v.x, v.y);
        dst[i * 2 + 1] = cvt2h(v.z, v.w);
        return;
    }
    i -= N4KV;
    {
        float4 v = ((const float4*)wo)[i];
        ((u32*)woh)[i * 2]     = cvt2h(v.x, v.y);
        ((u32*)woh)[i * 2 + 1] = cvt2h(v.z, v.w);
    }
}

// ---------------------------------------------------------------------------
// C[M,N] = A[M,K] @ B[N,K]^T ; both single fp16, 1-term MMA.
// 128x128x32 tiles, 256 thr (8 warps: 4m x 2n), 3-stage cp.async ring.
// dyn smem per stage 20480 B: A@0 B@10240; row stride 80 B. x3 = 61440.
// ---------------------------------------------------------------------------
__global__ __launch_bounds__(256, 2) void gemm1(
    const __half* __restrict__ Ah, const __half* __restrict__ Bh,
    float* __restrict__ C, int M, int N, int K)
{
    extern __shared__ char smd[];
    const u32 smb = sptr(smd);
    const int tid = threadIdx.x, lane = tid & 31, w = tid >> 5;
    const int wm = w >> 1, wn = w & 1;
    const int bm = blockIdx.y * 128, bn = blockIdx.x * 128;

    float acc[2][8][4];
#pragma unroll
    for (int a = 0; a < 2; a++)
#pragma unroll
        for (int b = 0; b < 8; b++)
#pragma unroll
            for (int c = 0; c < 4; c++) acc[a][b][c] = 0.f;

    const u32 aoff = (wm * 32 + (lane & 15)) * 80 + (lane >> 4) * 16;
    const u32 boff = 10240 + (wn * 64 + (lane >> 4) * 8 + (lane & 7)) * 80
                     + ((lane >> 3) & 1) * 16;

    auto load_stage = [&](int stg, int k0) {
        u32 sb = smb + stg * 20480;
#pragma unroll
        for (int p = 0; p < 2; p++) {
            int c = tid + p * 256;
            int row = c >> 2, kc = (c & 3) * 8;
            u32 d = sb + row * 80 + kc * 2;
            size_t ga = (size_t)(bm + row) * K + k0 + kc;
            size_t gb = (size_t)(bn + row) * K + k0 + kc;
            cpa16(d,         Ah + ga);
            cpa16(d + 10240, Bh + gb);
        }
        cpcommit();
    };

    const int NCH = K >> 5;
    load_stage(0, 0);
    load_stage(1, 32);

    int stg = 0;
    for (int ic = 0; ic < NCH; ic++) {
        if (ic + 2 < NCH) {
            int nxt = stg + 2; if (nxt >= 3) nxt -= 3;
            load_stage(nxt, (ic + 2) * 32);
            cpwait<2>();
        } else if (ic + 1 < NCH) {
            cpwait<1>();
        } else {
            cpwait<0>();
        }
        __syncthreads();
        const u32 base = smb + stg * 20480;
        const u32 a_ = base + aoff;
        const u32 b_ = base + boff;
#pragma unroll
        for (int ks = 0; ks < 2; ks++) {
            u32 ah[2][4];
            ldm4(a_ + ks * 32,        ah[0][0], ah[0][1], ah[0][2], ah[0][3]);
            ldm4(a_ + ks * 32 + 1280, ah[1][0], ah[1][1], ah[1][2], ah[1][3]);
#pragma unroll
            for (int g = 0; g < 4; g++) {
                u32 bh[4];
                ldm4(b_ + g * 1280 + ks * 32, bh[0], bh[1], bh[2], bh[3]);
#pragma unroll
                for (int mt = 0; mt < 2; mt++)
#pragma unroll
                    for (int s = 0; s < 2; s++)
                        mma_h(acc[mt][g * 2 + s],
                              ah[mt][0], ah[mt][1], ah[mt][2], ah[mt][3],
                              bh[2 * s], bh[2 * s + 1]);
            }
        }
        __syncthreads();
        stg = (stg + 1 == 3) ? 0 : stg + 1;
    }

#pragma unroll
    for (int mt = 0; mt < 2; mt++)
#pragma unroll
        for (int nt = 0; nt < 8; nt++) {
            int row = bm + wm * 32 + mt * 16 + (lane >> 2);
            int col = bn + wn * 64 + nt * 8 + (lane & 3) * 2;
            *(float2*)&C[(size_t)row * N + col] =
                make_float2(acc[mt][nt][0], acc[mt][nt][1]);
            *(float2*)&C[(size_t)(row + 8) * N + col] =
                make_float2(acc[mt][nt][2], acc[mt][nt][3]);
        }
}

// ---------------------------------------------------------------------------
// RMSNorm + RoPE + convert from packed qkv fp32.
// q is PRE-SCALED by scale*log2e before splitting.
// ---------------------------------------------------------------------------
__global__ __launch_bounds__(256) void norm_rope_cvt(
    const float* __restrict__ qkvf, const float* __restrict__ freqs,
    __half* __restrict__ qh, __half* __restrict__ ql,
    __half* __restrict__ kh, __half* __restrict__ vh)
{
    const float CS = 0.08838834764831845f * 1.4426950408889634f; // scale*log2e
    int gwarp = (blockIdx.x * blockDim.x + threadIdx.x) >> 5;
    int lane  = threadIdx.x & 31;
    const int total = SLEN * 24;
    if (gwarp >= total) return;
    int s = gwarp / 24;
    int h = gwarp % 24;

    if (h >= 20) {
        const float* row = qkvf + (size_t)s * 3072 + 2560 + (h - 20) * 128;
        float4 x = *(const float4*)&row[lane * 4];
        size_t idx = ((((size_t)s * NKV + (h - 20)) * HD) >> 1) + lane * 2;
        ((u32*)vh)[idx]     = cvt2h(x.x, x.y);
        ((u32*)vh)[idx + 1] = cvt2h(x.z, x.w);
        return;
    }

    bool isq = (h < 16);
    const float* row = qkvf + (size_t)s * 3072 + (isq ? h * 128 : 2048 + (h - 16) * 128);
    float4 x = *(const float4*)&row[lane * 4];
    float ss = x.x * x.x + x.y * x.y + x.z * x.z + x.w * x.w;
#pragma unroll
    for (int off = 16; off; off >>= 1)
        ss += __shfl_xor_sync(0xffffffffu, ss, off);
    float r = rsqrtf(ss * (1.f / 128.f) + 1.1920929e-07f);
    if (isq) r *= CS;

    float4 fc = *(const float4*)&freqs[(size_t)s * 128 + lane * 4];
    float x1 = x.x * r, x2 = x.y * r, x3 = x.z * r, x4 = x.w * r;
    float o0 = x1 * fc.x - x2 * fc.y;
    float o1 = x1 * fc.y + x2 * fc.x;
    float o2 = x3 * fc.z - x4 * fc.w;
    float o3 = x3 * fc.w + x4 * fc.z;

    if (isq) {
        size_t idx = ((((size_t)s * NH + h) * HD) >> 1) + lane * 2;
        u32 h0, l0, h1, l1;
        split2h(o0, o1, h0, l0); split2h(o2, o3, h1, l1);
        ((u32*)qh)[idx] = h0; ((u32*)qh)[idx + 1] = h1;
        ((u32*)ql)[idx] = l0; ((u32*)ql)[idx + 1] = l1;
    } else {
        size_t idx = ((((size_t)s * NKV + (h - 16)) * HD) >> 1) + lane * 2;
        ((u32*)kh)[idx]     = cvt2h(o0, o1);
        ((u32*)kh)[idx + 1] = cvt2h(o2, o3);
    }
}

// ---------------------------------------------------------------------------
// Flash attention (causal, sink), FA2 warp layout: 4 warps (128 thr).
// q split (2-term QK), k/v single, P split (2-term PV). Output single fp16.
// Grid (NH, NQT) heavy-first. smem: Qh 0, Ql 17408, K 34816, V 52224 -> 69632.
// ---------------------------------------------------------------------------
__global__ __launch_bounds__(128, 3) void attn_kernel(
    const __half* __restrict__ qh, const __half* __restrict__ ql,
    const __half* __restrict__ kh, const __half* __restrict__ vh,
    const float* __restrict__ sinks, __half* __restrict__ ath)
{
    extern __shared__ char smr[];
    const u32 smb = sptr(smr);

    const int tid = threadIdx.x, lane = tid & 31, w = tid >> 5;
    const int h = blockIdx.x, kvh = h >> 2;
    const int qt = gridDim.y - 1 - blockIdx.y;   // heavy tiles launch first

    // async-load Q tile (hi+lo): 64 rows x 256B x2
#pragma unroll
    for (int i = 0; i < 8; i++) {
        int c = tid + i * 128;
        int r = c >> 4, ck = c & 15;
        u32 d = smb + r * 272 + ck * 16;
        size_t g = ((size_t)(qt * 64 + r) * NH + h) * HD + ck * 8;
        cpa16(d,         qh + g);
        cpa16(d + 17408, ql + g);
    }
    auto load_k = [&](int kt) {
#pragma unroll
        for (int i = 0; i < 4; i++) {
            int c = tid + i * 128;
            int r = c >> 3, ck = c & 7;
            u32 d = smb + 34816 + r * 272 + ck * 32;
            size_t g = ((size_t)(kt * 64 + r) * NKV + kvh) * HD + ck * 16;
            cpa16(d,      kh + g);
            cpa16(d + 16, kh + g + 8);
        }
        cpcommit();
    };
    auto load_v = [&](int kt) {
#pragma unroll
        for (int i = 0; i < 4; i++) {
            int c = tid + i * 128;
            int r = c >> 3, ck = c & 7;
            u32 d = smb + 52224 + r * 272 + ck * 32;
            size_t g = ((size_t)(kt * 64 + r) * NKV + kvh) * HD + ck * 16;
            cpa16(d,      vh + g);
            cpa16(d + 16, vh + g + 8);
        }
        cpcommit();
    };
    load_k(0);   // Q + K(0) in one group

    float oacc[16][4];
#pragma unroll
    for (int a = 0; a < 16; a++)
#pragma unroll
        for (int c = 0; c < 4; c++) oacc[a][c] = 0.f;
    float mrow[2] = {-1e30f, -1e30f}, lrow[2] = {0.f, 0.f};

    const u32 qa = smb + (w * 16 + (lane & 15)) * 272 + (lane >> 4) * 16;
    const u32 kb = smb + 34816 + ((lane >> 4) * 8 + (lane & 7)) * 272
                   + ((lane >> 3) & 1) * 16;
    const u32 vb = smb + 52224 + (((lane >> 3) & 1) * 8 + (lane & 7)) * 272
                   + ((lane >> 4) * 8) * 2;

    for (int kt = 0; kt <= qt; kt++) {
        cpwait<0>();       // K(kt) (+Q first iter) arrived
        __syncthreads();   // (B) K visible; prev PV done with V buffer
        load_v(kt);        // V(kt) flies during QK

        float sacc[8][4];
#pragma unroll
        for (int a = 0; a < 8; a++)
#pragma unroll
            for (int c = 0; c < 4; c++) sacc[a][c] = 0.f;

#pragma unroll
        for (int ks = 0; ks < 8; ks++) {
            u32 ah0, ah1, ah2, ah3, al0, al1, al2, al3;
            ldm4(qa + ks * 32,         ah0, ah1, ah2, ah3);
            ldm4(qa + 17408 + ks * 32, al0, al1, al2, al3);
#pragma unroll
            for (int g = 0; g < 4; g++) {
                u32 bh[4];
                ldm4(kb + g * 4352 + ks * 32, bh[0], bh[1], bh[2], bh[3]);
#pragma unroll
                for (int s = 0; s < 2; s++) {
                    float* c = sacc[g * 2 + s];
                    mma_h(c, ah0, ah1, ah2, ah3, bh[2 * s], bh[2 * s + 1]);
                    mma_h(c, al0, al1, al2, al3, bh[2 * s], bh[2 * s + 1]);
                }
            }
        }
        __syncthreads();   // (B2) all warps done reading K buffer
        if (kt < qt) load_k(kt + 1);   // K(kt+1) flies during softmax

        // causal mask on diagonal tile
        if (kt == qt) {
            int r0 = qt * 64 + w * 16 + (lane >> 2);
#pragma unroll
            for (int nt = 0; nt < 8; nt++) {
                int col0 = kt * 64 + nt * 8 + (lane & 3) * 2;
#pragma unroll
                for (int ci = 0; ci < 4; ci++) {
                    int row = r0 + ((ci >= 2) ? 8 : 0);
                    int col = col0 + (ci & 1);
                    if (col > row) sacc[nt][ci] = -1e30f;
                }
            }
        }

        // softmax: rows fully quad-local, exp in place into sacc
        float alpha[2];
#pragma unroll
        for (int i = 0; i < 2; i++) {
            float rm = -1e30f;
#pragma unroll
            for (int nt = 0; nt < 8; nt++)
                rm = fmaxf(rm, fmaxf(sacc[nt][2 * i], sacc[nt][2 * i + 1]));
            rm = fmaxf(rm, __shfl_xor_sync(0xffffffffu, rm, 1));
            rm = fmaxf(rm, __shfl_xor_sync(0xffffffffu, rm, 2));
            float mn = fmaxf(mrow[i], rm);
            alpha[i] = ex2(mrow[i] - mn);
            mrow[i] = mn;
            float rs = 0.f;
#pragma unroll
            for (int nt = 0; nt < 8; nt++) {
                float p0 = ex2(sacc[nt][2 * i] - mn);
                float p1 = ex2(sacc[nt][2 * i + 1] - mn);
                sacc[nt][2 * i] = p0; sacc[nt][2 * i + 1] = p1;
                rs += p0 + p1;
            }
            rs += __shfl_xor_sync(0xffffffffu, rs, 1);
            rs += __shfl_xor_sync(0xffffffffu, rs, 2);
            lrow[i] = lrow[i] * alpha[i] + rs;
#pragma unroll
            for (int nt = 0; nt < 16; nt++) {
                oacc[nt][2 * i]     *= alpha[i];
                oacc[nt][2 * i + 1] *= alpha[i];
            }
        }

        cpwait<(1)>();     // V(kt) in (K(kt+1) may still fly)
        if (kt == qt) cpwait<0>();
        __syncthreads();   // (D) V visible to all warps

        // O += P V : m16 n128 k64, P from registers (split hi/lo)
#pragma unroll
        for (int j = 0; j < 4; j++) {
            u32 ph0, ph1, ph2, ph3, pl0, pl1, pl2, pl3;
            split2h(sacc[2 * j][0],     sacc[2 * j][1],     ph0, pl0);
            split2h(sacc[2 * j][2],     sacc[2 * j][3],     ph1, pl1);
            split2h(sacc[2 * j + 1][0], sacc[2 * j + 1][1], ph2, pl2);
            split2h(sacc[2 * j + 1][2], sacc[2 * j + 1][3], ph3, pl3);
#pragma unroll
            for (int g = 0; g < 8; g++) {
                u32 bh[4];
                ldm4t(vb + j * 4352 + g * 32, bh[0], bh[1], bh[2], bh[3]);
#pragma unroll
                for (int s = 0; s < 2; s++) {
                    float* c = oacc[g * 2 + s];
                    mma_h(c, ph0, ph1, ph2, ph3, bh[2 * s], bh[2 * s + 1]);
                    mma_h(c, pl0, pl1, pl2, pl3, bh[2 * s], bh[2 * s + 1]);
                }
            }
        }
    }

    // epilogue: lse, sink sigmoid, normalize, single-fp16 store
    float sk = sinks[h];
#pragma unroll
    for (int i = 0; i < 2; i++) {
        float lse = mrow[i] * 0.6931471805599453f + logf(lrow[i]);
        float sg = 1.f / (1.f + expf(sk - lse));
        float sc = sg / lrow[i];
        int row = qt * 64 + w * 16 + (lane >> 2) + i * 8;
        size_t rb = (size_t)row * DMODEL + h * HD;
#pragma unroll
        for (int nt = 0; nt < 16; nt++) {
            int col = nt * 8 + (lane & 3) * 2;
            ((u32*)ath)[(rb + col) >> 1] =
                cvt2h(oacc[nt][2 * i] * sc, oacc[nt][2 * i + 1] * sc);
        }
    }
}

// ---------------------------------------------------------------------------
extern "C" void kernel_launch(void* const* d_in, const int* in_sizes, int n_in,
                              void* d_out, int out_size)
{
    const float* x     = (const float*)d_in[0];
    const float* freqs = (const float*)d_in[1];
    const float* wq    = (const float*)d_in[2];
    const float* wk    = (const float*)d_in[3];
    const float* wv    = (const float*)d_in[4];
    const float* wo    = (const float*)d_in[5];
    const float* sinks = (const float*)d_in[6];
    float* out = (float*)d_out;

    float* qkvf;
    __half *xh, *wqkvh, *woh, *qh, *ql, *kh, *vh, *ath;
    cudaGetSymbolAddress((void**)&qkvf,  g_qkvf);
    cudaGetSymbolAddress((void**)&xh,    s_xh);
    cudaGetSymbolAddress((void**)&wqkvh, s_wqkvh);
    cudaGetSymbolAddress((void**)&woh,   s_woh);
    cudaGetSymbolAddress((void**)&qh,    s_qh);
    cudaGetSymbolAddress((void**)&ql,    s_ql);
    cudaGetSymbolAddress((void**)&kh,    s_kh);
    cudaGetSymbolAddress((void**)&vh,    s_vh);
    cudaGetSymbolAddress((void**)&ath,   s_ath);

    cudaFuncSetAttribute(gemm1, cudaFuncAttributeMaxDynamicSharedMemorySize, 61440);
    cudaFuncSetAttribute(attn_kernel, cudaFuncAttributeMaxDynamicSharedMemorySize, 69632);

    // merged operand prep (all single fp16)
    const int PREP_ITEMS = N4X * 3 + N4KV * 2;
    prep_all<<<PREP_ITEMS / 256, 256>>>(x, wq, wk, wv, wo, xh, wqkvh, woh);

    // fused QKV projection: [2048, 3072] = x @ [wq|wk|wv]^T
    gemm1<<<dim3(24, 16), 256, 61440>>>(xh, wqkvh, qkvf, SLEN, 3072, DMODEL);

    // RMSNorm + RoPE + convert (q split + pre-scaled, k/v single)
    norm_rope_cvt<<<(SLEN * 24 * 32) / 256, 256>>>(qkvf, freqs, qh, ql, kh, vh);

    // causal flash attention with sink scaling (heavy-first grid order)
    attn_kernel<<<dim3(NH, SLEN / 64), 128, 69632>>>(qh, ql, kh, vh, sinks, ath);

    // output projection
    gemm1<<<dim3(16, 16), 256, 61440>>>(ath, woh, out, SLEN, DMODEL, DMODEL);
}

// round 12
// speedup vs baseline: 11.4430x; 1.0653x over previous
#include <cuda_runtime.h>
#include <cuda_fp16.h>
#include <math.h>

typedef unsigned int u32;

#define SLEN 2048
#define DMODEL 2048
#define NH 16
#define NKV 4
#define HD 128
#define MX (SLEN * DMODEL)          // 4194304
#define MKV (SLEN * NKV * HD)       // 1048576
#define WKV (NKV * HD * DMODEL)     // 1048576
#define N4X (MX / 4)                // 1048576 float4 items
#define N4KV (WKV / 4)              // 262144

// fp32 packed QKV projection output: [s][3072] (q 0-2047, k 2048-2559, v 2560-3071)
__device__ __align__(16) float g_qkvf[SLEN * 3072];

// fp16 operands
__device__ __align__(16) __half s_xh[MX];                    // x single
__device__ __align__(16) __half s_wqkvh[3072 * DMODEL];      // packed wq|wk|wv, single
__device__ __align__(16) __half s_woh[MX];                   // wo, single
__device__ __align__(16) __half s_qh[MX];                    // q single (post norm+rope, pre-scaled)
__device__ __align__(16) __half s_kh[MKV];                   // k single (post norm+rope)
__device__ __align__(16) __half s_vh[MKV];                   // v single
__device__ __align__(16) __half s_ath[MX];                   // attention out single

// ---------------------------------------------------------------------------
// helpers
// ---------------------------------------------------------------------------
__device__ __forceinline__ u32 sptr(const void* p) {
    return (u32)__cvta_generic_to_shared(p);
}
__device__ __forceinline__ void ldm4(u32 a, u32& r0, u32& r1, u32& r2, u32& r3) {
    asm volatile("ldmatrix.sync.aligned.m8n8.x4.shared.b16 {%0,%1,%2,%3},[%4];"
                 : "=r"(r0), "=r"(r1), "=r"(r2), "=r"(r3) : "r"(a));
}
__device__ __forceinline__ void ldm4t(u32 a, u32& r0, u32& r1, u32& r2, u32& r3) {
    asm volatile("ldmatrix.sync.aligned.m8n8.x4.trans.shared.b16 {%0,%1,%2,%3},[%4];"
                 : "=r"(r0), "=r"(r1), "=r"(r2), "=r"(r3) : "r"(a));
}
__device__ __forceinline__ void mma_h(float* c, u32 a0, u32 a1, u32 a2, u32 a3,
                                      u32 b0, u32 b1) {
    asm volatile(
        "mma.sync.aligned.m16n8k16.row.col.f32.f16.f16.f32 "
        "{%0,%1,%2,%3},{%4,%5,%6,%7},{%8,%9},{%0,%1,%2,%3};"
        : "+f"(c[0]), "+f"(c[1]), "+f"(c[2]), "+f"(c[3])
        : "r"(a0), "r"(a1), "r"(a2), "r"(a3), "r"(b0), "r"(b1));
}
__device__ __forceinline__ u32 pack2h(__half a, __half b) {
    __half2 t = __halves2half2(a, b);
    return *reinterpret_cast<u32*>(&t);
}
__device__ __forceinline__ u32 cvt2h(float x, float y) {
    return pack2h(__float2half_rn(x), __float2half_rn(y));
}
__device__ __forceinline__ void split2h(float x, float y, u32& h, u32& l) {
    __half hx = __float2half_rn(x), hy = __float2half_rn(y);
    __half lx = __float2half_rn(x - __half2float(hx));
    __half ly = __float2half_rn(y - __half2float(hy));
    h = pack2h(hx, hy);
    l = pack2h(lx, ly);
}
__device__ __forceinline__ float ex2(float x) {
    float y; asm("ex2.approx.f32 %0, %1;" : "=f"(y) : "f"(x)); return y;
}
__device__ __forceinline__ void cpa16(u32 dst, const void* src) {
    asm volatile("cp.async.cg.shared.global [%0], [%1], 16;" :: "r"(dst), "l"(src));
}
__device__ __forceinline__ void cpcommit() {
    asm volatile("cp.async.commit_group;");
}
template <int N>
__device__ __forceinline__ void cpwait() {
    asm volatile("cp.async.wait_group %0;" :: "n"(N));
}

// ---------------------------------------------------------------------------
// merged prep: convert x -> xh ; wq|wk|wv -> wqkvh ; wo -> woh (all single)
// ---------------------------------------------------------------------------
__global__ __launch_bounds__(256) void prep_all(
    const float* __restrict__ x, const float* __restrict__ wq,
    const float* __restrict__ wk, const float* __restrict__ wv,
    const float* __restrict__ wo,
    __half* __restrict__ xh, __half* __restrict__ wqkvh, __half* __restrict__ woh)
{
    int i = blockIdx.x * blockDim.x + threadIdx.x;
    if (i < N4X) {
        float4 v = ((const float4*)x)[i];
        ((u32*)xh)[i * 2]     = cvt2h(v.x, v.y);
        ((u32*)xh)[i * 2 + 1] = cvt2h(v.z, v.w);
        return;
    }
    i -= N4X;
    if (i < N4X) {
        float4 v = ((const float4*)wq)[i];
        ((u32*)wqkvh)[i * 2]     = cvt2h(v.x, v.y);
        ((u32*)wqkvh)[i * 2 + 1] = cvt2h(v.z, v.w);
        return;
    }
    i -= N4X;
    if (i < N4KV) {
        float4 v = ((const float4*)wk)[i];
        u32* dst = (u32*)(wqkvh + MX);
        dst[i * 2]     = cvt2h(v.x, v.y);
        dst[i * 2 + 1] = cvt2h(v.z, v.w);
        return;
    }
    i -= N4KV;
    if (i < N4KV) {
        float4 v = ((const float4*)wv)[i];
        u32* dst = (u32*)(wqkvh + MX + WKV);
        dst[i * 2]     = cvt2h(v.x, v.y);
        dst[i * 2 + 1] = cvt2h(v.z, v.w);
        return;
    }
    i -= N4KV;
    {
        float4 v = ((const float4*)wo)[i];
        ((u32*)woh)[i * 2]     = cvt2h(v.x, v.y);
        ((u32*)woh)[i * 2 + 1] = cvt2h(v.z, v.w);
    }
}

// ---------------------------------------------------------------------------
// C[M,N] = A[M,K] @ B[N,K]^T ; both single fp16, 1-term MMA.
// 128x128x32 tiles, 256 thr (8 warps: 4m x 2n), 3-stage cp.async ring.
// ---------------------------------------------------------------------------
__global__ __launch_bounds__(256, 2) void gemm1(
    const __half* __restrict__ Ah, const __half* __restrict__ Bh,
    float* __restrict__ C, int M, int N, int K)
{
    extern __shared__ char smd[];
    const u32 smb = sptr(smd);
    const int tid = threadIdx.x, lane = tid & 31, w = tid >> 5;
    const int wm = w >> 1, wn = w & 1;
    const int bm = blockIdx.y * 128, bn = blockIdx.x * 128;

    float acc[2][8][4];
#pragma unroll
    for (int a = 0; a < 2; a++)
#pragma unroll
        for (int b = 0; b < 8; b++)
#pragma unroll
            for (int c = 0; c < 4; c++) acc[a][b][c] = 0.f;

    const u32 aoff = (wm * 32 + (lane & 15)) * 80 + (lane >> 4) * 16;
    const u32 boff = 10240 + (wn * 64 + (lane >> 4) * 8 + (lane & 7)) * 80
                     + ((lane >> 3) & 1) * 16;

    auto load_stage = [&](int stg, int k0) {
        u32 sb = smb + stg * 20480;
#pragma unroll
        for (int p = 0; p < 2; p++) {
            int c = tid + p * 256;
            int row = c >> 2, kc = (c & 3) * 8;
            u32 d = sb + row * 80 + kc * 2;
            size_t ga = (size_t)(bm + row) * K + k0 + kc;
            size_t gb = (size_t)(bn + row) * K + k0 + kc;
            cpa16(d,         Ah + ga);
            cpa16(d + 10240, Bh + gb);
        }
        cpcommit();
    };

    const int NCH = K >> 5;
    load_stage(0, 0);
    load_stage(1, 32);

    int stg = 0;
    for (int ic = 0; ic < NCH; ic++) {
        if (ic + 2 < NCH) {
            int nxt = stg + 2; if (nxt >= 3) nxt -= 3;
            load_stage(nxt, (ic + 2) * 32);
            cpwait<2>();
        } else if (ic + 1 < NCH) {
            cpwait<1>();
        } else {
            cpwait<0>();
        }
        __syncthreads();
        const u32 base = smb + stg * 20480;
        const u32 a_ = base + aoff;
        const u32 b_ = base + boff;
#pragma unroll
        for (int ks = 0; ks < 2; ks++) {
            u32 ah[2][4];
            ldm4(a_ + ks * 32,        ah[0][0], ah[0][1], ah[0][2], ah[0][3]);
            ldm4(a_ + ks * 32 + 1280, ah[1][0], ah[1][1], ah[1][2], ah[1][3]);
#pragma unroll
            for (int g = 0; g < 4; g++) {
                u32 bh[4];
                ldm4(b_ + g * 1280 + ks * 32, bh[0], bh[1], bh[2], bh[3]);
#pragma unroll
                for (int mt = 0; mt < 2; mt++)
#pragma unroll
                    for (int s = 0; s < 2; s++)
                        mma_h(acc[mt][g * 2 + s],
                              ah[mt][0], ah[mt][1], ah[mt][2], ah[mt][3],
                              bh[2 * s], bh[2 * s + 1]);
            }
        }
        __syncthreads();
        stg = (stg + 1 == 3) ? 0 : stg + 1;
    }

#pragma unroll
    for (int mt = 0; mt < 2; mt++)
#pragma unroll
        for (int nt = 0; nt < 8; nt++) {
            int row = bm + wm * 32 + mt * 16 + (lane >> 2);
            int col = bn + wn * 64 + nt * 8 + (lane & 3) * 2;
            *(float2*)&C[(size_t)row * N + col] =
                make_float2(acc[mt][nt][0], acc[mt][nt][1]);
            *(float2*)&C[(size_t)(row + 8) * N + col] =
                make_float2(acc[mt][nt][2], acc[mt][nt][3]);
        }
}

// ---------------------------------------------------------------------------
// RMSNorm + RoPE + convert from packed qkv fp32.
// q PRE-SCALED by scale*log2e; all outputs single fp16.
// ---------------------------------------------------------------------------
__global__ __launch_bounds__(256) void norm_rope_cvt(
    const float* __restrict__ qkvf, const float* __restrict__ freqs,
    __half* __restrict__ qh, __half* __restrict__ kh, __half* __restrict__ vh)
{
    const float CS = 0.08838834764831845f * 1.4426950408889634f; // scale*log2e
    int gwarp = (blockIdx.x * blockDim.x + threadIdx.x) >> 5;
    int lane  = threadIdx.x & 31;
    const int total = SLEN * 24;
    if (gwarp >= total) return;
    int s = gwarp / 24;
    int h = gwarp % 24;

    if (h >= 20) {
        const float* row = qkvf + (size_t)s * 3072 + 2560 + (h - 20) * 128;
        float4 x = *(const float4*)&row[lane * 4];
        size_t idx = ((((size_t)s * NKV + (h - 20)) * HD) >> 1) + lane * 2;
        ((u32*)vh)[idx]     = cvt2h(x.x, x.y);
        ((u32*)vh)[idx + 1] = cvt2h(x.z, x.w);
        return;
    }

    bool isq = (h < 16);
    const float* row = qkvf + (size_t)s * 3072 + (isq ? h * 128 : 2048 + (h - 16) * 128);
    float4 x = *(const float4*)&row[lane * 4];
    float ss = x.x * x.x + x.y * x.y + x.z * x.z + x.w * x.w;
#pragma unroll
    for (int off = 16; off; off >>= 1)
        ss += __shfl_xor_sync(0xffffffffu, ss, off);
    float r = rsqrtf(ss * (1.f / 128.f) + 1.1920929e-07f);
    if (isq) r *= CS;

    float4 fc = *(const float4*)&freqs[(size_t)s * 128 + lane * 4];
    float x1 = x.x * r, x2 = x.y * r, x3 = x.z * r, x4 = x.w * r;
    float o0 = x1 * fc.x - x2 * fc.y;
    float o1 = x1 * fc.y + x2 * fc.x;
    float o2 = x3 * fc.z - x4 * fc.w;
    float o3 = x3 * fc.w + x4 * fc.z;

    if (isq) {
        size_t idx = ((((size_t)s * NH + h) * HD) >> 1) + lane * 2;
        ((u32*)qh)[idx]     = cvt2h(o0, o1);
        ((u32*)qh)[idx + 1] = cvt2h(o2, o3);
    } else {
        size_t idx = ((((size_t)s * NKV + (h - 16)) * HD) >> 1) + lane * 2;
        ((u32*)kh)[idx]     = cvt2h(o0, o1);
        ((u32*)kh)[idx + 1] = cvt2h(o2, o3);
    }
}

// ---------------------------------------------------------------------------
// Flash attention (causal, sink), FA2 warp layout: 4 warps (128 thr), each
// warp owns 16 q-rows x full 64-wide KV tile. q/k/v single fp16 (1-term QK);
// P split in registers (2-term PV). Output single fp16.
// Grid (NH, NQT) heavy-first. smem: Q 0, K 17408, V 34816 -> 52224 B (3/SM).
// Schedule: wait K(kt) -> sync -> issue V(kt) -> QK -> sync -> issue K(kt+1)
//           -> softmax (loads fly) -> wait V -> sync -> PV.
// ---------------------------------------------------------------------------
__global__ __launch_bounds__(128, 3) void attn_kernel(
    const __half* __restrict__ qh, const __half* __restrict__ kh,
    const __half* __restrict__ vh, const float* __restrict__ sinks,
    __half* __restrict__ ath)
{
    extern __shared__ char smr[];
    const u32 smb = sptr(smr);

    const int tid = threadIdx.x, lane = tid & 31, w = tid >> 5;
    const int h = blockIdx.x, kvh = h >> 2;
    const int qt = gridDim.y - 1 - blockIdx.y;   // heavy tiles launch first

    // async-load Q tile (single): 64 rows x 256B
#pragma unroll
    for (int i = 0; i < 8; i++) {
        int c = tid + i * 128;
        int r = c >> 4, ck = c & 15;
        u32 d = smb + r * 272 + ck * 16;
        size_t g = ((size_t)(qt * 64 + r) * NH + h) * HD + ck * 8;
        cpa16(d, qh + g);
    }
    auto load_k = [&](int kt) {
#pragma unroll
        for (int i = 0; i < 4; i++) {
            int c = tid + i * 128;
            int r = c >> 3, ck = c & 7;
            u32 d = smb + 17408 + r * 272 + ck * 32;
            size_t g = ((size_t)(kt * 64 + r) * NKV + kvh) * HD + ck * 16;
            cpa16(d,      kh + g);
            cpa16(d + 16, kh + g + 8);
        }
        cpcommit();
    };
    auto load_v = [&](int kt) {
#pragma unroll
        for (int i = 0; i < 4; i++) {
            int c = tid + i * 128;
            int r = c >> 3, ck = c & 7;
            u32 d = smb + 34816 + r * 272 + ck * 32;
            size_t g = ((size_t)(kt * 64 + r) * NKV + kvh) * HD + ck * 16;
            cpa16(d,      vh + g);
            cpa16(d + 16, vh + g + 8);
        }
        cpcommit();
    };
    load_k(0);   // Q + K(0) in one group

    float oacc[16][4];
#pragma unroll
    for (int a = 0; a < 16; a++)
#pragma unroll
        for (int c = 0; c < 4; c++) oacc[a][c] = 0.f;
    float mrow[2] = {-1e30f, -1e30f}, lrow[2] = {0.f, 0.f};

    const u32 qa = smb + (w * 16 + (lane & 15)) * 272 + (lane >> 4) * 16;
    const u32 kb = smb + 17408 + ((lane >> 4) * 8 + (lane & 7)) * 272
                   + ((lane >> 3) & 1) * 16;
    const u32 vb = smb + 34816 + (((lane >> 3) & 1) * 8 + (lane & 7)) * 272
                   + ((lane >> 4) * 8) * 2;

    for (int kt = 0; kt <= qt; kt++) {
        cpwait<0>();       // K(kt) (+Q first iter) arrived
        __syncthreads();   // (B) K visible; prev PV done with V buffer
        load_v(kt);        // V(kt) flies during QK

        // S = q K^T : m16 n64 k128 per warp, single-term
        float sacc[8][4];
#pragma unroll
        for (int a = 0; a < 8; a++)
#pragma unroll
            for (int c = 0; c < 4; c++) sacc[a][c] = 0.f;

#pragma unroll
        for (int ks = 0; ks < 8; ks++) {
            u32 ah0, ah1, ah2, ah3;
            ldm4(qa + ks * 32, ah0, ah1, ah2, ah3);
#pragma unroll
            for (int g = 0; g < 4; g++) {
                u32 bh[4];
                ldm4(kb + g * 4352 + ks * 32, bh[0], bh[1], bh[2], bh[3]);
#pragma unroll
                for (int s = 0; s < 2; s++)
                    mma_h(sacc[g * 2 + s], ah0, ah1, ah2, ah3,
                          bh[2 * s], bh[2 * s + 1]);
            }
        }
        __syncthreads();   // (B2) all warps done reading K buffer
        if (kt < qt) load_k(kt + 1);   // K(kt+1) flies during softmax

        // causal mask on diagonal tile
        if (kt == qt) {
            int r0 = qt * 64 + w * 16 + (lane >> 2);
#pragma unroll
            for (int nt = 0; nt < 8; nt++) {
                int col0 = kt * 64 + nt * 8 + (lane & 3) * 2;
#pragma unroll
                for (int ci = 0; ci < 4; ci++) {
                    int row = r0 + ((ci >= 2) ? 8 : 0);
                    int col = col0 + (ci & 1);
                    if (col > row) sacc[nt][ci] = -1e30f;
                }
            }
        }

        // softmax: rows fully quad-local, exp in place into sacc
        float alpha[2];
#pragma unroll
        for (int i = 0; i < 2; i++) {
            float rm = -1e30f;
#pragma unroll
            for (int nt = 0; nt < 8; nt++)
                rm = fmaxf(rm, fmaxf(sacc[nt][2 * i], sacc[nt][2 * i + 1]));
            rm = fmaxf(rm, __shfl_xor_sync(0xffffffffu, rm, 1));
            rm = fmaxf(rm, __shfl_xor_sync(0xffffffffu, rm, 2));
            float mn = fmaxf(mrow[i], rm);
            alpha[i] = ex2(mrow[i] - mn);
            mrow[i] = mn;
            float rs = 0.f;
#pragma unroll
            for (int nt = 0; nt < 8; nt++) {
                float p0 = ex2(sacc[nt][2 * i] - mn);
                float p1 = ex2(sacc[nt][2 * i + 1] - mn);
                sacc[nt][2 * i] = p0; sacc[nt][2 * i + 1] = p1;
                rs += p0 + p1;
            }
            rs += __shfl_xor_sync(0xffffffffu, rs, 1);
            rs += __shfl_xor_sync(0xffffffffu, rs, 2);
            lrow[i] = lrow[i] * alpha[i] + rs;
#pragma unroll
            for (int nt = 0; nt < 16; nt++) {
                oacc[nt][2 * i]     *= alpha[i];
                oacc[nt][2 * i + 1] *= alpha[i];
            }
        }

        cpwait<(1)>();     // V(kt) in (K(kt+1) may still fly)
        if (kt == qt) cpwait<0>();
        __syncthreads();   // (D) V visible to all warps

        // O += P V : m16 n128 k64, P from registers (split hi/lo, 2-term)
#pragma unroll
        for (int j = 0; j < 4; j++) {
            u32 ph0, ph1, ph2, ph3, pl0, pl1, pl2, pl3;
            split2h(sacc[2 * j][0],     sacc[2 * j][1],     ph0, pl0);
            split2h(sacc[2 * j][2],     sacc[2 * j][3],     ph1, pl1);
            split2h(sacc[2 * j + 1][0], sacc[2 * j + 1][1], ph2, pl2);
            split2h(sacc[2 * j + 1][2], sacc[2 * j + 1][3], ph3, pl3);
#pragma unroll
            for (int g = 0; g < 8; g++) {
                u32 bh[4];
                ldm4t(vb + j * 4352 + g * 32, bh[0], bh[1], bh[2], bh[3]);
#pragma unroll
                for (int s = 0; s < 2; s++) {
                    float* c = oacc[g * 2 + s];
                    mma_h(c, ph0, ph1, ph2, ph3, bh[2 * s], bh[2 * s + 1]);
                    mma_h(c, pl0, pl1, pl2, pl3, bh[2 * s], bh[2 * s + 1]);
                }
            }
        }
    }

    // epilogue: lse, sink sigmoid, normalize, single-fp16 store
    float sk = sinks[h];
#pragma unroll
    for (int i = 0; i < 2; i++) {
        float lse = mrow[i] * 0.6931471805599453f + logf(lrow[i]);
        float sg = 1.f / (1.f + expf(sk - lse));
        float sc = sg / lrow[i];
        int row = qt * 64 + w * 16 + (lane >> 2) + i * 8;
        size_t rb = (size_t)row * DMODEL + h * HD;
#pragma unroll
        for (int nt = 0; nt < 16; nt++) {
            int col = nt * 8 + (lane & 3) * 2;
            ((u32*)ath)[(rb + col) >> 1] =
                cvt2h(oacc[nt][2 * i] * sc, oacc[nt][2 * i + 1] * sc);
        }
    }
}

// ---------------------------------------------------------------------------
extern "C" void kernel_launch(void* const* d_in, const int* in_sizes, int n_in,
                              void* d_out, int out_size)
{
    const float* x     = (const float*)d_in[0];
    const float* freqs = (const float*)d_in[1];
    const float* wq    = (const float*)d_in[2];
    const float* wk    = (const float*)d_in[3];
    const float* wv    = (const float*)d_in[4];
    const float* wo    = (const float*)d_in[5];
    const float* sinks = (const float*)d_in[6];
    float* out = (float*)d_out;

    float* qkvf;
    __half *xh, *wqkvh, *woh, *qh, *kh, *vh, *ath;
    cudaGetSymbolAddress((void**)&qkvf,  g_qkvf);
    cudaGetSymbolAddress((void**)&xh,    s_xh);
    cudaGetSymbolAddress((void**)&wqkvh, s_wqkvh);
    cudaGetSymbolAddress((void**)&woh,   s_woh);
    cudaGetSymbolAddress((void**)&qh,    s_qh);
    cudaGetSymbolAddress((void**)&kh,    s_kh);
    cudaGetSymbolAddress((void**)&vh,    s_vh);
    cudaGetSymbolAddress((void**)&ath,   s_ath);

    cudaFuncSetAttribute(gemm1, cudaFuncAttributeMaxDynamicSharedMemorySize, 61440);
    cudaFuncSetAttribute(attn_kernel, cudaFuncAttributeMaxDynamicSharedMemorySize, 52224);

    // merged operand prep (all single fp16)
    const int PREP_ITEMS = N4X * 3 + N4KV * 2;
    prep_all<<<PREP_ITEMS / 256, 256>>>(x, wq, wk, wv, wo, xh, wqkvh, woh);

    // fused QKV projection: [2048, 3072] = x @ [wq|wk|wv]^T
    gemm1<<<dim3(24, 16), 256, 61440>>>(xh, wqkvh, qkvf, SLEN, 3072, DMODEL);

    // RMSNorm + RoPE + convert (q pre-scaled; all single fp16)
    norm_rope_cvt<<<(SLEN * 24 * 32) / 256, 256>>>(qkvf, freqs, qh, kh, vh);

    // causal flash attention with sink scaling (heavy-first grid order)
    attn_kernel<<<dim3(NH, SLEN / 64), 128, 52224>>>(qh, kh, vh, sinks, ath);

    // output projection
    gemm1<<<dim3(16, 16), 256, 61440>>>(ath, woh, out, SLEN, DMODEL, DMODEL);
}

// round 13
// speedup vs baseline: 12.0104x; 1.0496x over previous
#include <cuda_runtime.h>
#include <cuda_fp16.h>
#include <math.h>

typedef unsigned int u32;

#define SLEN 2048
#define DMODEL 2048
#define NH 16
#define NKV 4
#define HD 128
#define MX (SLEN * DMODEL)          // 4194304
#define MKV (SLEN * NKV * HD)       // 1048576
#define WKV (NKV * HD * DMODEL)     // 1048576
#define N4X (MX / 4)                // 1048576 float4 items
#define N4KV (WKV / 4)              // 262144

// fp32 packed QKV projection output: [s][3072] (q 0-2047, k 2048-2559, v 2560-3071)
__device__ __align__(16) float g_qkvf[SLEN * 3072];

// fp16 operands
__device__ __align__(16) __half s_xh[MX];                    // x single
__device__ __align__(16) __half s_wqkvh[3072 * DMODEL];      // packed wq|wk|wv, single
__device__ __align__(16) __half s_woh[MX];                   // wo, single
__device__ __align__(16) __half s_qh[MX];                    // q single (post norm+rope, pre-scaled)
__device__ __align__(16) __half s_kh[MKV];                   // k single (post norm+rope)
__device__ __align__(16) __half s_vh[MKV];                   // v single
__device__ __align__(16) __half s_ath[MX];                   // attention out single

// ---------------------------------------------------------------------------
// helpers
// ---------------------------------------------------------------------------
__device__ __forceinline__ u32 sptr(const void* p) {
    return (u32)__cvta_generic_to_shared(p);
}
__device__ __forceinline__ void ldm4(u32 a, u32& r0, u32& r1, u32& r2, u32& r3) {
    asm volatile("ldmatrix.sync.aligned.m8n8.x4.shared.b16 {%0,%1,%2,%3},[%4];"
                 : "=r"(r0), "=r"(r1), "=r"(r2), "=r"(r3) : "r"(a));
}
__device__ __forceinline__ void ldm4t(u32 a, u32& r0, u32& r1, u32& r2, u32& r3) {
    asm volatile("ldmatrix.sync.aligned.m8n8.x4.trans.shared.b16 {%0,%1,%2,%3},[%4];"
                 : "=r"(r0), "=r"(r1), "=r"(r2), "=r"(r3) : "r"(a));
}
__device__ __forceinline__ void mma_h(float* c, u32 a0, u32 a1, u32 a2, u32 a3,
                                      u32 b0, u32 b1) {
    asm volatile(
        "mma.sync.aligned.m16n8k16.row.col.f32.f16.f16.f32 "
        "{%0,%1,%2,%3},{%4,%5,%6,%7},{%8,%9},{%0,%1,%2,%3};"
        : "+f"(c[0]), "+f"(c[1]), "+f"(c[2]), "+f"(c[3])
        : "r"(a0), "r"(a1), "r"(a2), "r"(a3), "r"(b0), "r"(b1));
}
__device__ __forceinline__ u32 pack2h(__half a, __half b) {
    __half2 t = __halves2half2(a, b);
    return *reinterpret_cast<u32*>(&t);
}
__device__ __forceinline__ u32 cvt2h(float x, float y) {
    return pack2h(__float2half_rn(x), __float2half_rn(y));
}
__device__ __forceinline__ float ex2(float x) {
    float y; asm("ex2.approx.f32 %0, %1;" : "=f"(y) : "f"(x)); return y;
}
__device__ __forceinline__ void cpa16(u32 dst, const void* src) {
    asm volatile("cp.async.cg.shared.global [%0], [%1], 16;" :: "r"(dst), "l"(src));
}
__device__ __forceinline__ void cpcommit() {
    asm volatile("cp.async.commit_group;");
}
template <int N>
__device__ __forceinline__ void cpwait() {
    asm volatile("cp.async.wait_group %0;" :: "n"(N));
}

// ---------------------------------------------------------------------------
// merged prep: convert x -> xh ; wq|wk|wv -> wqkvh ; wo -> woh (all single)
// ---------------------------------------------------------------------------
__global__ __launch_bounds__(256) void prep_all(
    const float* __restrict__ x, const float* __restrict__ wq,
    const float* __restrict__ wk, const float* __restrict__ wv,
    const float* __restrict__ wo,
    __half* __restrict__ xh, __half* __restrict__ wqkvh, __half* __restrict__ woh)
{
    int i = blockIdx.x * blockDim.x + threadIdx.x;
    if (i < N4X) {
        float4 v = ((const float4*)x)[i];
        ((u32*)xh)[i * 2]     = cvt2h(v.x, v.y);
        ((u32*)xh)[i * 2 + 1] = cvt2h(v.z, v.w);
        return;
    }
    i -= N4X;
    if (i < N4X) {
        float4 v = ((const float4*)wq)[i];
        ((u32*)wqkvh)[i * 2]     = cvt2h(v.x, v.y);
        ((u32*)wqkvh)[i * 2 + 1] = cvt2h(v.z, v.w);
        return;
    }
    i -= N4X;
    if (i < N4KV) {
        float4 v = ((const float4*)wk)[i];
        u32* dst = (u32*)(wqkvh + MX);
        dst[i * 2]     = cvt2h(v.x, v.y);
        dst[i * 2 + 1] = cvt2h(v.z, v.w);
        return;
    }
    i -= N4KV;
    if (i < N4KV) {
        float4 v = ((const float4*)wv)[i];
        u32* dst = (u32*)(wqkvh + MX + WKV);
        dst[i * 2]     = cvt2h(v.x, v.y);
        dst[i * 2 + 1] = cvt2h(v.z, v.w);
        return;
    }
    i -= N4KV;
    {
        float4 v = ((const float4*)wo)[i];
        ((u32*)woh)[i * 2]     = cvt2h(v.x, v.y);
        ((u32*)woh)[i * 2 + 1] = cvt2h(v.z, v.w);
    }
}

// ---------------------------------------------------------------------------
// C[M,N] = A[M,K] @ B[N,K]^T ; both single fp16, 1-term MMA.
// 128x128x32 tiles, 256 thr (8 warps: 4m x 2n), 3-stage cp.async ring.
// ---------------------------------------------------------------------------
__global__ __launch_bounds__(256, 2) void gemm1(
    const __half* __restrict__ Ah, const __half* __restrict__ Bh,
    float* __restrict__ C, int M, int N, int K)
{
    extern __shared__ char smd[];
    const u32 smb = sptr(smd);
    const int tid = threadIdx.x, lane = tid & 31, w = tid >> 5;
    const int wm = w >> 1, wn = w & 1;
    const int bm = blockIdx.y * 128, bn = blockIdx.x * 128;

    float acc[2][8][4];
#pragma unroll
    for (int a = 0; a < 2; a++)
#pragma unroll
        for (int b = 0; b < 8; b++)
#pragma unroll
            for (int c = 0; c < 4; c++) acc[a][b][c] = 0.f;

    const u32 aoff = (wm * 32 + (lane & 15)) * 80 + (lane >> 4) * 16;
    const u32 boff = 10240 + (wn * 64 + (lane >> 4) * 8 + (lane & 7)) * 80
                     + ((lane >> 3) & 1) * 16;

    auto load_stage = [&](int stg, int k0) {
        u32 sb = smb + stg * 20480;
#pragma unroll
        for (int p = 0; p < 2; p++) {
            int c = tid + p * 256;
            int row = c >> 2, kc = (c & 3) * 8;
            u32 d = sb + row * 80 + kc * 2;
            size_t ga = (size_t)(bm + row) * K + k0 + kc;
            size_t gb = (size_t)(bn + row) * K + k0 + kc;
            cpa16(d,         Ah + ga);
            cpa16(d + 10240, Bh + gb);
        }
        cpcommit();
    };

    const int NCH = K >> 5;
    load_stage(0, 0);
    load_stage(1, 32);

    int stg = 0;
    for (int ic = 0; ic < NCH; ic++) {
        if (ic + 2 < NCH) {
            int nxt = stg + 2; if (nxt >= 3) nxt -= 3;
            load_stage(nxt, (ic + 2) * 32);
            cpwait<2>();
        } else if (ic + 1 < NCH) {
            cpwait<1>();
        } else {
            cpwait<0>();
        }
        __syncthreads();
        const u32 base = smb + stg * 20480;
        const u32 a_ = base + aoff;
        const u32 b_ = base + boff;
#pragma unroll
        for (int ks = 0; ks < 2; ks++) {
            u32 ah[2][4];
            ldm4(a_ + ks * 32,        ah[0][0], ah[0][1], ah[0][2], ah[0][3]);
            ldm4(a_ + ks * 32 + 1280, ah[1][0], ah[1][1], ah[1][2], ah[1][3]);
#pragma unroll
            for (int g = 0; g < 4; g++) {
                u32 bh[4];
                ldm4(b_ + g * 1280 + ks * 32, bh[0], bh[1], bh[2], bh[3]);
#pragma unroll
                for (int mt = 0; mt < 2; mt++)
#pragma unroll
                    for (int s = 0; s < 2; s++)
                        mma_h(acc[mt][g * 2 + s],
                              ah[mt][0], ah[mt][1], ah[mt][2], ah[mt][3],
                              bh[2 * s], bh[2 * s + 1]);
            }
        }
        __syncthreads();
        stg = (stg + 1 == 3) ? 0 : stg + 1;
    }

#pragma unroll
    for (int mt = 0; mt < 2; mt++)
#pragma unroll
        for (int nt = 0; nt < 8; nt++) {
            int row = bm + wm * 32 + mt * 16 + (lane >> 2);
            int col = bn + wn * 64 + nt * 8 + (lane & 3) * 2;
            *(float2*)&C[(size_t)row * N + col] =
                make_float2(acc[mt][nt][0], acc[mt][nt][1]);
            *(float2*)&C[(size_t)(row + 8) * N + col] =
                make_float2(acc[mt][nt][2], acc[mt][nt][3]);
        }
}

// ---------------------------------------------------------------------------
// RMSNorm + RoPE + convert from packed qkv fp32.
// q PRE-SCALED by scale*log2e; all outputs single fp16.
// ---------------------------------------------------------------------------
__global__ __launch_bounds__(256) void norm_rope_cvt(
    const float* __restrict__ qkvf, const float* __restrict__ freqs,
    __half* __restrict__ qh, __half* __restrict__ kh, __half* __restrict__ vh)
{
    const float CS = 0.08838834764831845f * 1.4426950408889634f; // scale*log2e
    int gwarp = (blockIdx.x * blockDim.x + threadIdx.x) >> 5;
    int lane  = threadIdx.x & 31;
    const int total = SLEN * 24;
    if (gwarp >= total) return;
    int s = gwarp / 24;
    int h = gwarp % 24;

    if (h >= 20) {
        const float* row = qkvf + (size_t)s * 3072 + 2560 + (h - 20) * 128;
        float4 x = *(const float4*)&row[lane * 4];
        size_t idx = ((((size_t)s * NKV + (h - 20)) * HD) >> 1) + lane * 2;
        ((u32*)vh)[idx]     = cvt2h(x.x, x.y);
        ((u32*)vh)[idx + 1] = cvt2h(x.z, x.w);
        return;
    }

    bool isq = (h < 16);
    const float* row = qkvf + (size_t)s * 3072 + (isq ? h * 128 : 2048 + (h - 16) * 128);
    float4 x = *(const float4*)&row[lane * 4];
    float ss = x.x * x.x + x.y * x.y + x.z * x.z + x.w * x.w;
#pragma unroll
    for (int off = 16; off; off >>= 1)
        ss += __shfl_xor_sync(0xffffffffu, ss, off);
    float r = rsqrtf(ss * (1.f / 128.f) + 1.1920929e-07f);
    if (isq) r *= CS;

    float4 fc = *(const float4*)&freqs[(size_t)s * 128 + lane * 4];
    float x1 = x.x * r, x2 = x.y * r, x3 = x.z * r, x4 = x.w * r;
    float o0 = x1 * fc.x - x2 * fc.y;
    float o1 = x1 * fc.y + x2 * fc.x;
    float o2 = x3 * fc.z - x4 * fc.w;
    float o3 = x3 * fc.w + x4 * fc.z;

    if (isq) {
        size_t idx = ((((size_t)s * NH + h) * HD) >> 1) + lane * 2;
        ((u32*)qh)[idx]     = cvt2h(o0, o1);
        ((u32*)qh)[idx + 1] = cvt2h(o2, o3);
    } else {
        size_t idx = ((((size_t)s * NKV + (h - 16)) * HD) >> 1) + lane * 2;
        ((u32*)kh)[idx]     = cvt2h(o0, o1);
        ((u32*)kh)[idx + 1] = cvt2h(o2, o3);
    }
}

// ---------------------------------------------------------------------------
// Flash attention (causal, sink), FA2 warp layout: 4 warps (128 thr), each
// warp owns 16 q-rows x full 64-wide KV tile. q/k/v/P all single fp16
// (1-term QK and 1-term PV). Output single fp16.
// Grid (NH, NQT) heavy-first. smem: Q 0, K 17408, V 34816 -> 52224 B (3/SM).
// Schedule: wait K(kt) -> sync -> issue V(kt) -> QK -> sync -> issue K(kt+1)
//           -> softmax (loads fly) -> wait V -> sync -> PV.
// ---------------------------------------------------------------------------
__global__ __launch_bounds__(128, 3) void attn_kernel(
    const __half* __restrict__ qh, const __half* __restrict__ kh,
    const __half* __restrict__ vh, const float* __restrict__ sinks,
    __half* __restrict__ ath)
{
    extern __shared__ char smr[];
    const u32 smb = sptr(smr);

    const int tid = threadIdx.x, lane = tid & 31, w = tid >> 5;
    const int h = blockIdx.x, kvh = h >> 2;
    const int qt = gridDim.y - 1 - blockIdx.y;   // heavy tiles launch first

    // async-load Q tile (single): 64 rows x 256B
#pragma unroll
    for (int i = 0; i < 8; i++) {
        int c = tid + i * 128;
        int r = c >> 4, ck = c & 15;
        u32 d = smb + r * 272 + ck * 16;
        size_t g = ((size_t)(qt * 64 + r) * NH + h) * HD + ck * 8;
        cpa16(d, qh + g);
    }
    auto load_k = [&](int kt) {
#pragma unroll
        for (int i = 0; i < 4; i++) {
            int c = tid + i * 128;
            int r = c >> 3, ck = c & 7;
            u32 d = smb + 17408 + r * 272 + ck * 32;
            size_t g = ((size_t)(kt * 64 + r) * NKV + kvh) * HD + ck * 16;
            cpa16(d,      kh + g);
            cpa16(d + 16, kh + g + 8);
        }
        cpcommit();
    };
    auto load_v = [&](int kt) {
#pragma unroll
        for (int i = 0; i < 4; i++) {
            int c = tid + i * 128;
            int r = c >> 3, ck = c & 7;
            u32 d = smb + 34816 + r * 272 + ck * 32;
            size_t g = ((size_t)(kt * 64 + r) * NKV + kvh) * HD + ck * 16;
            cpa16(d,      vh + g);
            cpa16(d + 16, vh + g + 8);
        }
        cpcommit();
    };
    load_k(0);   // Q + K(0) in one group

    float oacc[16][4];
#pragma unroll
    for (int a = 0; a < 16; a++)
#pragma unroll
        for (int c = 0; c < 4; c++) oacc[a][c] = 0.f;
    float mrow[2] = {-1e30f, -1e30f}, lrow[2] = {0.f, 0.f};

    const u32 qa = smb + (w * 16 + (lane & 15)) * 272 + (lane >> 4) * 16;
    const u32 kb = smb + 17408 + ((lane >> 4) * 8 + (lane & 7)) * 272
                   + ((lane >> 3) & 1) * 16;
    const u32 vb = smb + 34816 + (((lane >> 3) & 1) * 8 + (lane & 7)) * 272
                   + ((lane >> 4) * 8) * 2;

    for (int kt = 0; kt <= qt; kt++) {
        cpwait<0>();       // K(kt) (+Q first iter) arrived
        __syncthreads();   // (B) K visible; prev PV done with V buffer
        load_v(kt);        // V(kt) flies during QK

        // S = q K^T : m16 n64 k128 per warp, single-term
        float sacc[8][4];
#pragma unroll
        for (int a = 0; a < 8; a++)
#pragma unroll
            for (int c = 0; c < 4; c++) sacc[a][c] = 0.f;

#pragma unroll
        for (int ks = 0; ks < 8; ks++) {
            u32 ah0, ah1, ah2, ah3;
            ldm4(qa + ks * 32, ah0, ah1, ah2, ah3);
#pragma unroll
            for (int g = 0; g < 4; g++) {
                u32 bh[4];
                ldm4(kb + g * 4352 + ks * 32, bh[0], bh[1], bh[2], bh[3]);
#pragma unroll
                for (int s = 0; s < 2; s++)
                    mma_h(sacc[g * 2 + s], ah0, ah1, ah2, ah3,
                          bh[2 * s], bh[2 * s + 1]);
            }
        }
        __syncthreads();   // (B2) all warps done reading K buffer
        if (kt < qt) load_k(kt + 1);   // K(kt+1) flies during softmax

        // causal mask on diagonal tile
        if (kt == qt) {
            int r0 = qt * 64 + w * 16 + (lane >> 2);
#pragma unroll
            for (int nt = 0; nt < 8; nt++) {
                int col0 = kt * 64 + nt * 8 + (lane & 3) * 2;
#pragma unroll
                for (int ci = 0; ci < 4; ci++) {
                    int row = r0 + ((ci >= 2) ? 8 : 0);
                    int col = col0 + (ci & 1);
                    if (col > row) sacc[nt][ci] = -1e30f;
                }
            }
        }

        // softmax: rows fully quad-local, exp in place into sacc
        float alpha[2];
#pragma unroll
        for (int i = 0; i < 2; i++) {
            float rm = -1e30f;
#pragma unroll
            for (int nt = 0; nt < 8; nt++)
                rm = fmaxf(rm, fmaxf(sacc[nt][2 * i], sacc[nt][2 * i + 1]));
            rm = fmaxf(rm, __shfl_xor_sync(0xffffffffu, rm, 1));
            rm = fmaxf(rm, __shfl_xor_sync(0xffffffffu, rm, 2));
            float mn = fmaxf(mrow[i], rm);
            alpha[i] = ex2(mrow[i] - mn);
            mrow[i] = mn;
            float rs = 0.f;
#pragma unroll
            for (int nt = 0; nt < 8; nt++) {
                float p0 = ex2(sacc[nt][2 * i] - mn);
                float p1 = ex2(sacc[nt][2 * i + 1] - mn);
                sacc[nt][2 * i] = p0; sacc[nt][2 * i + 1] = p1;
                rs += p0 + p1;
            }
            rs += __shfl_xor_sync(0xffffffffu, rs, 1);
            rs += __shfl_xor_sync(0xffffffffu, rs, 2);
            lrow[i] = lrow[i] * alpha[i] + rs;
#pragma unroll
            for (int nt = 0; nt < 16; nt++) {
                oacc[nt][2 * i]     *= alpha[i];
                oacc[nt][2 * i + 1] *= alpha[i];
            }
        }

        cpwait<(1)>();     // V(kt) in (K(kt+1) may still fly)
        if (kt == qt) cpwait<0>();
        __syncthreads();   // (D) V visible to all warps

        // O += P V : m16 n128 k64, P from registers, single-term
#pragma unroll
        for (int j = 0; j < 4; j++) {
            u32 ph0 = cvt2h(sacc[2 * j][0],     sacc[2 * j][1]);
            u32 ph1 = cvt2h(sacc[2 * j][2],     sacc[2 * j][3]);
            u32 ph2 = cvt2h(sacc[2 * j + 1][0], sacc[2 * j + 1][1]);
            u32 ph3 = cvt2h(sacc[2 * j + 1][2], sacc[2 * j + 1][3]);
#pragma unroll
            for (int g = 0; g < 8; g++) {
                u32 bh[4];
                ldm4t(vb + j * 4352 + g * 32, bh[0], bh[1], bh[2], bh[3]);
#pragma unroll
                for (int s = 0; s < 2; s++)
                    mma_h(oacc[g * 2 + s], ph0, ph1, ph2, ph3,
                          bh[2 * s], bh[2 * s + 1]);
            }
        }
    }

    // epilogue: lse, sink sigmoid, normalize, single-fp16 store
    float sk = sinks[h];
#pragma unroll
    for (int i = 0; i < 2; i++) {
        float lse = mrow[i] * 0.6931471805599453f + logf(lrow[i]);
        float sg = 1.f / (1.f + expf(sk - lse));
        float sc = sg / lrow[i];
        int row = qt * 64 + w * 16 + (lane >> 2) + i * 8;
        size_t rb = (size_t)row * DMODEL + h * HD;
#pragma unroll
        for (int nt = 0; nt < 16; nt++) {
            int col = nt * 8 + (lane & 3) * 2;
            ((u32*)ath)[(rb + col) >> 1] =
                cvt2h(oacc[nt][2 * i] * sc, oacc[nt][2 * i + 1] * sc);
        }
    }
}

// ---------------------------------------------------------------------------
extern "C" void kernel_launch(void* const* d_in, const int* in_sizes, int n_in,
                              void* d_out, int out_size)
{
    const float* x     = (const float*)d_in[0];
    const float* freqs = (const float*)d_in[1];
    const float* wq    = (const float*)d_in[2];
    const float* wk    = (const float*)d_in[3];
    const float* wv    = (const float*)d_in[4];
    const float* wo    = (const float*)d_in[5];
    const float* sinks = (const float*)d_in[6];
    float* out = (float*)d_out;

    float* qkvf;
    __half *xh, *wqkvh, *woh, *qh, *kh, *vh, *ath;
    cudaGetSymbolAddress((void**)&qkvf,  g_qkvf);
    cudaGetSymbolAddress((void**)&xh,    s_xh);
    cudaGetSymbolAddress((void**)&wqkvh, s_wqkvh);
    cudaGetSymbolAddress((void**)&woh,   s_woh);
    cudaGetSymbolAddress((void**)&qh,    s_qh);
    cudaGetSymbolAddress((void**)&kh,    s_kh);
    cudaGetSymbolAddress((void**)&vh,    s_vh);
    cudaGetSymbolAddress((void**)&ath,   s_ath);

    cudaFuncSetAttribute(gemm1, cudaFuncAttributeMaxDynamicSharedMemorySize, 61440);
    cudaFuncSetAttribute(attn_kernel, cudaFuncAttributeMaxDynamicSharedMemorySize, 52224);

    // merged operand prep (all single fp16)
    const int PREP_ITEMS = N4X * 3 + N4KV * 2;
    prep_all<<<PREP_ITEMS / 256, 256>>>(x, wq, wk, wv, wo, xh, wqkvh, woh);

    // fused QKV projection: [2048, 3072] = x @ [wq|wk|wv]^T
    gemm1<<<dim3(24, 16), 256, 61440>>>(xh, wqkvh, qkvf, SLEN, 3072, DMODEL);

    // RMSNorm + RoPE + convert (q pre-scaled; all single fp16)
    norm_rope_cvt<<<(SLEN * 24 * 32) / 256, 256>>>(qkvf, freqs, qh, kh, vh);

    // causal flash attention with sink scaling (heavy-first grid order)
    attn_kernel<<<dim3(NH, SLEN / 64), 128, 52224>>>(qh, kh, vh, sinks, ath);

    // output projection
    gemm1<<<dim3(16, 16), 256, 61440>>>(ath, woh, out, SLEN, DMODEL, DMODEL);
}